// round 1
// baseline (speedup 1.0000x reference)
#include <cuda_runtime.h>

#define N_EMBD 2048
#define N_HEAD 16
#define HEAD_DIM 128
#define BATCH 2
#define SEQ 2048

// ---------------- scratch (static device globals; no runtime alloc) ----------
__device__ float g_qkv[(size_t)BATCH * SEQ * 3 * N_EMBD];            // 100 MB
__device__ float g_scores[(size_t)BATCH * N_HEAD * SEQ * SEQ];       // 537 MB
__device__ float g_attn[(size_t)BATCH * SEQ * N_EMBD];               // 33 MB

// ---------------- generic fp32 SGEMM: C = scale * A @ B(^T) (+bias) ----------
// Tiles: 128x128x8, 256 threads, 8x8 per-thread microtile.
// All problem dims here are multiples of tile dims -> no bounds checks.
template <bool TRANSB, bool CAUSAL_SKIP, bool BIAS, bool TRIA>
__global__ __launch_bounds__(256) void gemm_f32(
    const float* __restrict__ A, const float* __restrict__ B,
    const float* __restrict__ bias, float* __restrict__ C,
    int M, int N, int K, int lda, int ldb, int ldc,
    int Hdiv,
    long long sAb, long long sAh,
    long long sBb, long long sBh,
    long long sCb, long long sCh,
    float scale)
{
    if (CAUSAL_SKIP && blockIdx.x > blockIdx.y) return;  // tile fully above diagonal

    const int z  = blockIdx.z;
    const int zb = z / Hdiv;
    const int zh = z % Hdiv;
    A += zb * sAb + zh * sAh;
    B += zb * sBb + zh * sBh;
    C += zb * sCb + zh * sCh;

    const int m0  = blockIdx.y * 128;
    const int n0  = blockIdx.x * 128;
    const int tid = threadIdx.x;
    const int tx  = tid & 15;   // 0..15 -> n microtile
    const int ty  = tid >> 4;   // 0..15 -> m microtile

    __shared__ float As[8][128];
    __shared__ float Bs[8][128];

    float acc[8][8];
#pragma unroll
    for (int i = 0; i < 8; ++i)
#pragma unroll
        for (int j = 0; j < 8; ++j) acc[i][j] = 0.f;

    const int Kend = TRIA ? min(K, m0 + 128) : K;

    // load-index precompute
    const int arow = tid >> 1;          // 0..127
    const int acol = (tid & 1) * 4;     // 0 or 4
    const int brow = tid >> 5;          // 0..7   (normal-B load)
    const int bcol = (tid & 31) * 4;    // 0..124

    for (int k0 = 0; k0 < Kend; k0 += 8) {
        // A tile (128m x 8k), transposed store
        {
            float4 a4 = *(const float4*)(A + (size_t)(m0 + arow) * lda + k0 + acol);
            As[acol + 0][arow] = a4.x;
            As[acol + 1][arow] = a4.y;
            As[acol + 2][arow] = a4.z;
            As[acol + 3][arow] = a4.w;
        }
        if (TRANSB) {
            // B data is [N x K] row-major; logical B[k][n] = Bdata[n][k]
            float4 b4 = *(const float4*)(B + (size_t)(n0 + arow) * ldb + k0 + acol);
            Bs[acol + 0][arow] = b4.x;
            Bs[acol + 1][arow] = b4.y;
            Bs[acol + 2][arow] = b4.z;
            Bs[acol + 3][arow] = b4.w;
        } else {
            float4 b4 = *(const float4*)(B + (size_t)(k0 + brow) * ldb + n0 + bcol);
            *(float4*)&Bs[brow][bcol] = b4;
        }
        __syncthreads();

#pragma unroll
        for (int k = 0; k < 8; ++k) {
            float4 a0 = *(const float4*)&As[k][ty * 8];
            float4 a1 = *(const float4*)&As[k][ty * 8 + 4];
            float4 b0 = *(const float4*)&Bs[k][tx * 8];
            float4 b1 = *(const float4*)&Bs[k][tx * 8 + 4];
            float av[8] = {a0.x, a0.y, a0.z, a0.w, a1.x, a1.y, a1.z, a1.w};
            float bv[8] = {b0.x, b0.y, b0.z, b0.w, b1.x, b1.y, b1.z, b1.w};
#pragma unroll
            for (int i = 0; i < 8; ++i)
#pragma unroll
                for (int j = 0; j < 8; ++j) acc[i][j] += av[i] * bv[j];
        }
        __syncthreads();
    }

    // epilogue
    float bv0[8];
    if (BIAS) {
#pragma unroll
        for (int j = 0; j < 8; ++j) bv0[j] = bias[n0 + tx * 8 + j];
    }
#pragma unroll
    for (int i = 0; i < 8; ++i) {
        const int m = m0 + ty * 8 + i;
        float* crow = C + (size_t)m * ldc + n0 + tx * 8;
        float4 v0, v1;
        v0.x = acc[i][0] * scale; v0.y = acc[i][1] * scale;
        v0.z = acc[i][2] * scale; v0.w = acc[i][3] * scale;
        v1.x = acc[i][4] * scale; v1.y = acc[i][5] * scale;
        v1.z = acc[i][6] * scale; v1.w = acc[i][7] * scale;
        if (BIAS) {
            v0.x += bv0[0]; v0.y += bv0[1]; v0.z += bv0[2]; v0.w += bv0[3];
            v1.x += bv0[4]; v1.y += bv0[5]; v1.z += bv0[6]; v1.w += bv0[7];
        }
        *(float4*)(crow)     = v0;
        *(float4*)(crow + 4) = v1;
    }
}

// ---------------- causal row softmax (in-place on g_scores) ------------------
// grid = BATCH*N_HEAD*SEQ blocks (one per row), 256 threads.
// Row bh,s1: softmax over [0, s1], zero-fill (s1, S) so PV can read full rows.
__global__ __launch_bounds__(256) void softmax_causal_kernel(float* __restrict__ scores)
{
    const long long row = blockIdx.x;
    const int s1  = (int)(row & (SEQ - 1));
    float* p = scores + row * (long long)SEQ;
    const int len = s1 + 1;
    const int tid = threadIdx.x;
    __shared__ float red[256];

    float mx = -3.402823e38f;
    for (int i = tid; i < len; i += 256) mx = fmaxf(mx, p[i]);
    red[tid] = mx; __syncthreads();
#pragma unroll
    for (int s = 128; s > 0; s >>= 1) {
        if (tid < s) red[tid] = fmaxf(red[tid], red[tid + s]);
        __syncthreads();
    }
    mx = red[0];
    __syncthreads();

    float sum = 0.f;
    for (int i = tid; i < len; i += 256) {
        float e = __expf(p[i] - mx);
        p[i] = e;
        sum += e;
    }
    red[tid] = sum; __syncthreads();
#pragma unroll
    for (int s = 128; s > 0; s >>= 1) {
        if (tid < s) red[tid] += red[tid + s];
        __syncthreads();
    }
    const float inv = 1.0f / red[0];

    for (int i = tid; i < len; i += 256) p[i] *= inv;
    for (int i = len + tid; i < SEQ; i += 256) p[i] = 0.f;
}

// ---------------- launch ------------------------------------------------------
extern "C" void kernel_launch(void* const* d_in, const int* in_sizes, int n_in,
                              void* d_out, int out_size)
{
    const float* x     = (const float*)d_in[0];  // [B,S,E]
    const float* Wqkv  = (const float*)d_in[1];  // [E,3E]
    const float* bqkv  = (const float*)d_in[2];  // [3E]
    const float* Wproj = (const float*)d_in[3];  // [E,E]
    const float* bproj = (const float*)d_in[4];  // [E]
    float* out = (float*)d_out;                  // [B,S,E]

    float *qkv, *scores, *attn;
    cudaGetSymbolAddress((void**)&qkv,    g_qkv);
    cudaGetSymbolAddress((void**)&scores, g_scores);
    cudaGetSymbolAddress((void**)&attn,   g_attn);

    const int M  = BATCH * SEQ;        // 4096
    const int E  = N_EMBD;             // 2048
    const int E3 = 3 * N_EMBD;         // 6144
    const long long sQKVb = (long long)SEQ * E3;          // per-batch qkv stride
    const long long sScB  = (long long)N_HEAD * SEQ * SEQ;
    const long long sScH  = (long long)SEQ * SEQ;
    const float inv_sqrt_d = 0.08838834764831845f;        // 1/sqrt(128)

    // 1) qkv = x @ Wqkv + b        [4096 x 6144], K=2048
    gemm_f32<false, false, true, false><<<dim3(E3 / 128, M / 128, 1), 256>>>(
        x, Wqkv, bqkv, qkv, M, E3, E, E, E3, E3,
        1, 0, 0, 0, 0, 0, 0, 1.f);

    // 2) scores[bh] = Q[bh] @ K[bh]^T * inv_sqrt_d    [2048 x 2048], K=128, 32 batches
    gemm_f32<true, true, false, false><<<dim3(SEQ / 128, SEQ / 128, BATCH * N_HEAD), 256>>>(
        qkv, qkv + N_EMBD, nullptr, scores, SEQ, SEQ, HEAD_DIM, E3, E3, SEQ,
        N_HEAD, sQKVb, HEAD_DIM, sQKVb, HEAD_DIM, sScB, sScH, inv_sqrt_d);

    // 3) causal softmax rows (in place)
    softmax_causal_kernel<<<BATCH * N_HEAD * SEQ, 256>>>(scores);

    // 4) attn[bh] = P[bh] @ V[bh]   [2048 x 128], K=2048 (triangular K-limit)
    gemm_f32<false, false, false, true><<<dim3(HEAD_DIM / 128, SEQ / 128, BATCH * N_HEAD), 256>>>(
        scores, qkv + 2 * N_EMBD, nullptr, attn, SEQ, HEAD_DIM, SEQ, SEQ, E3, E,
        N_HEAD, sScB, sScH, sQKVb, HEAD_DIM, (long long)SEQ * E, HEAD_DIM, 1.f);

    // 5) out = attn @ Wproj + b    [4096 x 2048], K=2048
    gemm_f32<false, false, true, false><<<dim3(E / 128, M / 128, 1), 256>>>(
        attn, Wproj, bproj, out, M, E, E, E, E, E,
        1, 0, 0, 0, 0, 0, 0, 1.f);
}

// round 2
// speedup vs baseline: 3.3785x; 3.3785x over previous
#include <cuda_runtime.h>
#include <cuda_bf16.h>
#include <cstdint>

#define N_EMBD 2048
#define N_HEAD 16
#define HEAD_DIM 128
#define BATCH 2
#define SEQ 2048

#define BM 128
#define BN 128
#define BK 32

// ---------------- scratch (static device globals) ----------------------------
__device__ __nv_bfloat16 g_x_h[(size_t)BATCH * SEQ * N_EMBD];
__device__ __nv_bfloat16 g_x_l[(size_t)BATCH * SEQ * N_EMBD];
__device__ __nv_bfloat16 g_wqkvT_h[(size_t)3 * N_EMBD * N_EMBD];
__device__ __nv_bfloat16 g_wqkvT_l[(size_t)3 * N_EMBD * N_EMBD];
__device__ __nv_bfloat16 g_wprojT_h[(size_t)N_EMBD * N_EMBD];
__device__ __nv_bfloat16 g_wprojT_l[(size_t)N_EMBD * N_EMBD];
__device__ float         g_qkv[(size_t)BATCH * SEQ * 3 * N_EMBD];
__device__ __nv_bfloat16 g_qkv_h[(size_t)BATCH * SEQ * 3 * N_EMBD];
__device__ __nv_bfloat16 g_qkv_l[(size_t)BATCH * SEQ * 3 * N_EMBD];
__device__ __nv_bfloat16 g_vT_h[(size_t)BATCH * N_HEAD * HEAD_DIM * SEQ];
__device__ __nv_bfloat16 g_vT_l[(size_t)BATCH * N_HEAD * HEAD_DIM * SEQ];
__device__ float         g_scores[(size_t)BATCH * N_HEAD * SEQ * SEQ];
__device__ __nv_bfloat16 g_p_h[(size_t)BATCH * N_HEAD * SEQ * SEQ];
__device__ __nv_bfloat16 g_p_l[(size_t)BATCH * N_HEAD * SEQ * SEQ];
__device__ __nv_bfloat16 g_attn_h[(size_t)BATCH * SEQ * N_EMBD];
__device__ __nv_bfloat16 g_attn_l[(size_t)BATCH * SEQ * N_EMBD];

// ---------------- PTX helpers -------------------------------------------------
__device__ __forceinline__ uint32_t smem_u32(const void* p) {
    return (uint32_t)__cvta_generic_to_shared(p);
}
__device__ __forceinline__ void ldsm_x4(uint32_t* r, uint32_t addr) {
    asm volatile("ldmatrix.sync.aligned.m8n8.x4.shared.b16 {%0,%1,%2,%3}, [%4];"
                 : "=r"(r[0]), "=r"(r[1]), "=r"(r[2]), "=r"(r[3]) : "r"(addr));
}
__device__ __forceinline__ void mma_bf16(float* d, const uint32_t* a, const uint32_t* b) {
    asm volatile(
        "mma.sync.aligned.m16n8k16.row.col.f32.bf16.bf16.f32 "
        "{%0,%1,%2,%3},{%4,%5,%6,%7},{%8,%9},{%0,%1,%2,%3};"
        : "+f"(d[0]), "+f"(d[1]), "+f"(d[2]), "+f"(d[3])
        : "r"(a[0]), "r"(a[1]), "r"(a[2]), "r"(a[3]), "r"(b[0]), "r"(b[1]));
}
__device__ __forceinline__ void cp16(uint32_t dst, const void* src) {
    asm volatile("cp.async.cg.shared.global [%0], [%1], 16;" :: "r"(dst), "l"(src));
}
__device__ __forceinline__ void cp_commit() {
    asm volatile("cp.async.commit_group;" ::: "memory");
}
template <int W> __device__ __forceinline__ void cp_wait() {
    asm volatile("cp.async.wait_group %0;" :: "n"(W) : "memory");
}

// ---------------- split-bf16 GEMM: C = scale*(A@B) (+bias) -------------------
// A: [M][K] row-major (hi/lo bf16), B: [N][K] k-contiguous (hi/lo bf16).
// 3-term MMA: hh + hl + lh.
template <bool CSKIP, bool TRIA, bool BIAS, bool WF32, bool WSPLIT>
__global__ __launch_bounds__(256) void gemm_bf16x3(
    const __nv_bfloat16* __restrict__ Ah, const __nv_bfloat16* __restrict__ Al,
    const __nv_bfloat16* __restrict__ Bh, const __nv_bfloat16* __restrict__ Bl,
    const float* __restrict__ bias,
    float* __restrict__ C, __nv_bfloat16* __restrict__ Ch, __nv_bfloat16* __restrict__ Cl,
    int K, int lda, int ldb, int ldc,
    int Hdiv,
    long long sAb, long long sAh,
    long long sBb, long long sBh,
    long long sCb, long long sCh,
    float scale)
{
    if (CSKIP && blockIdx.x > blockIdx.y) return;

    const int z = blockIdx.z, zb = z / Hdiv, zh = z % Hdiv;
    const long long offA = zb * sAb + zh * sAh;
    const long long offB = zb * sBb + zh * sBh;
    const long long offC = zb * sCb + zh * sCh;
    Ah += offA; Al += offA; Bh += offB; Bl += offB;
    C += offC; Ch += offC; Cl += offC;

    extern __shared__ char smem[];

    const int tid = threadIdx.x;
    const int m0 = blockIdx.y * BM, n0 = blockIdx.x * BN;
    const int Kend = TRIA ? min(K, m0 + BM) : K;
    const int ntiles = Kend >> 5;

    // ---- gmem -> smem tile copy (cp.async, XOR-swizzled) ----
    const int crow = tid >> 3;      // 0..31 base row
    const int cc   = tid & 7;       // 16B chunk 0..7 (0-3 = hi, 4-7 = lo)
    const __nv_bfloat16* aptr = (cc < 4) ? Ah : Al;
    const __nv_bfloat16* bptr = (cc < 4) ? Bh : Bl;
    const int kchunk = (cc & 3) << 3;   // bf16 offset within k-tile

    auto copy_tile = [&](int kt, int buf) {
        const int k0 = kt << 5;
        uint32_t abase = smem_u32(smem) + buf * 32768;
        uint32_t bbase = abase + 16384;
#pragma unroll
        for (int i = 0; i < 4; ++i) {
            int m = crow + (i << 5);
            cp16(abase + m * 128 + ((cc ^ (m & 7)) << 4),
                 aptr + (size_t)(m0 + m) * lda + k0 + kchunk);
        }
#pragma unroll
        for (int i = 0; i < 4; ++i) {
            int n = crow + (i << 5);
            cp16(bbase + n * 128 + ((cc ^ (n & 7)) << 4),
                 bptr + (size_t)(n0 + n) * ldb + k0 + kchunk);
        }
    };

    // ---- fragment compute ----
    const int warp = tid >> 5, lane = tid & 31;
    const int wm = warp >> 1, wn = warp & 1;          // 4x2 warp grid
    const int rselA = (lane & 7) + (((lane >> 3) & 1) << 3);
    const int chA   = (lane >> 4) & 1;
    const int rselB = (lane & 7) + (((lane >> 4) & 1) << 3);
    const int chB   = (lane >> 3) & 1;

    float acc[2][8][4];
#pragma unroll
    for (int a = 0; a < 2; ++a)
#pragma unroll
        for (int b = 0; b < 8; ++b)
#pragma unroll
            for (int c = 0; c < 4; ++c) acc[a][b][c] = 0.f;

    auto compute_tile = [&](int buf) {
        uint32_t abase = smem_u32(smem) + buf * 32768;
        uint32_t bbase = abase + 16384;
#pragma unroll
        for (int ks = 0; ks < 2; ++ks) {
            uint32_t ah[2][4], al[2][4];
#pragma unroll
            for (int mf = 0; mf < 2; ++mf) {
                int row = wm * 32 + mf * 16 + rselA;
                int chh = 2 * ks + chA;
                ldsm_x4(ah[mf], abase + row * 128 + ((chh ^ (row & 7)) << 4));
                int chl = chh + 4;
                ldsm_x4(al[mf], abase + row * 128 + ((chl ^ (row & 7)) << 4));
            }
#pragma unroll
            for (int np = 0; np < 4; ++np) {
                uint32_t bh[4], bl[4];
                int rowb = wn * 64 + np * 16 + rselB;
                int chh = 2 * ks + chB;
                ldsm_x4(bh, bbase + rowb * 128 + ((chh ^ (rowb & 7)) << 4));
                int chl = chh + 4;
                ldsm_x4(bl, bbase + rowb * 128 + ((chl ^ (rowb & 7)) << 4));
#pragma unroll
                for (int mf = 0; mf < 2; ++mf) {
                    mma_bf16(acc[mf][2 * np],     ah[mf], bh);
                    mma_bf16(acc[mf][2 * np],     ah[mf], bl);
                    mma_bf16(acc[mf][2 * np],     al[mf], bh);
                    mma_bf16(acc[mf][2 * np + 1], ah[mf], bh + 2);
                    mma_bf16(acc[mf][2 * np + 1], ah[mf], bl + 2);
                    mma_bf16(acc[mf][2 * np + 1], al[mf], bh + 2);
                }
            }
        }
    };

    // ---- pipelined main loop ----
    copy_tile(0, 0);
    cp_commit();
    for (int kt = 0; kt < ntiles; ++kt) {
        if (kt + 1 < ntiles) {
            copy_tile(kt + 1, (kt + 1) & 1);
            cp_commit();
            cp_wait<1>();
        } else {
            cp_wait<0>();
        }
        __syncthreads();
        compute_tile(kt & 1);
        __syncthreads();
    }

    // ---- epilogue ----
#pragma unroll
    for (int mf = 0; mf < 2; ++mf) {
        int row = m0 + wm * 32 + mf * 16 + (lane >> 2);
#pragma unroll
        for (int nf = 0; nf < 8; ++nf) {
            int col = n0 + wn * 64 + nf * 8 + (lane & 3) * 2;
            float v0 = acc[mf][nf][0] * scale, v1 = acc[mf][nf][1] * scale;
            float v2 = acc[mf][nf][2] * scale, v3 = acc[mf][nf][3] * scale;
            if (BIAS) {
                float b0 = bias[col], b1 = bias[col + 1];
                v0 += b0; v1 += b1; v2 += b0; v3 += b1;
            }
            size_t o0 = (size_t)row * ldc + col;
            size_t o1 = (size_t)(row + 8) * ldc + col;
            if (WF32) {
                *(float2*)(C + o0) = make_float2(v0, v1);
                *(float2*)(C + o1) = make_float2(v2, v3);
            }
            if (WSPLIT) {
                __nv_bfloat16 h0 = __float2bfloat16_rn(v0);
                __nv_bfloat16 h1 = __float2bfloat16_rn(v1);
                __nv_bfloat16 h2 = __float2bfloat16_rn(v2);
                __nv_bfloat16 h3 = __float2bfloat16_rn(v3);
                __nv_bfloat162 hp0; hp0.x = h0; hp0.y = h1;
                __nv_bfloat162 hp1; hp1.x = h2; hp1.y = h3;
                __nv_bfloat162 lp0;
                lp0.x = __float2bfloat16_rn(v0 - __bfloat162float(h0));
                lp0.y = __float2bfloat16_rn(v1 - __bfloat162float(h1));
                __nv_bfloat162 lp1;
                lp1.x = __float2bfloat16_rn(v2 - __bfloat162float(h2));
                lp1.y = __float2bfloat16_rn(v3 - __bfloat162float(h3));
                *(__nv_bfloat162*)(Ch + o0) = hp0;
                *(__nv_bfloat162*)(Ch + o1) = hp1;
                *(__nv_bfloat162*)(Cl + o0) = lp0;
                *(__nv_bfloat162*)(Cl + o1) = lp1;
            }
        }
    }
}

// ---------------- elementwise fp32 -> hi/lo bf16 ------------------------------
__global__ __launch_bounds__(256) void convert_split(
    const float* __restrict__ in, __nv_bfloat16* __restrict__ oh,
    __nv_bfloat16* __restrict__ ol, int n)
{
    for (int i = blockIdx.x * 256 + threadIdx.x; i < n; i += gridDim.x * 256) {
        float v = in[i];
        __nv_bfloat16 h = __float2bfloat16_rn(v);
        oh[i] = h;
        ol[i] = __float2bfloat16_rn(v - __bfloat162float(h));
    }
}

// ---------------- transpose + split: out[c][r] = in[r][c] ---------------------
__global__ __launch_bounds__(256) void transpose_split(
    const float* __restrict__ in, __nv_bfloat16* __restrict__ oh,
    __nv_bfloat16* __restrict__ ol,
    int ld_in, int ld_out, int Hdiv,
    long long sInB, long long sInH, long long sOutZ)
{
    const int z = blockIdx.z;
    in += (z / Hdiv) * sInB + (z % Hdiv) * sInH;
    oh += (long long)z * sOutZ;
    ol += (long long)z * sOutZ;

    __shared__ float t[32][33];
    const int c0 = blockIdx.x * 32, r0 = blockIdx.y * 32;
    const int tx = threadIdx.x, ty = threadIdx.y;   // 32 x 8
#pragma unroll
    for (int j = 0; j < 32; j += 8)
        t[ty + j][tx] = in[(size_t)(r0 + ty + j) * ld_in + c0 + tx];
    __syncthreads();
#pragma unroll
    for (int j = 0; j < 32; j += 8) {
        float v = t[tx][ty + j];
        __nv_bfloat16 h = __float2bfloat16_rn(v);
        size_t o = (size_t)(c0 + ty + j) * ld_out + r0 + tx;
        oh[o] = h;
        ol[o] = __float2bfloat16_rn(v - __bfloat162float(h));
    }
}

// ---------------- causal row softmax: fp32 scores -> hi/lo bf16 P -------------
__global__ __launch_bounds__(256) void softmax_causal(
    const float* __restrict__ scores,
    __nv_bfloat16* __restrict__ ph, __nv_bfloat16* __restrict__ pl)
{
    const long long row = blockIdx.x;
    const int s1 = (int)(row & (SEQ - 1));
    const float* p = scores + row * (long long)SEQ;
    __nv_bfloat16* oh = ph + row * (long long)SEQ;
    __nv_bfloat16* ol = pl + row * (long long)SEQ;
    const int len  = s1 + 1;
    const int kend = ((s1 >> 7) + 1) << 7;   // PV reads k < kend (tile boundary)
    const int tid  = threadIdx.x;

    float v[8];
    float mx = -3.402823e38f;
    int cnt = 0;
    for (int i = tid; i < len; i += 256) { float t = p[i]; v[cnt++] = t; mx = fmaxf(mx, t); }

    __shared__ float red[8];
#pragma unroll
    for (int o = 16; o; o >>= 1) mx = fmaxf(mx, __shfl_xor_sync(0xffffffffu, mx, o));
    if ((tid & 31) == 0) red[tid >> 5] = mx;
    __syncthreads();
    mx = red[0];
#pragma unroll
    for (int w = 1; w < 8; ++w) mx = fmaxf(mx, red[w]);
    __syncthreads();

    float s = 0.f;
#pragma unroll
    for (int j = 0; j < 8; ++j)
        if (j < cnt) { v[j] = __expf(v[j] - mx); s += v[j]; }
#pragma unroll
    for (int o = 16; o; o >>= 1) s += __shfl_xor_sync(0xffffffffu, s, o);
    if ((tid & 31) == 0) red[tid >> 5] = s;
    __syncthreads();
    s = 0.f;
#pragma unroll
    for (int w = 0; w < 8; ++w) s += red[w];
    const float inv = 1.0f / s;

    int j = 0;
    for (int i = tid; i < len; i += 256, ++j) {
        float w = v[j] * inv;
        __nv_bfloat16 h = __float2bfloat16_rn(w);
        oh[i] = h;
        ol[i] = __float2bfloat16_rn(w - __bfloat162float(h));
    }
    const __nv_bfloat16 z16 = __float2bfloat16(0.0f);
    for (int i = len + tid; i < kend; i += 256) { oh[i] = z16; ol[i] = z16; }
}

// ---------------- launch ------------------------------------------------------
extern "C" void kernel_launch(void* const* d_in, const int* in_sizes, int n_in,
                              void* d_out, int out_size)
{
    const float* x     = (const float*)d_in[0];
    const float* Wqkv  = (const float*)d_in[1];
    const float* bqkv  = (const float*)d_in[2];
    const float* Wproj = (const float*)d_in[3];
    const float* bproj = (const float*)d_in[4];
    float* out = (float*)d_out;

    __nv_bfloat16 *x_h, *x_l, *wqkvT_h, *wqkvT_l, *wprojT_h, *wprojT_l;
    __nv_bfloat16 *qkv_h, *qkv_l, *vT_h, *vT_l, *p_h, *p_l, *attn_h, *attn_l;
    float *qkv, *scores;
    cudaGetSymbolAddress((void**)&x_h, g_x_h);
    cudaGetSymbolAddress((void**)&x_l, g_x_l);
    cudaGetSymbolAddress((void**)&wqkvT_h, g_wqkvT_h);
    cudaGetSymbolAddress((void**)&wqkvT_l, g_wqkvT_l);
    cudaGetSymbolAddress((void**)&wprojT_h, g_wprojT_h);
    cudaGetSymbolAddress((void**)&wprojT_l, g_wprojT_l);
    cudaGetSymbolAddress((void**)&qkv,   g_qkv);
    cudaGetSymbolAddress((void**)&qkv_h, g_qkv_h);
    cudaGetSymbolAddress((void**)&qkv_l, g_qkv_l);
    cudaGetSymbolAddress((void**)&vT_h,  g_vT_h);
    cudaGetSymbolAddress((void**)&vT_l,  g_vT_l);
    cudaGetSymbolAddress((void**)&scores, g_scores);
    cudaGetSymbolAddress((void**)&p_h, g_p_h);
    cudaGetSymbolAddress((void**)&p_l, g_p_l);
    cudaGetSymbolAddress((void**)&attn_h, g_attn_h);
    cudaGetSymbolAddress((void**)&attn_l, g_attn_l);

    const int SMEM = 65536;
    cudaFuncSetAttribute(gemm_bf16x3<false, false, true,  true,  true >, cudaFuncAttributeMaxDynamicSharedMemorySize, SMEM);
    cudaFuncSetAttribute(gemm_bf16x3<true,  false, false, true,  false>, cudaFuncAttributeMaxDynamicSharedMemorySize, SMEM);
    cudaFuncSetAttribute(gemm_bf16x3<false, true,  false, false, true >, cudaFuncAttributeMaxDynamicSharedMemorySize, SMEM);
    cudaFuncSetAttribute(gemm_bf16x3<false, false, true,  true,  false>, cudaFuncAttributeMaxDynamicSharedMemorySize, SMEM);

    const int M  = BATCH * SEQ;   // 4096
    const int E  = N_EMBD;        // 2048
    const int E3 = 3 * N_EMBD;    // 6144
    const long long sQKV  = (long long)SEQ * E3;
    const long long sSS   = (long long)SEQ * SEQ;
    const long long sVT   = (long long)HEAD_DIM * SEQ;
    const float inv_sqrt_d = 0.08838834764831845f;

    // 0a) x -> hi/lo
    convert_split<<<4096, 256>>>(x, x_h, x_l, M * E);
    // 0b) Wqkv^T -> hi/lo   [6144][2048]
    transpose_split<<<dim3(E3 / 32, E / 32, 1), dim3(32, 8)>>>(
        Wqkv, wqkvT_h, wqkvT_l, E3, E, 1, 0, 0, 0);
    // 0c) Wproj^T -> hi/lo  [2048][2048]
    transpose_split<<<dim3(E / 32, E / 32, 1), dim3(32, 8)>>>(
        Wproj, wprojT_h, wprojT_l, E, E, 1, 0, 0, 0);

    // 1) qkv = x @ Wqkv + b   (writes fp32 + hi/lo)
    gemm_bf16x3<false, false, true, true, true><<<dim3(E3 / BN, M / BM, 1), 256, SMEM>>>(
        x_h, x_l, wqkvT_h, wqkvT_l, bqkv,
        qkv, qkv_h, qkv_l,
        E, E, E, E3,
        1, 0, 0, 0, 0, 0, 0, 1.f);

    // 1b) V^T per head -> hi/lo  [bh][128][2048]
    transpose_split<<<dim3(HEAD_DIM / 32, SEQ / 32, BATCH * N_HEAD), dim3(32, 8)>>>(
        qkv + 2 * E, vT_h, vT_l, E3, SEQ, N_HEAD, sQKV, HEAD_DIM, sVT);

    // 2) scores = Q @ K^T * inv_sqrt_d  (causal tile-skip, fp32 out)
    gemm_bf16x3<true, false, false, true, false><<<dim3(SEQ / BN, SEQ / BM, BATCH * N_HEAD), 256, SMEM>>>(
        qkv_h, qkv_l, qkv_h + E, qkv_l + E, nullptr,
        scores, p_h /*unused*/, p_l /*unused*/,
        HEAD_DIM, E3, E3, SEQ,
        N_HEAD, sQKV, HEAD_DIM, sQKV, HEAD_DIM,
        (long long)N_HEAD * sSS, sSS, inv_sqrt_d);

    // 3) causal softmax -> P hi/lo (zero-padded to 128 boundary)
    softmax_causal<<<BATCH * N_HEAD * SEQ, 256>>>(scores, p_h, p_l);

    // 4) attn = P @ V  (triangular K-limit, hi/lo out)
    gemm_bf16x3<false, true, false, false, true><<<dim3(HEAD_DIM / BN + (HEAD_DIM % BN ? 1 : 0), SEQ / BM, BATCH * N_HEAD), 256, SMEM>>>(
        p_h, p_l, vT_h, vT_l, nullptr,
        scores /*unused*/, attn_h, attn_l,
        SEQ, SEQ, SEQ, E,
        N_HEAD, (long long)N_HEAD * sSS, sSS,
        (long long)N_HEAD * sVT, sVT,
        (long long)SEQ * E, HEAD_DIM, 1.f);

    // 5) out = attn @ Wproj + b
    gemm_bf16x3<false, false, true, true, false><<<dim3(E / BN, M / BM, 1), 256, SMEM>>>(
        attn_h, attn_l, wprojT_h, wprojT_l, bproj,
        out, qkv_h /*unused*/, qkv_l /*unused*/,
        E, E, E, E,
        1, 0, 0, 0, 0, 0, 0, 1.f);
}

// round 3
// speedup vs baseline: 3.3927x; 1.0042x over previous
#include <cuda_runtime.h>
#include <cuda_bf16.h>
#include <cstdint>

#define N_EMBD 2048
#define N_HEAD 16
#define HEAD_DIM 128
#define BATCH 2
#define SEQ 2048

#define BM 128
#define BN 128
#define BK 32

// ---------------- scratch (static device globals) ----------------------------
__device__ __nv_bfloat16 g_x_h[(size_t)BATCH * SEQ * N_EMBD];
__device__ __nv_bfloat16 g_x_l[(size_t)BATCH * SEQ * N_EMBD];
__device__ __nv_bfloat16 g_wqkvT_h[(size_t)3 * N_EMBD * N_EMBD];
__device__ __nv_bfloat16 g_wqkvT_l[(size_t)3 * N_EMBD * N_EMBD];
__device__ __nv_bfloat16 g_wprojT_h[(size_t)N_EMBD * N_EMBD];
__device__ __nv_bfloat16 g_wprojT_l[(size_t)N_EMBD * N_EMBD];
__device__ float         g_qkv[(size_t)BATCH * SEQ * 3 * N_EMBD];
__device__ __nv_bfloat16 g_qkv_h[(size_t)BATCH * SEQ * 3 * N_EMBD];
__device__ __nv_bfloat16 g_qkv_l[(size_t)BATCH * SEQ * 3 * N_EMBD];
__device__ __nv_bfloat16 g_vT_h[(size_t)BATCH * N_HEAD * HEAD_DIM * SEQ];
__device__ __nv_bfloat16 g_vT_l[(size_t)BATCH * N_HEAD * HEAD_DIM * SEQ];
__device__ float         g_scores[(size_t)BATCH * N_HEAD * SEQ * SEQ];
__device__ __nv_bfloat16 g_p_h[(size_t)BATCH * N_HEAD * SEQ * SEQ];
__device__ __nv_bfloat16 g_p_l[(size_t)BATCH * N_HEAD * SEQ * SEQ];
__device__ __nv_bfloat16 g_attn_h[(size_t)BATCH * SEQ * N_EMBD];
__device__ __nv_bfloat16 g_attn_l[(size_t)BATCH * SEQ * N_EMBD];

// ---------------- PTX helpers -------------------------------------------------
__device__ __forceinline__ uint32_t smem_u32(const void* p) {
    return (uint32_t)__cvta_generic_to_shared(p);
}
__device__ __forceinline__ void ldsm_x4(uint32_t* r, uint32_t addr) {
    asm volatile("ldmatrix.sync.aligned.m8n8.x4.shared.b16 {%0,%1,%2,%3}, [%4];"
                 : "=r"(r[0]), "=r"(r[1]), "=r"(r[2]), "=r"(r[3]) : "r"(addr));
}
__device__ __forceinline__ void mma_bf16(float* d, const uint32_t* a, const uint32_t* b) {
    asm volatile(
        "mma.sync.aligned.m16n8k16.row.col.f32.bf16.bf16.f32 "
        "{%0,%1,%2,%3},{%4,%5,%6,%7},{%8,%9},{%0,%1,%2,%3};"
        : "+f"(d[0]), "+f"(d[1]), "+f"(d[2]), "+f"(d[3])
        : "r"(a[0]), "r"(a[1]), "r"(a[2]), "r"(a[3]), "r"(b[0]), "r"(b[1]));
}
__device__ __forceinline__ void cp16(uint32_t dst, const void* src) {
    asm volatile("cp.async.cg.shared.global [%0], [%1], 16;" :: "r"(dst), "l"(src));
}
__device__ __forceinline__ void cp_commit() {
    asm volatile("cp.async.commit_group;" ::: "memory");
}
template <int W> __device__ __forceinline__ void cp_wait() {
    asm volatile("cp.async.wait_group %0;" :: "n"(W) : "memory");
}

// ---------------- split-bf16 GEMM: C = scale*(A@B) (+bias) -------------------
// A: [M][K] row-major (hi/lo bf16), B: [N][K] k-contiguous (hi/lo bf16).
// 3-term MMA: hh + hl + lh.
template <bool CSKIP, bool TRIA, bool BIAS, bool WF32, bool WSPLIT>
__global__ __launch_bounds__(256) void gemm_bf16x3(
    const __nv_bfloat16* __restrict__ Ah, const __nv_bfloat16* __restrict__ Al,
    const __nv_bfloat16* __restrict__ Bh, const __nv_bfloat16* __restrict__ Bl,
    const float* __restrict__ bias,
    float* __restrict__ C, __nv_bfloat16* __restrict__ Ch, __nv_bfloat16* __restrict__ Cl,
    int K, int lda, int ldb, int ldc,
    int Hdiv,
    long long sAb, long long sAh,
    long long sBb, long long sBh,
    long long sCb, long long sCh,
    float scale)
{
    if (CSKIP && blockIdx.x > blockIdx.y) return;

    const int z = blockIdx.z, zb = z / Hdiv, zh = z % Hdiv;
    const long long offA = zb * sAb + zh * sAh;
    const long long offB = zb * sBb + zh * sBh;
    const long long offC = zb * sCb + zh * sCh;
    Ah += offA; Al += offA; Bh += offB; Bl += offB;
    C += offC; Ch += offC; Cl += offC;

    extern __shared__ char smem[];

    const int tid = threadIdx.x;
    const int m0 = blockIdx.y * BM, n0 = blockIdx.x * BN;
    const int Kend = TRIA ? min(K, m0 + BM) : K;
    const int ntiles = Kend >> 5;

    // ---- gmem -> smem tile copy (cp.async, XOR-swizzled) ----
    const int crow = tid >> 3;      // 0..31 base row
    const int cc   = tid & 7;       // 16B chunk 0..7 (0-3 = hi, 4-7 = lo)
    const __nv_bfloat16* aptr = (cc < 4) ? Ah : Al;
    const __nv_bfloat16* bptr = (cc < 4) ? Bh : Bl;
    const int kchunk = (cc & 3) << 3;   // bf16 offset within k-tile

    auto copy_tile = [&](int kt, int buf) {
        const int k0 = kt << 5;
        uint32_t abase = smem_u32(smem) + buf * 32768;
        uint32_t bbase = abase + 16384;
#pragma unroll
        for (int i = 0; i < 4; ++i) {
            int m = crow + (i << 5);
            cp16(abase + m * 128 + ((cc ^ (m & 7)) << 4),
                 aptr + (size_t)(m0 + m) * lda + k0 + kchunk);
        }
#pragma unroll
        for (int i = 0; i < 4; ++i) {
            int n = crow + (i << 5);
            cp16(bbase + n * 128 + ((cc ^ (n & 7)) << 4),
                 bptr + (size_t)(n0 + n) * ldb + k0 + kchunk);
        }
    };

    // ---- fragment compute ----
    const int warp = tid >> 5, lane = tid & 31;
    const int wm = warp >> 1, wn = warp & 1;          // 4x2 warp grid
    const int rselA = (lane & 7) + (((lane >> 3) & 1) << 3);
    const int chA   = (lane >> 4) & 1;
    const int rselB = (lane & 7) + (((lane >> 4) & 1) << 3);
    const int chB   = (lane >> 3) & 1;

    float acc[2][8][4];
#pragma unroll
    for (int a = 0; a < 2; ++a)
#pragma unroll
        for (int b = 0; b < 8; ++b)
#pragma unroll
            for (int c = 0; c < 4; ++c) acc[a][b][c] = 0.f;

    auto compute_tile = [&](int buf) {
        uint32_t abase = smem_u32(smem) + buf * 32768;
        uint32_t bbase = abase + 16384;
#pragma unroll
        for (int ks = 0; ks < 2; ++ks) {
            uint32_t ah[2][4], al[2][4];
#pragma unroll
            for (int mf = 0; mf < 2; ++mf) {
                int row = wm * 32 + mf * 16 + rselA;
                int chh = 2 * ks + chA;
                ldsm_x4(ah[mf], abase + row * 128 + ((chh ^ (row & 7)) << 4));
                int chl = chh + 4;
                ldsm_x4(al[mf], abase + row * 128 + ((chl ^ (row & 7)) << 4));
            }
#pragma unroll
            for (int np = 0; np < 4; ++np) {
                uint32_t bh[4], bl[4];
                int rowb = wn * 64 + np * 16 + rselB;
                int chh = 2 * ks + chB;
                ldsm_x4(bh, bbase + rowb * 128 + ((chh ^ (rowb & 7)) << 4));
                int chl = chh + 4;
                ldsm_x4(bl, bbase + rowb * 128 + ((chl ^ (rowb & 7)) << 4));
#pragma unroll
                for (int mf = 0; mf < 2; ++mf) {
                    mma_bf16(acc[mf][2 * np],     ah[mf], bh);
                    mma_bf16(acc[mf][2 * np],     ah[mf], bl);
                    mma_bf16(acc[mf][2 * np],     al[mf], bh);
                    mma_bf16(acc[mf][2 * np + 1], ah[mf], bh + 2);
                    mma_bf16(acc[mf][2 * np + 1], ah[mf], bl + 2);
                    mma_bf16(acc[mf][2 * np + 1], al[mf], bh + 2);
                }
            }
        }
    };

    // ---- pipelined main loop ----
    copy_tile(0, 0);
    cp_commit();
    for (int kt = 0; kt < ntiles; ++kt) {
        if (kt + 1 < ntiles) {
            copy_tile(kt + 1, (kt + 1) & 1);
            cp_commit();
            cp_wait<1>();
        } else {
            cp_wait<0>();
        }
        __syncthreads();
        compute_tile(kt & 1);
        __syncthreads();
    }

    // ---- epilogue ----
#pragma unroll
    for (int mf = 0; mf < 2; ++mf) {
        int row = m0 + wm * 32 + mf * 16 + (lane >> 2);
#pragma unroll
        for (int nf = 0; nf < 8; ++nf) {
            int col = n0 + wn * 64 + nf * 8 + (lane & 3) * 2;
            float v0 = acc[mf][nf][0] * scale, v1 = acc[mf][nf][1] * scale;
            float v2 = acc[mf][nf][2] * scale, v3 = acc[mf][nf][3] * scale;
            if (BIAS) {
                float b0 = bias[col], b1 = bias[col + 1];
                v0 += b0; v1 += b1; v2 += b0; v3 += b1;
            }
            size_t o0 = (size_t)row * ldc + col;
            size_t o1 = (size_t)(row + 8) * ldc + col;
            if (WF32) {
                *(float2*)(C + o0) = make_float2(v0, v1);
                *(float2*)(C + o1) = make_float2(v2, v3);
            }
            if (WSPLIT) {
                __nv_bfloat16 h0 = __float2bfloat16_rn(v0);
                __nv_bfloat16 h1 = __float2bfloat16_rn(v1);
                __nv_bfloat16 h2 = __float2bfloat16_rn(v2);
                __nv_bfloat16 h3 = __float2bfloat16_rn(v3);
                __nv_bfloat162 hp0; hp0.x = h0; hp0.y = h1;
                __nv_bfloat162 hp1; hp1.x = h2; hp1.y = h3;
                __nv_bfloat162 lp0;
                lp0.x = __float2bfloat16_rn(v0 - __bfloat162float(h0));
                lp0.y = __float2bfloat16_rn(v1 - __bfloat162float(h1));
                __nv_bfloat162 lp1;
                lp1.x = __float2bfloat16_rn(v2 - __bfloat162float(h2));
                lp1.y = __float2bfloat16_rn(v3 - __bfloat162float(h3));
                *(__nv_bfloat162*)(Ch + o0) = hp0;
                *(__nv_bfloat162*)(Ch + o1) = hp1;
                *(__nv_bfloat162*)(Cl + o0) = lp0;
                *(__nv_bfloat162*)(Cl + o1) = lp1;
            }
        }
    }
}

// ---------------- elementwise fp32 -> hi/lo bf16 ------------------------------
__global__ __launch_bounds__(256) void convert_split(
    const float* __restrict__ in, __nv_bfloat16* __restrict__ oh,
    __nv_bfloat16* __restrict__ ol, int n)
{
    for (int i = blockIdx.x * 256 + threadIdx.x; i < n; i += gridDim.x * 256) {
        float v = in[i];
        __nv_bfloat16 h = __float2bfloat16_rn(v);
        oh[i] = h;
        ol[i] = __float2bfloat16_rn(v - __bfloat162float(h));
    }
}

// ---------------- transpose + split: out[c][r] = in[r][c] ---------------------
__global__ __launch_bounds__(256) void transpose_split(
    const float* __restrict__ in, __nv_bfloat16* __restrict__ oh,
    __nv_bfloat16* __restrict__ ol,
    int ld_in, int ld_out, int Hdiv,
    long long sInB, long long sInH, long long sOutZ)
{
    const int z = blockIdx.z;
    in += (z / Hdiv) * sInB + (z % Hdiv) * sInH;
    oh += (long long)z * sOutZ;
    ol += (long long)z * sOutZ;

    __shared__ float t[32][33];
    const int c0 = blockIdx.x * 32, r0 = blockIdx.y * 32;
    const int tx = threadIdx.x, ty = threadIdx.y;   // 32 x 8
#pragma unroll
    for (int j = 0; j < 32; j += 8)
        t[ty + j][tx] = in[(size_t)(r0 + ty + j) * ld_in + c0 + tx];
    __syncthreads();
#pragma unroll
    for (int j = 0; j < 32; j += 8) {
        float v = t[tx][ty + j];
        __nv_bfloat16 h = __float2bfloat16_rn(v);
        size_t o = (size_t)(c0 + ty + j) * ld_out + r0 + tx;
        oh[o] = h;
        ol[o] = __float2bfloat16_rn(v - __bfloat162float(h));
    }
}

// ---------------- causal row softmax: fp32 scores -> hi/lo bf16 P -------------
__global__ __launch_bounds__(256) void softmax_causal(
    const float* __restrict__ scores,
    __nv_bfloat16* __restrict__ ph, __nv_bfloat16* __restrict__ pl)
{
    const long long row = blockIdx.x;
    const int s1 = (int)(row & (SEQ - 1));
    const float* p = scores + row * (long long)SEQ;
    __nv_bfloat16* oh = ph + row * (long long)SEQ;
    __nv_bfloat16* ol = pl + row * (long long)SEQ;
    const int len  = s1 + 1;
    const int kend = ((s1 >> 7) + 1) << 7;   // PV reads k < kend (tile boundary)
    const int tid  = threadIdx.x;

    float v[8];
    float mx = -3.402823e38f;
    int cnt = 0;
    for (int i = tid; i < len; i += 256) { float t = p[i]; v[cnt++] = t; mx = fmaxf(mx, t); }

    __shared__ float red[8];
#pragma unroll
    for (int o = 16; o; o >>= 1) mx = fmaxf(mx, __shfl_xor_sync(0xffffffffu, mx, o));
    if ((tid & 31) == 0) red[tid >> 5] = mx;
    __syncthreads();
    mx = red[0];
#pragma unroll
    for (int w = 1; w < 8; ++w) mx = fmaxf(mx, red[w]);
    __syncthreads();

    float s = 0.f;
#pragma unroll
    for (int j = 0; j < 8; ++j)
        if (j < cnt) { v[j] = __expf(v[j] - mx); s += v[j]; }
#pragma unroll
    for (int o = 16; o; o >>= 1) s += __shfl_xor_sync(0xffffffffu, s, o);
    if ((tid & 31) == 0) red[tid >> 5] = s;
    __syncthreads();
    s = 0.f;
#pragma unroll
    for (int w = 0; w < 8; ++w) s += red[w];
    const float inv = 1.0f / s;

    int j = 0;
    for (int i = tid; i < len; i += 256, ++j) {
        float w = v[j] * inv;
        __nv_bfloat16 h = __float2bfloat16_rn(w);
        oh[i] = h;
        ol[i] = __float2bfloat16_rn(w - __bfloat162float(h));
    }
    const __nv_bfloat16 z16 = __float2bfloat16(0.0f);
    for (int i = len + tid; i < kend; i += 256) { oh[i] = z16; ol[i] = z16; }
}

// ---------------- launch ------------------------------------------------------
extern "C" void kernel_launch(void* const* d_in, const int* in_sizes, int n_in,
                              void* d_out, int out_size)
{
    const float* x     = (const float*)d_in[0];
    const float* Wqkv  = (const float*)d_in[1];
    const float* bqkv  = (const float*)d_in[2];
    const float* Wproj = (const float*)d_in[3];
    const float* bproj = (const float*)d_in[4];
    float* out = (float*)d_out;

    __nv_bfloat16 *x_h, *x_l, *wqkvT_h, *wqkvT_l, *wprojT_h, *wprojT_l;
    __nv_bfloat16 *qkv_h, *qkv_l, *vT_h, *vT_l, *p_h, *p_l, *attn_h, *attn_l;
    float *qkv, *scores;
    cudaGetSymbolAddress((void**)&x_h, g_x_h);
    cudaGetSymbolAddress((void**)&x_l, g_x_l);
    cudaGetSymbolAddress((void**)&wqkvT_h, g_wqkvT_h);
    cudaGetSymbolAddress((void**)&wqkvT_l, g_wqkvT_l);
    cudaGetSymbolAddress((void**)&wprojT_h, g_wprojT_h);
    cudaGetSymbolAddress((void**)&wprojT_l, g_wprojT_l);
    cudaGetSymbolAddress((void**)&qkv,   g_qkv);
    cudaGetSymbolAddress((void**)&qkv_h, g_qkv_h);
    cudaGetSymbolAddress((void**)&qkv_l, g_qkv_l);
    cudaGetSymbolAddress((void**)&vT_h,  g_vT_h);
    cudaGetSymbolAddress((void**)&vT_l,  g_vT_l);
    cudaGetSymbolAddress((void**)&scores, g_scores);
    cudaGetSymbolAddress((void**)&p_h, g_p_h);
    cudaGetSymbolAddress((void**)&p_l, g_p_l);
    cudaGetSymbolAddress((void**)&attn_h, g_attn_h);
    cudaGetSymbolAddress((void**)&attn_l, g_attn_l);

    const int SMEM = 65536;
    cudaFuncSetAttribute(gemm_bf16x3<false, false, true,  true,  true >, cudaFuncAttributeMaxDynamicSharedMemorySize, SMEM);
    cudaFuncSetAttribute(gemm_bf16x3<true,  false, false, true,  false>, cudaFuncAttributeMaxDynamicSharedMemorySize, SMEM);
    cudaFuncSetAttribute(gemm_bf16x3<false, true,  false, false, true >, cudaFuncAttributeMaxDynamicSharedMemorySize, SMEM);
    cudaFuncSetAttribute(gemm_bf16x3<false, false, true,  true,  false>, cudaFuncAttributeMaxDynamicSharedMemorySize, SMEM);

    const int M  = BATCH * SEQ;   // 4096
    const int E  = N_EMBD;        // 2048
    const int E3 = 3 * N_EMBD;    // 6144
    const long long sQKV  = (long long)SEQ * E3;
    const long long sSS   = (long long)SEQ * SEQ;
    const long long sVT   = (long long)HEAD_DIM * SEQ;
    const float inv_sqrt_d = 0.08838834764831845f;

    // 0a) x -> hi/lo
    convert_split<<<4096, 256>>>(x, x_h, x_l, M * E);
    // 0b) Wqkv^T -> hi/lo   [6144][2048]
    transpose_split<<<dim3(E3 / 32, E / 32, 1), dim3(32, 8)>>>(
        Wqkv, wqkvT_h, wqkvT_l, E3, E, 1, 0, 0, 0);
    // 0c) Wproj^T -> hi/lo  [2048][2048]
    transpose_split<<<dim3(E / 32, E / 32, 1), dim3(32, 8)>>>(
        Wproj, wprojT_h, wprojT_l, E, E, 1, 0, 0, 0);

    // 1) qkv = x @ Wqkv + b   (writes fp32 + hi/lo)
    gemm_bf16x3<false, false, true, true, true><<<dim3(E3 / BN, M / BM, 1), 256, SMEM>>>(
        x_h, x_l, wqkvT_h, wqkvT_l, bqkv,
        qkv, qkv_h, qkv_l,
        E, E, E, E3,
        1, 0, 0, 0, 0, 0, 0, 1.f);

    // 1b) V^T per head -> hi/lo  [bh][128][2048]
    transpose_split<<<dim3(HEAD_DIM / 32, SEQ / 32, BATCH * N_HEAD), dim3(32, 8)>>>(
        qkv + 2 * E, vT_h, vT_l, E3, SEQ, N_HEAD, sQKV, HEAD_DIM, sVT);

    // 2) scores = Q @ K^T * inv_sqrt_d  (causal tile-skip, fp32 out)
    gemm_bf16x3<true, false, false, true, false><<<dim3(SEQ / BN, SEQ / BM, BATCH * N_HEAD), 256, SMEM>>>(
        qkv_h, qkv_l, qkv_h + E, qkv_l + E, nullptr,
        scores, p_h /*unused*/, p_l /*unused*/,
        HEAD_DIM, E3, E3, SEQ,
        N_HEAD, sQKV, HEAD_DIM, sQKV, HEAD_DIM,
        (long long)N_HEAD * sSS, sSS, inv_sqrt_d);

    // 3) causal softmax -> P hi/lo (zero-padded to 128 boundary)
    softmax_causal<<<BATCH * N_HEAD * SEQ, 256>>>(scores, p_h, p_l);

    // 4) attn = P @ V  (triangular K-limit, hi/lo out)
    gemm_bf16x3<false, true, false, false, true><<<dim3(HEAD_DIM / BN + (HEAD_DIM % BN ? 1 : 0), SEQ / BM, BATCH * N_HEAD), 256, SMEM>>>(
        p_h, p_l, vT_h, vT_l, nullptr,
        scores /*unused*/, attn_h, attn_l,
        SEQ, SEQ, SEQ, E,
        N_HEAD, (long long)N_HEAD * sSS, sSS,
        (long long)N_HEAD * sVT, sVT,
        (long long)SEQ * E, HEAD_DIM, 1.f);

    // 5) out = attn @ Wproj + b
    gemm_bf16x3<false, false, true, true, false><<<dim3(E / BN, M / BM, 1), 256, SMEM>>>(
        attn_h, attn_l, wprojT_h, wprojT_l, bproj,
        out, qkv_h /*unused*/, qkv_l /*unused*/,
        E, E, E, E,
        1, 0, 0, 0, 0, 0, 0, 1.f);
}

// round 5
// speedup vs baseline: 3.9362x; 1.1602x over previous
#include <cuda_runtime.h>
#include <cuda_bf16.h>
#include <cstdint>

#define N_EMBD 2048
#define N_HEAD 16
#define HEAD_DIM 128
#define BATCH 2
#define SEQ 2048

#define BM 128
#define BN 128

// ---------------- scratch ----------------------------------------------------
__device__ __nv_bfloat16 g_x_h[(size_t)BATCH * SEQ * N_EMBD];
__device__ __nv_bfloat16 g_x_l[(size_t)BATCH * SEQ * N_EMBD];
__device__ __nv_bfloat16 g_wqkvT_h[(size_t)3 * N_EMBD * N_EMBD];
__device__ __nv_bfloat16 g_wqkvT_l[(size_t)3 * N_EMBD * N_EMBD];
__device__ __nv_bfloat16 g_wprojT_h[(size_t)N_EMBD * N_EMBD];
__device__ __nv_bfloat16 g_wprojT_l[(size_t)N_EMBD * N_EMBD];
__device__ __nv_bfloat16 g_qkv_h[(size_t)BATCH * SEQ * 3 * N_EMBD];
__device__ __nv_bfloat16 g_qkv_l[(size_t)BATCH * SEQ * 3 * N_EMBD];
__device__ __nv_bfloat16 g_attn_h[(size_t)BATCH * SEQ * N_EMBD];
__device__ __nv_bfloat16 g_attn_l[(size_t)BATCH * SEQ * N_EMBD];

// ---------------- PTX helpers -------------------------------------------------
__device__ __forceinline__ uint32_t smem_u32(const void* p) {
    return (uint32_t)__cvta_generic_to_shared(p);
}
__device__ __forceinline__ void ldsm_x4(uint32_t* r, uint32_t addr) {
    asm volatile("ldmatrix.sync.aligned.m8n8.x4.shared.b16 {%0,%1,%2,%3}, [%4];"
                 : "=r"(r[0]), "=r"(r[1]), "=r"(r[2]), "=r"(r[3]) : "r"(addr));
}
__device__ __forceinline__ void ldsm_x4_t(uint32_t* r, uint32_t addr) {
    asm volatile("ldmatrix.sync.aligned.m8n8.x4.trans.shared.b16 {%0,%1,%2,%3}, [%4];"
                 : "=r"(r[0]), "=r"(r[1]), "=r"(r[2]), "=r"(r[3]) : "r"(addr));
}
__device__ __forceinline__ void mma_bf16(float* d, const uint32_t* a, const uint32_t* b) {
    asm volatile(
        "mma.sync.aligned.m16n8k16.row.col.f32.bf16.bf16.f32 "
        "{%0,%1,%2,%3},{%4,%5,%6,%7},{%8,%9},{%0,%1,%2,%3};"
        : "+f"(d[0]), "+f"(d[1]), "+f"(d[2]), "+f"(d[3])
        : "r"(a[0]), "r"(a[1]), "r"(a[2]), "r"(a[3]), "r"(b[0]), "r"(b[1]));
}
__device__ __forceinline__ void cp16(uint32_t dst, const void* src) {
    asm volatile("cp.async.cg.shared.global [%0], [%1], 16;" :: "r"(dst), "l"(src));
}
__device__ __forceinline__ void cp_commit() {
    asm volatile("cp.async.commit_group;" ::: "memory");
}
template <int W> __device__ __forceinline__ void cp_wait() {
    asm volatile("cp.async.wait_group %0;" :: "n"(W) : "memory");
}
__device__ __forceinline__ uint32_t packbf(__nv_bfloat16 a, __nv_bfloat16 b) {
    __nv_bfloat162 t; t.x = a; t.y = b;
    uint32_t u; *(__nv_bfloat162*)&u = t; return u;
}

// ---------------- split-bf16 GEMM (proven round-2 core, term-interleaved) -----
template <bool BIAS, bool WF32, bool WSPLIT>
__global__ __launch_bounds__(256) void gemm_bf16x3(
    const __nv_bfloat16* __restrict__ Ah, const __nv_bfloat16* __restrict__ Al,
    const __nv_bfloat16* __restrict__ Bh, const __nv_bfloat16* __restrict__ Bl,
    const float* __restrict__ bias,
    float* __restrict__ C, __nv_bfloat16* __restrict__ Ch, __nv_bfloat16* __restrict__ Cl,
    int K, int lda, int ldb, int ldc, float scale)
{
    extern __shared__ char smem[];
    const int tid = threadIdx.x;
    const int m0 = blockIdx.y * BM, n0 = blockIdx.x * BN;
    const int ntiles = K >> 5;

    const int crow = tid >> 3;
    const int cc   = tid & 7;
    const __nv_bfloat16* aptr = (cc < 4) ? Ah : Al;
    const __nv_bfloat16* bptr = (cc < 4) ? Bh : Bl;
    const int kchunk = (cc & 3) << 3;

    auto copy_tile = [&](int kt, int buf) {
        const int k0 = kt << 5;
        uint32_t abase = smem_u32(smem) + buf * 32768;
        uint32_t bbase = abase + 16384;
#pragma unroll
        for (int i = 0; i < 4; ++i) {
            int m = crow + (i << 5);
            cp16(abase + m * 128 + ((cc ^ (m & 7)) << 4),
                 aptr + (size_t)(m0 + m) * lda + k0 + kchunk);
        }
#pragma unroll
        for (int i = 0; i < 4; ++i) {
            int n = crow + (i << 5);
            cp16(bbase + n * 128 + ((cc ^ (n & 7)) << 4),
                 bptr + (size_t)(n0 + n) * ldb + k0 + kchunk);
        }
    };

    const int warp = tid >> 5, lane = tid & 31;
    const int wm = warp >> 1, wn = warp & 1;
    const int rselA = (lane & 7) + (((lane >> 3) & 1) << 3);
    const int chA   = (lane >> 4) & 1;
    const int rselB = (lane & 7) + (((lane >> 4) & 1) << 3);
    const int chB   = (lane >> 3) & 1;

    float acc[2][8][4];
#pragma unroll
    for (int a = 0; a < 2; ++a)
#pragma unroll
        for (int b = 0; b < 8; ++b)
#pragma unroll
            for (int c = 0; c < 4; ++c) acc[a][b][c] = 0.f;

    auto compute_tile = [&](int buf) {
        uint32_t abase = smem_u32(smem) + buf * 32768;
        uint32_t bbase = abase + 16384;
#pragma unroll
        for (int ks = 0; ks < 2; ++ks) {
            uint32_t ah[2][4], al[2][4];
#pragma unroll
            for (int mf = 0; mf < 2; ++mf) {
                int row = wm * 32 + mf * 16 + rselA;
                int chh = 2 * ks + chA;
                ldsm_x4(ah[mf], abase + row * 128 + ((chh ^ (row & 7)) << 4));
                ldsm_x4(al[mf], abase + row * 128 + (((chh + 4) ^ (row & 7)) << 4));
            }
#pragma unroll
            for (int np = 0; np < 4; ++np) {
                uint32_t bh[4], bl[4];
                int rowb = wn * 64 + np * 16 + rselB;
                int chh = 2 * ks + chB;
                ldsm_x4(bh, bbase + rowb * 128 + ((chh ^ (rowb & 7)) << 4));
                ldsm_x4(bl, bbase + rowb * 128 + (((chh + 4) ^ (rowb & 7)) << 4));
#pragma unroll
                for (int mf = 0; mf < 2; ++mf) {
                    mma_bf16(acc[mf][2 * np],     ah[mf], bh);
                    mma_bf16(acc[mf][2 * np + 1], ah[mf], bh + 2);
                    mma_bf16(acc[mf][2 * np],     ah[mf], bl);
                    mma_bf16(acc[mf][2 * np + 1], ah[mf], bl + 2);
                    mma_bf16(acc[mf][2 * np],     al[mf], bh);
                    mma_bf16(acc[mf][2 * np + 1], al[mf], bh + 2);
                }
            }
        }
    };

    copy_tile(0, 0);
    cp_commit();
    for (int kt = 0; kt < ntiles; ++kt) {
        if (kt + 1 < ntiles) {
            copy_tile(kt + 1, (kt + 1) & 1);
            cp_commit();
            cp_wait<1>();
        } else {
            cp_wait<0>();
        }
        __syncthreads();
        compute_tile(kt & 1);
        __syncthreads();
    }

#pragma unroll
    for (int mf = 0; mf < 2; ++mf) {
        int row = m0 + wm * 32 + mf * 16 + (lane >> 2);
#pragma unroll
        for (int nf = 0; nf < 8; ++nf) {
            int col = n0 + wn * 64 + nf * 8 + (lane & 3) * 2;
            float v0 = acc[mf][nf][0] * scale, v1 = acc[mf][nf][1] * scale;
            float v2 = acc[mf][nf][2] * scale, v3 = acc[mf][nf][3] * scale;
            if (BIAS) {
                float b0 = bias[col], b1 = bias[col + 1];
                v0 += b0; v1 += b1; v2 += b0; v3 += b1;
            }
            size_t o0 = (size_t)row * ldc + col;
            size_t o1 = (size_t)(row + 8) * ldc + col;
            if (WF32) {
                *(float2*)(C + o0) = make_float2(v0, v1);
                *(float2*)(C + o1) = make_float2(v2, v3);
            }
            if (WSPLIT) {
                __nv_bfloat16 h0 = __float2bfloat16_rn(v0);
                __nv_bfloat16 h1 = __float2bfloat16_rn(v1);
                __nv_bfloat16 h2 = __float2bfloat16_rn(v2);
                __nv_bfloat16 h3 = __float2bfloat16_rn(v3);
                *(uint32_t*)(Ch + o0) = packbf(h0, h1);
                *(uint32_t*)(Ch + o1) = packbf(h2, h3);
                *(uint32_t*)(Cl + o0) = packbf(
                    __float2bfloat16_rn(v0 - __bfloat162float(h0)),
                    __float2bfloat16_rn(v1 - __bfloat162float(h1)));
                *(uint32_t*)(Cl + o1) = packbf(
                    __float2bfloat16_rn(v2 - __bfloat162float(h2)),
                    __float2bfloat16_rn(v3 - __bfloat162float(h3)));
            }
        }
    }
}

// ---------------- fused flash attention ---------------------------------------
// 256 thr (8 warps x 16 q-rows). Q tile 128, KV tile 64, D=128.
// qkv layout: [b][s][6144]; Q at h*128, K at 2048+h*128, V at 4096+h*128.
__global__ __launch_bounds__(256) void flash_attn(
    const __nv_bfloat16* __restrict__ qkvh, const __nv_bfloat16* __restrict__ qkvl,
    __nv_bfloat16* __restrict__ outh, __nv_bfloat16* __restrict__ outl)
{
    const int qi = 15 - (int)blockIdx.x;   // big tiles first
    const int bh = blockIdx.y;
    const int b = bh >> 4, h = bh & 15;
    const int q0 = qi * 128;
    const size_t base = (size_t)b * SEQ * 6144 + (size_t)h * 128;
    const __nv_bfloat16* Qp[2] = {qkvh + base, qkvl + base};
    const __nv_bfloat16* KVsrc[4] = {qkvh + base + 2048, qkvl + base + 2048,
                                     qkvh + base + 4096, qkvl + base + 4096};

    extern __shared__ char smem[];
    const uint32_t S0 = smem_u32(smem);
    const int tid = threadIdx.x, lane = tid & 31, warp = tid >> 5;

    // Q copy: 2 halves x (128 rows x 16 chunks)
#pragma unroll
    for (int half = 0; half < 2; ++half) {
        const __nv_bfloat16* src = Qp[half];
        const uint32_t qb = S0 + half * 32768;
#pragma unroll
        for (int i = 0; i < 8; ++i) {
            int idx = tid + i * 256;
            int row = idx >> 4, c = idx & 15, p = c >> 3, c8 = c & 7;
            cp16(qb + p * 16384 + row * 128 + ((c8 ^ (row & 7)) << 4),
                 src + (size_t)(q0 + row) * 6144 + p * 64 + c8 * 8);
        }
    }

    auto copy_kv = [&](int t) {
        const uint32_t sb = S0 + 65536 + (uint32_t)(t & 1) * 65536;
        const int kv0 = t * 64;
#pragma unroll
        for (int q = 0; q < 4; ++q) {
#pragma unroll
            for (int i = 0; i < 4; ++i) {
                int idx = tid + i * 256;
                int row = idx >> 4, c = idx & 15, p = c >> 3, c8 = c & 7;
                cp16(sb + q * 16384 + p * 8192 + row * 128 + ((c8 ^ (row & 7)) << 4),
                     KVsrc[q] + (size_t)(kv0 + row) * 6144 + p * 64 + c8 * 8);
            }
        }
    };

    const int rselA = (lane & 7) + (((lane >> 3) & 1) << 3);
    const int chA   = (lane >> 4) & 1;
    const int rselB = (lane & 7) + (((lane >> 4) & 1) << 3);
    const int chB   = (lane >> 3) & 1;
    const int qr = warp * 16;

    float m0 = -1e30f, m1 = -1e30f, l0 = 0.f, l1 = 0.f;
    float accO[16][4];
#pragma unroll
    for (int j = 0; j < 16; ++j)
#pragma unroll
        for (int c = 0; c < 4; ++c) accO[j][c] = 0.f;

    const int nt = 2 * qi + 2;
    copy_kv(0); cp_commit();
    if (nt > 1) { copy_kv(1); cp_commit(); }

    for (int t = 0; t < nt; ++t) {
        if (t + 1 < nt) cp_wait<1>(); else cp_wait<0>();
        __syncthreads();

        const uint32_t sb  = S0 + 65536 + (uint32_t)(t & 1) * 65536;
        const uint32_t sKh = sb, sKl = sb + 16384, sVh = sb + 32768, sVl = sb + 49152;

        // ---- S = Q K^T ----
        float accS[8][4];
#pragma unroll
        for (int j = 0; j < 8; ++j)
#pragma unroll
            for (int c = 0; c < 4; ++c) accS[j][c] = 0.f;

#pragma unroll
        for (int ks = 0; ks < 8; ++ks) {
            uint32_t aH[4], aL[4];
            {
                int row = qr + rselA;
                int g = ks * 2 + chA, p = g >> 3, c8 = g & 7;
                uint32_t off = (uint32_t)p * 16384 + row * 128 + ((c8 ^ (row & 7)) << 4);
                ldsm_x4(aH, S0 + off);
                ldsm_x4(aL, S0 + 32768 + off);
            }
            uint32_t bH[4][4], bL[4][4];
#pragma unroll
            for (int n2 = 0; n2 < 4; ++n2) {
                int row = n2 * 16 + rselB;
                int g = ks * 2 + chB, p = g >> 3, c8 = g & 7;
                uint32_t off = (uint32_t)p * 8192 + row * 128 + ((c8 ^ (row & 7)) << 4);
                ldsm_x4(bH[n2], sKh + off);
                ldsm_x4(bL[n2], sKl + off);
            }
#pragma unroll
            for (int n2 = 0; n2 < 4; ++n2) {
                mma_bf16(accS[2 * n2],     aH, bH[n2]);
                mma_bf16(accS[2 * n2 + 1], aH, bH[n2] + 2);
            }
#pragma unroll
            for (int n2 = 0; n2 < 4; ++n2) {
                mma_bf16(accS[2 * n2],     aH, bL[n2]);
                mma_bf16(accS[2 * n2 + 1], aH, bL[n2] + 2);
            }
#pragma unroll
            for (int n2 = 0; n2 < 4; ++n2) {
                mma_bf16(accS[2 * n2],     aL, bH[n2]);
                mma_bf16(accS[2 * n2 + 1], aL, bH[n2] + 2);
            }
        }

        // ---- scale + causal mask + online softmax ----
        const float isd = 0.08838834764831845f;
        const int kv0 = t * 64;
        const int grow0 = q0 + qr + (lane >> 2);
        const int grow1 = grow0 + 8;
        const bool masked = (t >= 2 * qi);
#pragma unroll
        for (int nf = 0; nf < 8; ++nf) {
#pragma unroll
            for (int c = 0; c < 4; ++c) accS[nf][c] *= isd;
            if (masked) {
                int col = kv0 + nf * 8 + (lane & 3) * 2;
                if (col     > grow0) accS[nf][0] = -1e30f;
                if (col + 1 > grow0) accS[nf][1] = -1e30f;
                if (col     > grow1) accS[nf][2] = -1e30f;
                if (col + 1 > grow1) accS[nf][3] = -1e30f;
            }
        }
        float mx0 = -1e30f, mx1 = -1e30f;
#pragma unroll
        for (int nf = 0; nf < 8; ++nf) {
            mx0 = fmaxf(mx0, fmaxf(accS[nf][0], accS[nf][1]));
            mx1 = fmaxf(mx1, fmaxf(accS[nf][2], accS[nf][3]));
        }
        mx0 = fmaxf(mx0, __shfl_xor_sync(0xffffffffu, mx0, 1));
        mx0 = fmaxf(mx0, __shfl_xor_sync(0xffffffffu, mx0, 2));
        mx1 = fmaxf(mx1, __shfl_xor_sync(0xffffffffu, mx1, 1));
        mx1 = fmaxf(mx1, __shfl_xor_sync(0xffffffffu, mx1, 2));
        const float nm0 = fmaxf(m0, mx0), nm1 = fmaxf(m1, mx1);
        const float cr0 = __expf(m0 - nm0), cr1 = __expf(m1 - nm1);
        m0 = nm0; m1 = nm1;

        float rs0 = 0.f, rs1 = 0.f;
        uint32_t phr[8], phr8[8], plr[8], plr8[8];
#pragma unroll
        for (int nf = 0; nf < 8; ++nf) {
            float p0 = __expf(accS[nf][0] - nm0), p1 = __expf(accS[nf][1] - nm0);
            float p2 = __expf(accS[nf][2] - nm1), p3 = __expf(accS[nf][3] - nm1);
            rs0 += p0 + p1; rs1 += p2 + p3;
            __nv_bfloat16 h0 = __float2bfloat16_rn(p0), h1 = __float2bfloat16_rn(p1);
            __nv_bfloat16 h2 = __float2bfloat16_rn(p2), h3 = __float2bfloat16_rn(p3);
            phr[nf]  = packbf(h0, h1);
            phr8[nf] = packbf(h2, h3);
            plr[nf]  = packbf(__float2bfloat16_rn(p0 - __bfloat162float(h0)),
                              __float2bfloat16_rn(p1 - __bfloat162float(h1)));
            plr8[nf] = packbf(__float2bfloat16_rn(p2 - __bfloat162float(h2)),
                              __float2bfloat16_rn(p3 - __bfloat162float(h3)));
        }
        rs0 += __shfl_xor_sync(0xffffffffu, rs0, 1);
        rs0 += __shfl_xor_sync(0xffffffffu, rs0, 2);
        rs1 += __shfl_xor_sync(0xffffffffu, rs1, 1);
        rs1 += __shfl_xor_sync(0xffffffffu, rs1, 2);
        l0 = l0 * cr0 + rs0;
        l1 = l1 * cr1 + rs1;
#pragma unroll
        for (int j = 0; j < 16; ++j) {
            accO[j][0] *= cr0; accO[j][1] *= cr0;
            accO[j][2] *= cr1; accO[j][3] *= cr1;
        }

        // ---- O += P V ----
#pragma unroll
        for (int ks = 0; ks < 4; ++ks) {
            uint32_t Aph[4] = {phr[2 * ks], phr8[2 * ks], phr[2 * ks + 1], phr8[2 * ks + 1]};
            uint32_t Apl[4] = {plr[2 * ks], plr8[2 * ks], plr[2 * ks + 1], plr8[2 * ks + 1]};
            const int rowv = ks * 16 + (lane & 15);
#pragma unroll
            for (int j = 0; j < 8; ++j) {
                int cv = 2 * j + (lane >> 4), p = cv >> 3, c8 = cv & 7;
                uint32_t off = (uint32_t)p * 8192 + rowv * 128 + ((c8 ^ (rowv & 7)) << 4);
                uint32_t vh[4], vl[4];
                ldsm_x4_t(vh, sVh + off);
                ldsm_x4_t(vl, sVl + off);
                mma_bf16(accO[2 * j],     Aph, vh);
                mma_bf16(accO[2 * j + 1], Aph, vh + 2);
                mma_bf16(accO[2 * j],     Aph, vl);
                mma_bf16(accO[2 * j + 1], Aph, vl + 2);
                mma_bf16(accO[2 * j],     Apl, vh);
                mma_bf16(accO[2 * j + 1], Apl, vh + 2);
            }
        }

        __syncthreads();
        if (t + 2 < nt) { copy_kv(t + 2); cp_commit(); }
    }

    // ---- normalize + write attn hi/lo ----
    const float i0 = 1.f / l0, i1 = 1.f / l1;
    const size_t obase = (size_t)b * SEQ * N_EMBD + (size_t)h * 128;
    const int row0 = q0 + qr + (lane >> 2);
#pragma unroll
    for (int j = 0; j < 16; ++j) {
        int d = j * 8 + (lane & 3) * 2;
        size_t o0 = obase + (size_t)row0 * N_EMBD + d;
        size_t o1 = obase + (size_t)(row0 + 8) * N_EMBD + d;
        float v0 = accO[j][0] * i0, v1 = accO[j][1] * i0;
        float v2 = accO[j][2] * i1, v3 = accO[j][3] * i1;
        __nv_bfloat16 h0 = __float2bfloat16_rn(v0), h1 = __float2bfloat16_rn(v1);
        __nv_bfloat16 h2 = __float2bfloat16_rn(v2), h3 = __float2bfloat16_rn(v3);
        *(uint32_t*)(outh + o0) = packbf(h0, h1);
        *(uint32_t*)(outh + o1) = packbf(h2, h3);
        *(uint32_t*)(outl + o0) = packbf(__float2bfloat16_rn(v0 - __bfloat162float(h0)),
                                         __float2bfloat16_rn(v1 - __bfloat162float(h1)));
        *(uint32_t*)(outl + o1) = packbf(__float2bfloat16_rn(v2 - __bfloat162float(h2)),
                                         __float2bfloat16_rn(v3 - __bfloat162float(h3)));
    }
}

// ---------------- converts ----------------------------------------------------
__global__ __launch_bounds__(256) void convert_split(
    const float* __restrict__ in, __nv_bfloat16* __restrict__ oh,
    __nv_bfloat16* __restrict__ ol, int n)
{
    for (int i = blockIdx.x * 256 + threadIdx.x; i < n; i += gridDim.x * 256) {
        float v = in[i];
        __nv_bfloat16 h = __float2bfloat16_rn(v);
        oh[i] = h;
        ol[i] = __float2bfloat16_rn(v - __bfloat162float(h));
    }
}
__global__ __launch_bounds__(256) void transpose_split(
    const float* __restrict__ in, __nv_bfloat16* __restrict__ oh,
    __nv_bfloat16* __restrict__ ol, int ld_in, int ld_out)
{
    __shared__ float t[32][33];
    const int c0 = blockIdx.x * 32, r0 = blockIdx.y * 32;
    const int tx = threadIdx.x, ty = threadIdx.y;
#pragma unroll
    for (int j = 0; j < 32; j += 8)
        t[ty + j][tx] = in[(size_t)(r0 + ty + j) * ld_in + c0 + tx];
    __syncthreads();
#pragma unroll
    for (int j = 0; j < 32; j += 8) {
        float v = t[tx][ty + j];
        __nv_bfloat16 h = __float2bfloat16_rn(v);
        size_t o = (size_t)(c0 + ty + j) * ld_out + r0 + tx;
        oh[o] = h;
        ol[o] = __float2bfloat16_rn(v - __bfloat162float(h));
    }
}

// ---------------- launch ------------------------------------------------------
extern "C" void kernel_launch(void* const* d_in, const int* in_sizes, int n_in,
                              void* d_out, int out_size)
{
    const float* x     = (const float*)d_in[0];
    const float* Wqkv  = (const float*)d_in[1];
    const float* bqkv  = (const float*)d_in[2];
    const float* Wproj = (const float*)d_in[3];
    const float* bproj = (const float*)d_in[4];
    float* out = (float*)d_out;

    __nv_bfloat16 *x_h, *x_l, *wq_h, *wq_l, *wp_h, *wp_l;
    __nv_bfloat16 *qkv_h, *qkv_l, *at_h, *at_l;
    cudaGetSymbolAddress((void**)&x_h, g_x_h);
    cudaGetSymbolAddress((void**)&x_l, g_x_l);
    cudaGetSymbolAddress((void**)&wq_h, g_wqkvT_h);
    cudaGetSymbolAddress((void**)&wq_l, g_wqkvT_l);
    cudaGetSymbolAddress((void**)&wp_h, g_wprojT_h);
    cudaGetSymbolAddress((void**)&wp_l, g_wprojT_l);
    cudaGetSymbolAddress((void**)&qkv_h, g_qkv_h);
    cudaGetSymbolAddress((void**)&qkv_l, g_qkv_l);
    cudaGetSymbolAddress((void**)&at_h, g_attn_h);
    cudaGetSymbolAddress((void**)&at_l, g_attn_l);

    const int GEMM_SMEM = 65536;
    const int FLASH_SMEM = 196608;
    cudaFuncSetAttribute(gemm_bf16x3<true, false, true>,
                         cudaFuncAttributeMaxDynamicSharedMemorySize, GEMM_SMEM);
    cudaFuncSetAttribute(gemm_bf16x3<true, true, false>,
                         cudaFuncAttributeMaxDynamicSharedMemorySize, GEMM_SMEM);
    cudaFuncSetAttribute(flash_attn,
                         cudaFuncAttributeMaxDynamicSharedMemorySize, FLASH_SMEM);

    const int M = BATCH * SEQ, E = N_EMBD, E3 = 3 * N_EMBD;

    // 0) input/weight conversion
    convert_split<<<4096, 256>>>(x, x_h, x_l, M * E);
    transpose_split<<<dim3(E3 / 32, E / 32), dim3(32, 8)>>>(Wqkv, wq_h, wq_l, E3, E);
    transpose_split<<<dim3(E / 32, E / 32), dim3(32, 8)>>>(Wproj, wp_h, wp_l, E, E);

    // 1) qkv = x @ Wqkv + b  -> hi/lo bf16
    gemm_bf16x3<true, false, true><<<dim3(E3 / BN, M / BM), 256, GEMM_SMEM>>>(
        x_h, x_l, wq_h, wq_l, bqkv, nullptr, qkv_h, qkv_l, E, E, E, E3, 1.f);

    // 2-4) fused flash attention -> attn hi/lo
    flash_attn<<<dim3(SEQ / 128, BATCH * N_HEAD), 256, FLASH_SMEM>>>(
        qkv_h, qkv_l, at_h, at_l);

    // 5) out = attn @ Wproj + b
    gemm_bf16x3<true, true, false><<<dim3(E / BN, M / BM), 256, GEMM_SMEM>>>(
        at_h, at_l, wp_h, wp_l, bproj, out, nullptr, nullptr, E, E, E, E, 1.f);
}

// round 6
// speedup vs baseline: 3.9585x; 1.0057x over previous
#include <cuda_runtime.h>
#include <cuda_bf16.h>
#include <cstdint>

#define N_EMBD 2048
#define N_HEAD 16
#define HEAD_DIM 128
#define BATCH 2
#define SEQ 2048

#define BM 128
#define BN 128

// ---------------- scratch ----------------------------------------------------
__device__ __nv_bfloat16 g_x_h[(size_t)BATCH * SEQ * N_EMBD];
__device__ __nv_bfloat16 g_x_l[(size_t)BATCH * SEQ * N_EMBD];
__device__ __nv_bfloat16 g_wqkvT_h[(size_t)3 * N_EMBD * N_EMBD];
__device__ __nv_bfloat16 g_wqkvT_l[(size_t)3 * N_EMBD * N_EMBD];
__device__ __nv_bfloat16 g_wprojT_h[(size_t)N_EMBD * N_EMBD];
__device__ __nv_bfloat16 g_wprojT_l[(size_t)N_EMBD * N_EMBD];
__device__ __nv_bfloat16 g_qkv_h[(size_t)BATCH * SEQ * 3 * N_EMBD];
__device__ __nv_bfloat16 g_qkv_l[(size_t)BATCH * SEQ * 3 * N_EMBD];
__device__ __nv_bfloat16 g_attn_h[(size_t)BATCH * SEQ * N_EMBD];
__device__ __nv_bfloat16 g_attn_l[(size_t)BATCH * SEQ * N_EMBD];

// ---------------- PTX helpers -------------------------------------------------
__device__ __forceinline__ uint32_t smem_u32(const void* p) {
    return (uint32_t)__cvta_generic_to_shared(p);
}
__device__ __forceinline__ void ldsm_x4(uint32_t* r, uint32_t addr) {
    asm volatile("ldmatrix.sync.aligned.m8n8.x4.shared.b16 {%0,%1,%2,%3}, [%4];"
                 : "=r"(r[0]), "=r"(r[1]), "=r"(r[2]), "=r"(r[3]) : "r"(addr));
}
__device__ __forceinline__ void ldsm_x4_t(uint32_t* r, uint32_t addr) {
    asm volatile("ldmatrix.sync.aligned.m8n8.x4.trans.shared.b16 {%0,%1,%2,%3}, [%4];"
                 : "=r"(r[0]), "=r"(r[1]), "=r"(r[2]), "=r"(r[3]) : "r"(addr));
}
__device__ __forceinline__ void mma_bf16(float* d, const uint32_t* a, const uint32_t* b) {
    asm volatile(
        "mma.sync.aligned.m16n8k16.row.col.f32.bf16.bf16.f32 "
        "{%0,%1,%2,%3},{%4,%5,%6,%7},{%8,%9},{%0,%1,%2,%3};"
        : "+f"(d[0]), "+f"(d[1]), "+f"(d[2]), "+f"(d[3])
        : "r"(a[0]), "r"(a[1]), "r"(a[2]), "r"(a[3]), "r"(b[0]), "r"(b[1]));
}
__device__ __forceinline__ void cp16(uint32_t dst, const void* src) {
    asm volatile("cp.async.cg.shared.global [%0], [%1], 16;" :: "r"(dst), "l"(src));
}
__device__ __forceinline__ void cp_commit() {
    asm volatile("cp.async.commit_group;" ::: "memory");
}
template <int W> __device__ __forceinline__ void cp_wait() {
    asm volatile("cp.async.wait_group %0;" :: "n"(W) : "memory");
}
__device__ __forceinline__ uint32_t packbf(__nv_bfloat16 a, __nv_bfloat16 b) {
    __nv_bfloat162 t; t.x = a; t.y = b;
    uint32_t u; *(__nv_bfloat162*)&u = t; return u;
}

// ---------------- split-bf16 GEMM: term-major MMA, 3-stage, 1 sync/tile -------
template <bool BIAS, bool WF32, bool WSPLIT>
__global__ __launch_bounds__(256) void gemm_bf16x3(
    const __nv_bfloat16* __restrict__ Ah, const __nv_bfloat16* __restrict__ Al,
    const __nv_bfloat16* __restrict__ Bh, const __nv_bfloat16* __restrict__ Bl,
    const float* __restrict__ bias,
    float* __restrict__ C, __nv_bfloat16* __restrict__ Ch, __nv_bfloat16* __restrict__ Cl,
    int K, int lda, int ldb, int ldc, float scale)
{
    extern __shared__ char smem[];
    const int tid = threadIdx.x;
    const int m0 = blockIdx.y * BM, n0 = blockIdx.x * BN;
    const int ntiles = K >> 5;

    const int crow = tid >> 3;
    const int cc   = tid & 7;
    const __nv_bfloat16* aptr = (cc < 4) ? Ah : Al;
    const __nv_bfloat16* bptr = (cc < 4) ? Bh : Bl;
    const int kchunk = (cc & 3) << 3;

    auto copy_tile = [&](int kt, int buf) {
        const int k0 = kt << 5;
        uint32_t abase = smem_u32(smem) + buf * 32768;
        uint32_t bbase = abase + 16384;
#pragma unroll
        for (int i = 0; i < 4; ++i) {
            int m = crow + (i << 5);
            cp16(abase + m * 128 + ((cc ^ (m & 7)) << 4),
                 aptr + (size_t)(m0 + m) * lda + k0 + kchunk);
        }
#pragma unroll
        for (int i = 0; i < 4; ++i) {
            int n = crow + (i << 5);
            cp16(bbase + n * 128 + ((cc ^ (n & 7)) << 4),
                 bptr + (size_t)(n0 + n) * ldb + k0 + kchunk);
        }
    };

    const int warp = tid >> 5, lane = tid & 31;
    const int wm = warp >> 1, wn = warp & 1;
    const int rselA = (lane & 7) + (((lane >> 3) & 1) << 3);
    const int chA   = (lane >> 4) & 1;
    const int rselB = (lane & 7) + (((lane >> 4) & 1) << 3);
    const int chB   = (lane >> 3) & 1;

    float acc[2][8][4];
#pragma unroll
    for (int a = 0; a < 2; ++a)
#pragma unroll
        for (int b = 0; b < 8; ++b)
#pragma unroll
            for (int c = 0; c < 4; ++c) acc[a][b][c] = 0.f;

    auto compute_tile = [&](int buf) {
        uint32_t abase = smem_u32(smem) + buf * 32768;
        uint32_t bbase = abase + 16384;
#pragma unroll
        for (int ks = 0; ks < 2; ++ks) {
            uint32_t aH[2][4], aL[2][4];
#pragma unroll
            for (int mf = 0; mf < 2; ++mf) {
                int row = wm * 32 + mf * 16 + rselA;
                int chh = 2 * ks + chA;
                ldsm_x4(aH[mf], abase + row * 128 + ((chh ^ (row & 7)) << 4));
                ldsm_x4(aL[mf], abase + row * 128 + (((chh + 4) ^ (row & 7)) << 4));
            }
            uint32_t bh[4][4], bl[4][4];
#pragma unroll
            for (int np = 0; np < 4; ++np) {
                int rowb = wn * 64 + np * 16 + rselB;
                int chh = 2 * ks + chB;
                ldsm_x4(bh[np], bbase + rowb * 128 + ((chh ^ (rowb & 7)) << 4));
                ldsm_x4(bl[np], bbase + rowb * 128 + (((chh + 4) ^ (rowb & 7)) << 4));
            }
            // term-major x np-major: same accumulator revisited every 16 MMAs
#pragma unroll
            for (int np = 0; np < 4; ++np)
#pragma unroll
                for (int mf = 0; mf < 2; ++mf) {
                    mma_bf16(acc[mf][2 * np],     aH[mf], bh[np]);
                    mma_bf16(acc[mf][2 * np + 1], aH[mf], bh[np] + 2);
                }
#pragma unroll
            for (int np = 0; np < 4; ++np)
#pragma unroll
                for (int mf = 0; mf < 2; ++mf) {
                    mma_bf16(acc[mf][2 * np],     aH[mf], bl[np]);
                    mma_bf16(acc[mf][2 * np + 1], aH[mf], bl[np] + 2);
                }
#pragma unroll
            for (int np = 0; np < 4; ++np)
#pragma unroll
                for (int mf = 0; mf < 2; ++mf) {
                    mma_bf16(acc[mf][2 * np],     aL[mf], bh[np]);
                    mma_bf16(acc[mf][2 * np + 1], aL[mf], bh[np] + 2);
                }
        }
    };

    // 3-stage ring, one barrier per k-tile
    copy_tile(0, 0); cp_commit();
    if (ntiles > 1) { copy_tile(1, 1); cp_commit(); }
    for (int kt = 0; kt < ntiles; ++kt) {
        if (kt + 1 < ntiles) cp_wait<1>(); else cp_wait<0>();
        __syncthreads();
        if (kt + 2 < ntiles) {
            copy_tile(kt + 2, (kt + 2) % 3);
            cp_commit();
        }
        compute_tile(kt % 3);
    }

#pragma unroll
    for (int mf = 0; mf < 2; ++mf) {
        int row = m0 + wm * 32 + mf * 16 + (lane >> 2);
#pragma unroll
        for (int nf = 0; nf < 8; ++nf) {
            int col = n0 + wn * 64 + nf * 8 + (lane & 3) * 2;
            float v0 = acc[mf][nf][0] * scale, v1 = acc[mf][nf][1] * scale;
            float v2 = acc[mf][nf][2] * scale, v3 = acc[mf][nf][3] * scale;
            if (BIAS) {
                float b0 = bias[col], b1 = bias[col + 1];
                v0 += b0; v1 += b1; v2 += b0; v3 += b1;
            }
            size_t o0 = (size_t)row * ldc + col;
            size_t o1 = (size_t)(row + 8) * ldc + col;
            if (WF32) {
                *(float2*)(C + o0) = make_float2(v0, v1);
                *(float2*)(C + o1) = make_float2(v2, v3);
            }
            if (WSPLIT) {
                __nv_bfloat16 h0 = __float2bfloat16_rn(v0);
                __nv_bfloat16 h1 = __float2bfloat16_rn(v1);
                __nv_bfloat16 h2 = __float2bfloat16_rn(v2);
                __nv_bfloat16 h3 = __float2bfloat16_rn(v3);
                *(uint32_t*)(Ch + o0) = packbf(h0, h1);
                *(uint32_t*)(Ch + o1) = packbf(h2, h3);
                *(uint32_t*)(Cl + o0) = packbf(
                    __float2bfloat16_rn(v0 - __bfloat162float(h0)),
                    __float2bfloat16_rn(v1 - __bfloat162float(h1)));
                *(uint32_t*)(Cl + o1) = packbf(
                    __float2bfloat16_rn(v2 - __bfloat162float(h2)),
                    __float2bfloat16_rn(v3 - __bfloat162float(h3)));
            }
        }
    }
}

// ---------------- fused flash attention ---------------------------------------
__global__ __launch_bounds__(256) void flash_attn(
    const __nv_bfloat16* __restrict__ qkvh, const __nv_bfloat16* __restrict__ qkvl,
    __nv_bfloat16* __restrict__ outh, __nv_bfloat16* __restrict__ outl)
{
    const int qi = 15 - (int)blockIdx.x;
    const int bh = blockIdx.y;
    const int b = bh >> 4, h = bh & 15;
    const int q0 = qi * 128;
    const size_t base = (size_t)b * SEQ * 6144 + (size_t)h * 128;
    const __nv_bfloat16* Qp[2] = {qkvh + base, qkvl + base};
    const __nv_bfloat16* KVsrc[4] = {qkvh + base + 2048, qkvl + base + 2048,
                                     qkvh + base + 4096, qkvl + base + 4096};

    extern __shared__ char smem[];
    const uint32_t S0 = smem_u32(smem);
    const int tid = threadIdx.x, lane = tid & 31, warp = tid >> 5;

#pragma unroll
    for (int half = 0; half < 2; ++half) {
        const __nv_bfloat16* src = Qp[half];
        const uint32_t qb = S0 + half * 32768;
#pragma unroll
        for (int i = 0; i < 8; ++i) {
            int idx = tid + i * 256;
            int row = idx >> 4, c = idx & 15, p = c >> 3, c8 = c & 7;
            cp16(qb + p * 16384 + row * 128 + ((c8 ^ (row & 7)) << 4),
                 src + (size_t)(q0 + row) * 6144 + p * 64 + c8 * 8);
        }
    }

    auto copy_kv = [&](int t) {
        const uint32_t sb = S0 + 65536 + (uint32_t)(t & 1) * 65536;
        const int kv0 = t * 64;
#pragma unroll
        for (int q = 0; q < 4; ++q) {
#pragma unroll
            for (int i = 0; i < 4; ++i) {
                int idx = tid + i * 256;
                int row = idx >> 4, c = idx & 15, p = c >> 3, c8 = c & 7;
                cp16(sb + q * 16384 + p * 8192 + row * 128 + ((c8 ^ (row & 7)) << 4),
                     KVsrc[q] + (size_t)(kv0 + row) * 6144 + p * 64 + c8 * 8);
            }
        }
    };

    const int rselA = (lane & 7) + (((lane >> 3) & 1) << 3);
    const int chA   = (lane >> 4) & 1;
    const int rselB = (lane & 7) + (((lane >> 4) & 1) << 3);
    const int chB   = (lane >> 3) & 1;
    const int qr = warp * 16;

    float m0 = -1e30f, m1 = -1e30f, l0 = 0.f, l1 = 0.f;
    float accO[16][4];
#pragma unroll
    for (int j = 0; j < 16; ++j)
#pragma unroll
        for (int c = 0; c < 4; ++c) accO[j][c] = 0.f;

    const int nt = 2 * qi + 2;
    copy_kv(0); cp_commit();
    if (nt > 1) { copy_kv(1); cp_commit(); }

    for (int t = 0; t < nt; ++t) {
        if (t + 1 < nt) cp_wait<1>(); else cp_wait<0>();
        __syncthreads();

        const uint32_t sb  = S0 + 65536 + (uint32_t)(t & 1) * 65536;
        const uint32_t sKh = sb, sKl = sb + 16384, sVh = sb + 32768, sVl = sb + 49152;

        float accS[8][4];
#pragma unroll
        for (int j = 0; j < 8; ++j)
#pragma unroll
            for (int c = 0; c < 4; ++c) accS[j][c] = 0.f;

#pragma unroll
        for (int ks = 0; ks < 8; ++ks) {
            uint32_t aH[4], aL[4];
            {
                int row = qr + rselA;
                int g = ks * 2 + chA, p = g >> 3, c8 = g & 7;
                uint32_t off = (uint32_t)p * 16384 + row * 128 + ((c8 ^ (row & 7)) << 4);
                ldsm_x4(aH, S0 + off);
                ldsm_x4(aL, S0 + 32768 + off);
            }
            uint32_t bH[4][4], bL[4][4];
#pragma unroll
            for (int n2 = 0; n2 < 4; ++n2) {
                int row = n2 * 16 + rselB;
                int g = ks * 2 + chB, p = g >> 3, c8 = g & 7;
                uint32_t off = (uint32_t)p * 8192 + row * 128 + ((c8 ^ (row & 7)) << 4);
                ldsm_x4(bH[n2], sKh + off);
                ldsm_x4(bL[n2], sKl + off);
            }
#pragma unroll
            for (int n2 = 0; n2 < 4; ++n2) {
                mma_bf16(accS[2 * n2],     aH, bH[n2]);
                mma_bf16(accS[2 * n2 + 1], aH, bH[n2] + 2);
            }
#pragma unroll
            for (int n2 = 0; n2 < 4; ++n2) {
                mma_bf16(accS[2 * n2],     aH, bL[n2]);
                mma_bf16(accS[2 * n2 + 1], aH, bL[n2] + 2);
            }
#pragma unroll
            for (int n2 = 0; n2 < 4; ++n2) {
                mma_bf16(accS[2 * n2],     aL, bH[n2]);
                mma_bf16(accS[2 * n2 + 1], aL, bH[n2] + 2);
            }
        }

        const float isd = 0.08838834764831845f;
        const int kv0 = t * 64;
        const int grow0 = q0 + qr + (lane >> 2);
        const int grow1 = grow0 + 8;
        const bool masked = (t >= 2 * qi);
#pragma unroll
        for (int nf = 0; nf < 8; ++nf) {
#pragma unroll
            for (int c = 0; c < 4; ++c) accS[nf][c] *= isd;
            if (masked) {
                int col = kv0 + nf * 8 + (lane & 3) * 2;
                if (col     > grow0) accS[nf][0] = -1e30f;
                if (col + 1 > grow0) accS[nf][1] = -1e30f;
                if (col     > grow1) accS[nf][2] = -1e30f;
                if (col + 1 > grow1) accS[nf][3] = -1e30f;
            }
        }
        float mx0 = -1e30f, mx1 = -1e30f;
#pragma unroll
        for (int nf = 0; nf < 8; ++nf) {
            mx0 = fmaxf(mx0, fmaxf(accS[nf][0], accS[nf][1]));
            mx1 = fmaxf(mx1, fmaxf(accS[nf][2], accS[nf][3]));
        }
        mx0 = fmaxf(mx0, __shfl_xor_sync(0xffffffffu, mx0, 1));
        mx0 = fmaxf(mx0, __shfl_xor_sync(0xffffffffu, mx0, 2));
        mx1 = fmaxf(mx1, __shfl_xor_sync(0xffffffffu, mx1, 1));
        mx1 = fmaxf(mx1, __shfl_xor_sync(0xffffffffu, mx1, 2));
        const float nm0 = fmaxf(m0, mx0), nm1 = fmaxf(m1, mx1);
        const float cr0 = __expf(m0 - nm0), cr1 = __expf(m1 - nm1);
        m0 = nm0; m1 = nm1;

        float rs0 = 0.f, rs1 = 0.f;
        uint32_t phr[8], phr8[8], plr[8], plr8[8];
#pragma unroll
        for (int nf = 0; nf < 8; ++nf) {
            float p0 = __expf(accS[nf][0] - nm0), p1 = __expf(accS[nf][1] - nm0);
            float p2 = __expf(accS[nf][2] - nm1), p3 = __expf(accS[nf][3] - nm1);
            rs0 += p0 + p1; rs1 += p2 + p3;
            __nv_bfloat16 h0 = __float2bfloat16_rn(p0), h1 = __float2bfloat16_rn(p1);
            __nv_bfloat16 h2 = __float2bfloat16_rn(p2), h3 = __float2bfloat16_rn(p3);
            phr[nf]  = packbf(h0, h1);
            phr8[nf] = packbf(h2, h3);
            plr[nf]  = packbf(__float2bfloat16_rn(p0 - __bfloat162float(h0)),
                              __float2bfloat16_rn(p1 - __bfloat162float(h1)));
            plr8[nf] = packbf(__float2bfloat16_rn(p2 - __bfloat162float(h2)),
                              __float2bfloat16_rn(p3 - __bfloat162float(h3)));
        }
        rs0 += __shfl_xor_sync(0xffffffffu, rs0, 1);
        rs0 += __shfl_xor_sync(0xffffffffu, rs0, 2);
        rs1 += __shfl_xor_sync(0xffffffffu, rs1, 1);
        rs1 += __shfl_xor_sync(0xffffffffu, rs1, 2);
        l0 = l0 * cr0 + rs0;
        l1 = l1 * cr1 + rs1;
#pragma unroll
        for (int j = 0; j < 16; ++j) {
            accO[j][0] *= cr0; accO[j][1] *= cr0;
            accO[j][2] *= cr1; accO[j][3] *= cr1;
        }

        // O += P V   (j-pairs chunked: same-acc distance 4)
#pragma unroll
        for (int ks = 0; ks < 4; ++ks) {
            uint32_t Aph[4] = {phr[2 * ks], phr8[2 * ks], phr[2 * ks + 1], phr8[2 * ks + 1]};
            uint32_t Apl[4] = {plr[2 * ks], plr8[2 * ks], plr[2 * ks + 1], plr8[2 * ks + 1]};
            const int rowv = ks * 16 + (lane & 15);
#pragma unroll
            for (int jj = 0; jj < 4; ++jj) {
                uint32_t vh0[4], vl0[4], vh1[4], vl1[4];
                {
                    int cv = 4 * jj + (lane >> 4), p = cv >> 3, c8 = cv & 7;
                    uint32_t off = (uint32_t)p * 8192 + rowv * 128 + ((c8 ^ (rowv & 7)) << 4);
                    ldsm_x4_t(vh0, sVh + off);
                    ldsm_x4_t(vl0, sVl + off);
                }
                {
                    int cv = 4 * jj + 2 + (lane >> 4), p = cv >> 3, c8 = cv & 7;
                    uint32_t off = (uint32_t)p * 8192 + rowv * 128 + ((c8 ^ (rowv & 7)) << 4);
                    ldsm_x4_t(vh1, sVh + off);
                    ldsm_x4_t(vl1, sVl + off);
                }
                float* a0 = accO[4 * jj];
                float* a1 = accO[4 * jj + 1];
                float* a2 = accO[4 * jj + 2];
                float* a3 = accO[4 * jj + 3];
                mma_bf16(a0, Aph, vh0); mma_bf16(a1, Aph, vh0 + 2);
                mma_bf16(a2, Aph, vh1); mma_bf16(a3, Aph, vh1 + 2);
                mma_bf16(a0, Aph, vl0); mma_bf16(a1, Aph, vl0 + 2);
                mma_bf16(a2, Aph, vl1); mma_bf16(a3, Aph, vl1 + 2);
                mma_bf16(a0, Apl, vh0); mma_bf16(a1, Apl, vh0 + 2);
                mma_bf16(a2, Apl, vh1); mma_bf16(a3, Apl, vh1 + 2);
            }
        }

        __syncthreads();
        if (t + 2 < nt) { copy_kv(t + 2); cp_commit(); }
    }

    const float i0 = 1.f / l0, i1 = 1.f / l1;
    const size_t obase = (size_t)b * SEQ * N_EMBD + (size_t)h * 128;
    const int row0 = q0 + qr + (lane >> 2);
#pragma unroll
    for (int j = 0; j < 16; ++j) {
        int d = j * 8 + (lane & 3) * 2;
        size_t o0 = obase + (size_t)row0 * N_EMBD + d;
        size_t o1 = obase + (size_t)(row0 + 8) * N_EMBD + d;
        float v0 = accO[j][0] * i0, v1 = accO[j][1] * i0;
        float v2 = accO[j][2] * i1, v3 = accO[j][3] * i1;
        __nv_bfloat16 h0 = __float2bfloat16_rn(v0), h1 = __float2bfloat16_rn(v1);
        __nv_bfloat16 h2 = __float2bfloat16_rn(v2), h3 = __float2bfloat16_rn(v3);
        *(uint32_t*)(outh + o0) = packbf(h0, h1);
        *(uint32_t*)(outh + o1) = packbf(h2, h3);
        *(uint32_t*)(outl + o0) = packbf(__float2bfloat16_rn(v0 - __bfloat162float(h0)),
                                         __float2bfloat16_rn(v1 - __bfloat162float(h1)));
        *(uint32_t*)(outl + o1) = packbf(__float2bfloat16_rn(v2 - __bfloat162float(h2)),
                                         __float2bfloat16_rn(v3 - __bfloat162float(h3)));
    }
}

// ---------------- converts ----------------------------------------------------
__global__ __launch_bounds__(256) void convert_split(
    const float* __restrict__ in, __nv_bfloat16* __restrict__ oh,
    __nv_bfloat16* __restrict__ ol, int n)
{
    for (int i = blockIdx.x * 256 + threadIdx.x; i < n; i += gridDim.x * 256) {
        float v = in[i];
        __nv_bfloat16 h = __float2bfloat16_rn(v);
        oh[i] = h;
        ol[i] = __float2bfloat16_rn(v - __bfloat162float(h));
    }
}
__global__ __launch_bounds__(256) void transpose_split(
    const float* __restrict__ in, __nv_bfloat16* __restrict__ oh,
    __nv_bfloat16* __restrict__ ol, int ld_in, int ld_out)
{
    __shared__ float t[32][33];
    const int c0 = blockIdx.x * 32, r0 = blockIdx.y * 32;
    const int tx = threadIdx.x, ty = threadIdx.y;
#pragma unroll
    for (int j = 0; j < 32; j += 8)
        t[ty + j][tx] = in[(size_t)(r0 + ty + j) * ld_in + c0 + tx];
    __syncthreads();
#pragma unroll
    for (int j = 0; j < 32; j += 8) {
        float v = t[tx][ty + j];
        __nv_bfloat16 h = __float2bfloat16_rn(v);
        size_t o = (size_t)(c0 + ty + j) * ld_out + r0 + tx;
        oh[o] = h;
        ol[o] = __float2bfloat16_rn(v - __bfloat162float(h));
    }
}

// ---------------- launch ------------------------------------------------------
extern "C" void kernel_launch(void* const* d_in, const int* in_sizes, int n_in,
                              void* d_out, int out_size)
{
    const float* x     = (const float*)d_in[0];
    const float* Wqkv  = (const float*)d_in[1];
    const float* bqkv  = (const float*)d_in[2];
    const float* Wproj = (const float*)d_in[3];
    const float* bproj = (const float*)d_in[4];
    float* out = (float*)d_out;

    __nv_bfloat16 *x_h, *x_l, *wq_h, *wq_l, *wp_h, *wp_l;
    __nv_bfloat16 *qkv_h, *qkv_l, *at_h, *at_l;
    cudaGetSymbolAddress((void**)&x_h, g_x_h);
    cudaGetSymbolAddress((void**)&x_l, g_x_l);
    cudaGetSymbolAddress((void**)&wq_h, g_wqkvT_h);
    cudaGetSymbolAddress((void**)&wq_l, g_wqkvT_l);
    cudaGetSymbolAddress((void**)&wp_h, g_wprojT_h);
    cudaGetSymbolAddress((void**)&wp_l, g_wprojT_l);
    cudaGetSymbolAddress((void**)&qkv_h, g_qkv_h);
    cudaGetSymbolAddress((void**)&qkv_l, g_qkv_l);
    cudaGetSymbolAddress((void**)&at_h, g_attn_h);
    cudaGetSymbolAddress((void**)&at_l, g_attn_l);

    const int GEMM_SMEM = 98304;     // 3 stages x 32KB
    const int FLASH_SMEM = 196608;
    cudaFuncSetAttribute(gemm_bf16x3<true, false, true>,
                         cudaFuncAttributeMaxDynamicSharedMemorySize, GEMM_SMEM);
    cudaFuncSetAttribute(gemm_bf16x3<true, true, false>,
                         cudaFuncAttributeMaxDynamicSharedMemorySize, GEMM_SMEM);
    cudaFuncSetAttribute(flash_attn,
                         cudaFuncAttributeMaxDynamicSharedMemorySize, FLASH_SMEM);

    const int M = BATCH * SEQ, E = N_EMBD, E3 = 3 * N_EMBD;

    convert_split<<<4096, 256>>>(x, x_h, x_l, M * E);
    transpose_split<<<dim3(E3 / 32, E / 32), dim3(32, 8)>>>(Wqkv, wq_h, wq_l, E3, E);
    transpose_split<<<dim3(E / 32, E / 32), dim3(32, 8)>>>(Wproj, wp_h, wp_l, E, E);

    gemm_bf16x3<true, false, true><<<dim3(E3 / BN, M / BM), 256, GEMM_SMEM>>>(
        x_h, x_l, wq_h, wq_l, bqkv, nullptr, qkv_h, qkv_l, E, E, E, E3, 1.f);

    flash_attn<<<dim3(SEQ / 128, BATCH * N_HEAD), 256, FLASH_SMEM>>>(
        qkv_h, qkv_l, at_h, at_l);

    gemm_bf16x3<true, true, false><<<dim3(E / BN, M / BM), 256, GEMM_SMEM>>>(
        at_h, at_l, wp_h, wp_l, bproj, out, nullptr, nullptr, E, E, E, E, 1.f);
}

// round 7
// speedup vs baseline: 4.3391x; 1.0961x over previous
#include <cuda_runtime.h>
#include <cuda_bf16.h>
#include <cstdint>

#define N_EMBD 2048
#define N_HEAD 16
#define HEAD_DIM 128
#define BATCH 2
#define SEQ 2048

#define BM 128
#define BN 128

// ---------------- scratch ----------------------------------------------------
__device__ __nv_bfloat16 g_x_h[(size_t)BATCH * SEQ * N_EMBD];
__device__ __nv_bfloat16 g_x_l[(size_t)BATCH * SEQ * N_EMBD];
__device__ __nv_bfloat16 g_wqkvT_h[(size_t)3 * N_EMBD * N_EMBD];
__device__ __nv_bfloat16 g_wqkvT_l[(size_t)3 * N_EMBD * N_EMBD];
__device__ __nv_bfloat16 g_wprojT_h[(size_t)N_EMBD * N_EMBD];
__device__ __nv_bfloat16 g_wprojT_l[(size_t)N_EMBD * N_EMBD];
__device__ __nv_bfloat16 g_qkv_h[(size_t)BATCH * SEQ * 3 * N_EMBD];
__device__ __nv_bfloat16 g_qkv_l[(size_t)BATCH * SEQ * 3 * N_EMBD];
__device__ __nv_bfloat16 g_attn_h[(size_t)BATCH * SEQ * N_EMBD];
__device__ __nv_bfloat16 g_attn_l[(size_t)BATCH * SEQ * N_EMBD];

// ---------------- PTX helpers -------------------------------------------------
__device__ __forceinline__ uint32_t smem_u32(const void* p) {
    return (uint32_t)__cvta_generic_to_shared(p);
}
__device__ __forceinline__ void ldsm_x4(uint32_t* r, uint32_t addr) {
    asm volatile("ldmatrix.sync.aligned.m8n8.x4.shared.b16 {%0,%1,%2,%3}, [%4];"
                 : "=r"(r[0]), "=r"(r[1]), "=r"(r[2]), "=r"(r[3]) : "r"(addr));
}
__device__ __forceinline__ void ldsm_x4_t(uint32_t* r, uint32_t addr) {
    asm volatile("ldmatrix.sync.aligned.m8n8.x4.trans.shared.b16 {%0,%1,%2,%3}, [%4];"
                 : "=r"(r[0]), "=r"(r[1]), "=r"(r[2]), "=r"(r[3]) : "r"(addr));
}
__device__ __forceinline__ void mma_bf16(float* d, const uint32_t* a, const uint32_t* b) {
    asm volatile(
        "mma.sync.aligned.m16n8k16.row.col.f32.bf16.bf16.f32 "
        "{%0,%1,%2,%3},{%4,%5,%6,%7},{%8,%9},{%0,%1,%2,%3};"
        : "+f"(d[0]), "+f"(d[1]), "+f"(d[2]), "+f"(d[3])
        : "r"(a[0]), "r"(a[1]), "r"(a[2]), "r"(a[3]), "r"(b[0]), "r"(b[1]));
}
__device__ __forceinline__ void cp16(uint32_t dst, const void* src) {
    asm volatile("cp.async.cg.shared.global [%0], [%1], 16;" :: "r"(dst), "l"(src));
}
__device__ __forceinline__ void cp_commit() {
    asm volatile("cp.async.commit_group;" ::: "memory");
}
template <int W> __device__ __forceinline__ void cp_wait() {
    asm volatile("cp.async.wait_group %0;" :: "n"(W) : "memory");
}
__device__ __forceinline__ uint32_t packbf(__nv_bfloat16 a, __nv_bfloat16 b) {
    __nv_bfloat162 t; t.x = a; t.y = b;
    uint32_t u; *(__nv_bfloat162*)&u = t; return u;
}

// ---------------- split-bf16 GEMM: 2 CTAs/SM, 3-stage, 1 sync/tile ------------
template <bool BIAS, bool WF32, bool WSPLIT>
__global__ __launch_bounds__(256, 2) void gemm_bf16x3(
    const __nv_bfloat16* __restrict__ Ah, const __nv_bfloat16* __restrict__ Al,
    const __nv_bfloat16* __restrict__ Bh, const __nv_bfloat16* __restrict__ Bl,
    const float* __restrict__ bias,
    float* __restrict__ C, __nv_bfloat16* __restrict__ Ch, __nv_bfloat16* __restrict__ Cl,
    int K, int lda, int ldb, int ldc, float scale)
{
    extern __shared__ char smem[];
    const int tid = threadIdx.x;
    const int m0 = blockIdx.y * BM, n0 = blockIdx.x * BN;
    const int ntiles = K >> 5;

    const int crow = tid >> 3;
    const int cc   = tid & 7;
    const __nv_bfloat16* aptr = (cc < 4) ? Ah : Al;
    const __nv_bfloat16* bptr = (cc < 4) ? Bh : Bl;
    const int kchunk = (cc & 3) << 3;

    auto copy_tile = [&](int kt, int buf) {
        const int k0 = kt << 5;
        uint32_t abase = smem_u32(smem) + buf * 32768;
        uint32_t bbase = abase + 16384;
#pragma unroll
        for (int i = 0; i < 4; ++i) {
            int m = crow + (i << 5);
            cp16(abase + m * 128 + ((cc ^ (m & 7)) << 4),
                 aptr + (size_t)(m0 + m) * lda + k0 + kchunk);
        }
#pragma unroll
        for (int i = 0; i < 4; ++i) {
            int n = crow + (i << 5);
            cp16(bbase + n * 128 + ((cc ^ (n & 7)) << 4),
                 bptr + (size_t)(n0 + n) * ldb + k0 + kchunk);
        }
    };

    const int warp = tid >> 5, lane = tid & 31;
    const int wm = warp >> 1, wn = warp & 1;
    const int rselA = (lane & 7) + (((lane >> 3) & 1) << 3);
    const int chA   = (lane >> 4) & 1;
    const int rselB = (lane & 7) + (((lane >> 4) & 1) << 3);
    const int chB   = (lane >> 3) & 1;

    float acc[2][8][4];
#pragma unroll
    for (int a = 0; a < 2; ++a)
#pragma unroll
        for (int b = 0; b < 8; ++b)
#pragma unroll
            for (int c = 0; c < 4; ++c) acc[a][b][c] = 0.f;

    auto compute_tile = [&](int buf) {
        uint32_t abase = smem_u32(smem) + buf * 32768;
        uint32_t bbase = abase + 16384;
#pragma unroll
        for (int ks = 0; ks < 2; ++ks) {
            uint32_t aH[2][4], aL[2][4];
#pragma unroll
            for (int mf = 0; mf < 2; ++mf) {
                int row = wm * 32 + mf * 16 + rselA;
                int chh = 2 * ks + chA;
                ldsm_x4(aH[mf], abase + row * 128 + ((chh ^ (row & 7)) << 4));
                ldsm_x4(aL[mf], abase + row * 128 + (((chh + 4) ^ (row & 7)) << 4));
            }
#pragma unroll
            for (int np = 0; np < 4; ++np) {
                uint32_t bh[4], bl[4];
                int rowb = wn * 64 + np * 16 + rselB;
                int chh = 2 * ks + chB;
                ldsm_x4(bh, bbase + rowb * 128 + ((chh ^ (rowb & 7)) << 4));
                ldsm_x4(bl, bbase + rowb * 128 + (((chh + 4) ^ (rowb & 7)) << 4));
#pragma unroll
                for (int mf = 0; mf < 2; ++mf) {
                    mma_bf16(acc[mf][2 * np],     aH[mf], bh);
                    mma_bf16(acc[mf][2 * np + 1], aH[mf], bh + 2);
                    mma_bf16(acc[mf][2 * np],     aH[mf], bl);
                    mma_bf16(acc[mf][2 * np + 1], aH[mf], bl + 2);
                    mma_bf16(acc[mf][2 * np],     aL[mf], bh);
                    mma_bf16(acc[mf][2 * np + 1], aL[mf], bh + 2);
                }
            }
        }
    };

    // 3-stage ring, one barrier per k-tile
    copy_tile(0, 0); cp_commit();
    if (ntiles > 1) { copy_tile(1, 1); cp_commit(); }
    for (int kt = 0; kt < ntiles; ++kt) {
        if (kt + 1 < ntiles) cp_wait<1>(); else cp_wait<0>();
        __syncthreads();
        if (kt + 2 < ntiles) {
            copy_tile(kt + 2, (kt + 2) % 3);
            cp_commit();
        }
        compute_tile(kt % 3);
    }

#pragma unroll
    for (int mf = 0; mf < 2; ++mf) {
        int row = m0 + wm * 32 + mf * 16 + (lane >> 2);
#pragma unroll
        for (int nf = 0; nf < 8; ++nf) {
            int col = n0 + wn * 64 + nf * 8 + (lane & 3) * 2;
            float v0 = acc[mf][nf][0] * scale, v1 = acc[mf][nf][1] * scale;
            float v2 = acc[mf][nf][2] * scale, v3 = acc[mf][nf][3] * scale;
            if (BIAS) {
                float b0 = bias[col], b1 = bias[col + 1];
                v0 += b0; v1 += b1; v2 += b0; v3 += b1;
            }
            size_t o0 = (size_t)row * ldc + col;
            size_t o1 = (size_t)(row + 8) * ldc + col;
            if (WF32) {
                *(float2*)(C + o0) = make_float2(v0, v1);
                *(float2*)(C + o1) = make_float2(v2, v3);
            }
            if (WSPLIT) {
                __nv_bfloat16 h0 = __float2bfloat16_rn(v0);
                __nv_bfloat16 h1 = __float2bfloat16_rn(v1);
                __nv_bfloat16 h2 = __float2bfloat16_rn(v2);
                __nv_bfloat16 h3 = __float2bfloat16_rn(v3);
                *(uint32_t*)(Ch + o0) = packbf(h0, h1);
                *(uint32_t*)(Ch + o1) = packbf(h2, h3);
                *(uint32_t*)(Cl + o0) = packbf(
                    __float2bfloat16_rn(v0 - __bfloat162float(h0)),
                    __float2bfloat16_rn(v1 - __bfloat162float(h1)));
                *(uint32_t*)(Cl + o1) = packbf(
                    __float2bfloat16_rn(v2 - __bfloat162float(h2)),
                    __float2bfloat16_rn(v3 - __bfloat162float(h3)));
            }
        }
    }
}

// ---------------- fused flash attention ---------------------------------------
__global__ __launch_bounds__(256) void flash_attn(
    const __nv_bfloat16* __restrict__ qkvh, const __nv_bfloat16* __restrict__ qkvl,
    __nv_bfloat16* __restrict__ outh, __nv_bfloat16* __restrict__ outl)
{
    const int qi = 15 - (int)blockIdx.x;
    const int bh = blockIdx.y;
    const int b = bh >> 4, h = bh & 15;
    const int q0 = qi * 128;
    const size_t base = (size_t)b * SEQ * 6144 + (size_t)h * 128;
    const __nv_bfloat16* Qp[2] = {qkvh + base, qkvl + base};
    const __nv_bfloat16* KVsrc[4] = {qkvh + base + 2048, qkvl + base + 2048,
                                     qkvh + base + 4096, qkvl + base + 4096};

    extern __shared__ char smem[];
    const uint32_t S0 = smem_u32(smem);
    const int tid = threadIdx.x, lane = tid & 31, warp = tid >> 5;

#pragma unroll
    for (int half = 0; half < 2; ++half) {
        const __nv_bfloat16* src = Qp[half];
        const uint32_t qb = S0 + half * 32768;
#pragma unroll
        for (int i = 0; i < 8; ++i) {
            int idx = tid + i * 256;
            int row = idx >> 4, c = idx & 15, p = c >> 3, c8 = c & 7;
            cp16(qb + p * 16384 + row * 128 + ((c8 ^ (row & 7)) << 4),
                 src + (size_t)(q0 + row) * 6144 + p * 64 + c8 * 8);
        }
    }

    auto copy_kv = [&](int t) {
        const uint32_t sb = S0 + 65536 + (uint32_t)(t & 1) * 65536;
        const int kv0 = t * 64;
#pragma unroll
        for (int q = 0; q < 4; ++q) {
#pragma unroll
            for (int i = 0; i < 4; ++i) {
                int idx = tid + i * 256;
                int row = idx >> 4, c = idx & 15, p = c >> 3, c8 = c & 7;
                cp16(sb + q * 16384 + p * 8192 + row * 128 + ((c8 ^ (row & 7)) << 4),
                     KVsrc[q] + (size_t)(kv0 + row) * 6144 + p * 64 + c8 * 8);
            }
        }
    };

    const int rselA = (lane & 7) + (((lane >> 3) & 1) << 3);
    const int chA   = (lane >> 4) & 1;
    const int rselB = (lane & 7) + (((lane >> 4) & 1) << 3);
    const int chB   = (lane >> 3) & 1;
    const int qr = warp * 16;

    float m0 = -1e30f, m1 = -1e30f, l0 = 0.f, l1 = 0.f;
    float accO[16][4];
#pragma unroll
    for (int j = 0; j < 16; ++j)
#pragma unroll
        for (int c = 0; c < 4; ++c) accO[j][c] = 0.f;

    const int nt = 2 * qi + 2;
    copy_kv(0); cp_commit();
    if (nt > 1) { copy_kv(1); cp_commit(); }

    for (int t = 0; t < nt; ++t) {
        if (t + 1 < nt) cp_wait<1>(); else cp_wait<0>();
        __syncthreads();

        const uint32_t sb  = S0 + 65536 + (uint32_t)(t & 1) * 65536;
        const uint32_t sKh = sb, sKl = sb + 16384, sVh = sb + 32768, sVl = sb + 49152;

        float accS[8][4];
#pragma unroll
        for (int j = 0; j < 8; ++j)
#pragma unroll
            for (int c = 0; c < 4; ++c) accS[j][c] = 0.f;

#pragma unroll
        for (int ks = 0; ks < 8; ++ks) {
            uint32_t aH[4], aL[4];
            {
                int row = qr + rselA;
                int g = ks * 2 + chA, p = g >> 3, c8 = g & 7;
                uint32_t off = (uint32_t)p * 16384 + row * 128 + ((c8 ^ (row & 7)) << 4);
                ldsm_x4(aH, S0 + off);
                ldsm_x4(aL, S0 + 32768 + off);
            }
#pragma unroll
            for (int n2 = 0; n2 < 4; ++n2) {
                uint32_t bH[4], bL[4];
                int row = n2 * 16 + rselB;
                int g = ks * 2 + chB, p = g >> 3, c8 = g & 7;
                uint32_t off = (uint32_t)p * 8192 + row * 128 + ((c8 ^ (row & 7)) << 4);
                ldsm_x4(bH, sKh + off);
                ldsm_x4(bL, sKl + off);
                mma_bf16(accS[2 * n2],     aH, bH);
                mma_bf16(accS[2 * n2 + 1], aH, bH + 2);
                mma_bf16(accS[2 * n2],     aH, bL);
                mma_bf16(accS[2 * n2 + 1], aH, bL + 2);
                mma_bf16(accS[2 * n2],     aL, bH);
                mma_bf16(accS[2 * n2 + 1], aL, bH + 2);
            }
        }

        const float isd = 0.08838834764831845f;
        const int kv0 = t * 64;
        const int grow0 = q0 + qr + (lane >> 2);
        const int grow1 = grow0 + 8;
        const bool masked = (t >= 2 * qi);
#pragma unroll
        for (int nf = 0; nf < 8; ++nf) {
#pragma unroll
            for (int c = 0; c < 4; ++c) accS[nf][c] *= isd;
            if (masked) {
                int col = kv0 + nf * 8 + (lane & 3) * 2;
                if (col     > grow0) accS[nf][0] = -1e30f;
                if (col + 1 > grow0) accS[nf][1] = -1e30f;
                if (col     > grow1) accS[nf][2] = -1e30f;
                if (col + 1 > grow1) accS[nf][3] = -1e30f;
            }
        }
        float mx0 = -1e30f, mx1 = -1e30f;
#pragma unroll
        for (int nf = 0; nf < 8; ++nf) {
            mx0 = fmaxf(mx0, fmaxf(accS[nf][0], accS[nf][1]));
            mx1 = fmaxf(mx1, fmaxf(accS[nf][2], accS[nf][3]));
        }
        mx0 = fmaxf(mx0, __shfl_xor_sync(0xffffffffu, mx0, 1));
        mx0 = fmaxf(mx0, __shfl_xor_sync(0xffffffffu, mx0, 2));
        mx1 = fmaxf(mx1, __shfl_xor_sync(0xffffffffu, mx1, 1));
        mx1 = fmaxf(mx1, __shfl_xor_sync(0xffffffffu, mx1, 2));
        const float nm0 = fmaxf(m0, mx0), nm1 = fmaxf(m1, mx1);
        const float cr0 = __expf(m0 - nm0), cr1 = __expf(m1 - nm1);
        m0 = nm0; m1 = nm1;

        float rs0 = 0.f, rs1 = 0.f;
        uint32_t phr[8], phr8[8], plr[8], plr8[8];
#pragma unroll
        for (int nf = 0; nf < 8; ++nf) {
            float p0 = __expf(accS[nf][0] - nm0), p1 = __expf(accS[nf][1] - nm0);
            float p2 = __expf(accS[nf][2] - nm1), p3 = __expf(accS[nf][3] - nm1);
            rs0 += p0 + p1; rs1 += p2 + p3;
            __nv_bfloat16 h0 = __float2bfloat16_rn(p0), h1 = __float2bfloat16_rn(p1);
            __nv_bfloat16 h2 = __float2bfloat16_rn(p2), h3 = __float2bfloat16_rn(p3);
            phr[nf]  = packbf(h0, h1);
            phr8[nf] = packbf(h2, h3);
            plr[nf]  = packbf(__float2bfloat16_rn(p0 - __bfloat162float(h0)),
                              __float2bfloat16_rn(p1 - __bfloat162float(h1)));
            plr8[nf] = packbf(__float2bfloat16_rn(p2 - __bfloat162float(h2)),
                              __float2bfloat16_rn(p3 - __bfloat162float(h3)));
        }
        rs0 += __shfl_xor_sync(0xffffffffu, rs0, 1);
        rs0 += __shfl_xor_sync(0xffffffffu, rs0, 2);
        rs1 += __shfl_xor_sync(0xffffffffu, rs1, 1);
        rs1 += __shfl_xor_sync(0xffffffffu, rs1, 2);
        l0 = l0 * cr0 + rs0;
        l1 = l1 * cr1 + rs1;
#pragma unroll
        for (int j = 0; j < 16; ++j) {
            accO[j][0] *= cr0; accO[j][1] *= cr0;
            accO[j][2] *= cr1; accO[j][3] *= cr1;
        }

#pragma unroll
        for (int ks = 0; ks < 4; ++ks) {
            uint32_t Aph[4] = {phr[2 * ks], phr8[2 * ks], phr[2 * ks + 1], phr8[2 * ks + 1]};
            uint32_t Apl[4] = {plr[2 * ks], plr8[2 * ks], plr[2 * ks + 1], plr8[2 * ks + 1]};
            const int rowv = ks * 16 + (lane & 15);
#pragma unroll
            for (int jj = 0; jj < 4; ++jj) {
                uint32_t vh0[4], vl0[4], vh1[4], vl1[4];
                {
                    int cv = 4 * jj + (lane >> 4), p = cv >> 3, c8 = cv & 7;
                    uint32_t off = (uint32_t)p * 8192 + rowv * 128 + ((c8 ^ (rowv & 7)) << 4);
                    ldsm_x4_t(vh0, sVh + off);
                    ldsm_x4_t(vl0, sVl + off);
                }
                {
                    int cv = 4 * jj + 2 + (lane >> 4), p = cv >> 3, c8 = cv & 7;
                    uint32_t off = (uint32_t)p * 8192 + rowv * 128 + ((c8 ^ (rowv & 7)) << 4);
                    ldsm_x4_t(vh1, sVh + off);
                    ldsm_x4_t(vl1, sVl + off);
                }
                float* a0 = accO[4 * jj];
                float* a1 = accO[4 * jj + 1];
                float* a2 = accO[4 * jj + 2];
                float* a3 = accO[4 * jj + 3];
                mma_bf16(a0, Aph, vh0); mma_bf16(a1, Aph, vh0 + 2);
                mma_bf16(a2, Aph, vh1); mma_bf16(a3, Aph, vh1 + 2);
                mma_bf16(a0, Aph, vl0); mma_bf16(a1, Aph, vl0 + 2);
                mma_bf16(a2, Aph, vl1); mma_bf16(a3, Aph, vl1 + 2);
                mma_bf16(a0, Apl, vh0); mma_bf16(a1, Apl, vh0 + 2);
                mma_bf16(a2, Apl, vh1); mma_bf16(a3, Apl, vh1 + 2);
            }
        }

        __syncthreads();
        if (t + 2 < nt) { copy_kv(t + 2); cp_commit(); }
    }

    const float i0 = 1.f / l0, i1 = 1.f / l1;
    const size_t obase = (size_t)b * SEQ * N_EMBD + (size_t)h * 128;
    const int row0 = q0 + qr + (lane >> 2);
#pragma unroll
    for (int j = 0; j < 16; ++j) {
        int d = j * 8 + (lane & 3) * 2;
        size_t o0 = obase + (size_t)row0 * N_EMBD + d;
        size_t o1 = obase + (size_t)(row0 + 8) * N_EMBD + d;
        float v0 = accO[j][0] * i0, v1 = accO[j][1] * i0;
        float v2 = accO[j][2] * i1, v3 = accO[j][3] * i1;
        __nv_bfloat16 h0 = __float2bfloat16_rn(v0), h1 = __float2bfloat16_rn(v1);
        __nv_bfloat16 h2 = __float2bfloat16_rn(v2), h3 = __float2bfloat16_rn(v3);
        *(uint32_t*)(outh + o0) = packbf(h0, h1);
        *(uint32_t*)(outh + o1) = packbf(h2, h3);
        *(uint32_t*)(outl + o0) = packbf(__float2bfloat16_rn(v0 - __bfloat162float(h0)),
                                         __float2bfloat16_rn(v1 - __bfloat162float(h1)));
        *(uint32_t*)(outl + o1) = packbf(__float2bfloat16_rn(v2 - __bfloat162float(h2)),
                                         __float2bfloat16_rn(v3 - __bfloat162float(h3)));
    }
}

// ---------------- converts ----------------------------------------------------
__global__ __launch_bounds__(256) void convert_split(
    const float* __restrict__ in, __nv_bfloat16* __restrict__ oh,
    __nv_bfloat16* __restrict__ ol, int n)
{
    for (int i = blockIdx.x * 256 + threadIdx.x; i < n; i += gridDim.x * 256) {
        float v = in[i];
        __nv_bfloat16 h = __float2bfloat16_rn(v);
        oh[i] = h;
        ol[i] = __float2bfloat16_rn(v - __bfloat162float(h));
    }
}
__global__ __launch_bounds__(256) void transpose_split(
    const float* __restrict__ in, __nv_bfloat16* __restrict__ oh,
    __nv_bfloat16* __restrict__ ol, int ld_in, int ld_out)
{
    __shared__ float t[32][33];
    const int c0 = blockIdx.x * 32, r0 = blockIdx.y * 32;
    const int tx = threadIdx.x, ty = threadIdx.y;
#pragma unroll
    for (int j = 0; j < 32; j += 8)
        t[ty + j][tx] = in[(size_t)(r0 + ty + j) * ld_in + c0 + tx];
    __syncthreads();
#pragma unroll
    for (int j = 0; j < 32; j += 8) {
        float v = t[tx][ty + j];
        __nv_bfloat16 h = __float2bfloat16_rn(v);
        size_t o = (size_t)(c0 + ty + j) * ld_out + r0 + tx;
        oh[o] = h;
        ol[o] = __float2bfloat16_rn(v - __bfloat162float(h));
    }
}

// ---------------- launch ------------------------------------------------------
extern "C" void kernel_launch(void* const* d_in, const int* in_sizes, int n_in,
                              void* d_out, int out_size)
{
    const float* x     = (const float*)d_in[0];
    const float* Wqkv  = (const float*)d_in[1];
    const float* bqkv  = (const float*)d_in[2];
    const float* Wproj = (const float*)d_in[3];
    const float* bproj = (const float*)d_in[4];
    float* out = (float*)d_out;

    __nv_bfloat16 *x_h, *x_l, *wq_h, *wq_l, *wp_h, *wp_l;
    __nv_bfloat16 *qkv_h, *qkv_l, *at_h, *at_l;
    cudaGetSymbolAddress((void**)&x_h, g_x_h);
    cudaGetSymbolAddress((void**)&x_l, g_x_l);
    cudaGetSymbolAddress((void**)&wq_h, g_wqkvT_h);
    cudaGetSymbolAddress((void**)&wq_l, g_wqkvT_l);
    cudaGetSymbolAddress((void**)&wp_h, g_wprojT_h);
    cudaGetSymbolAddress((void**)&wp_l, g_wprojT_l);
    cudaGetSymbolAddress((void**)&qkv_h, g_qkv_h);
    cudaGetSymbolAddress((void**)&qkv_l, g_qkv_l);
    cudaGetSymbolAddress((void**)&at_h, g_attn_h);
    cudaGetSymbolAddress((void**)&at_l, g_attn_l);

    const int GEMM_SMEM = 98304;     // 3 stages x 32KB; 2 CTAs/SM = 192KB
    const int FLASH_SMEM = 196608;
    cudaFuncSetAttribute(gemm_bf16x3<true, false, true>,
                         cudaFuncAttributeMaxDynamicSharedMemorySize, GEMM_SMEM);
    cudaFuncSetAttribute(gemm_bf16x3<true, true, false>,
                         cudaFuncAttributeMaxDynamicSharedMemorySize, GEMM_SMEM);
    cudaFuncSetAttribute(flash_attn,
                         cudaFuncAttributeMaxDynamicSharedMemorySize, FLASH_SMEM);

    const int M = BATCH * SEQ, E = N_EMBD, E3 = 3 * N_EMBD;

    convert_split<<<4096, 256>>>(x, x_h, x_l, M * E);
    transpose_split<<<dim3(E3 / 32, E / 32), dim3(32, 8)>>>(Wqkv, wq_h, wq_l, E3, E);
    transpose_split<<<dim3(E / 32, E / 32), dim3(32, 8)>>>(Wproj, wp_h, wp_l, E, E);

    gemm_bf16x3<true, false, true><<<dim3(E3 / BN, M / BM), 256, GEMM_SMEM>>>(
        x_h, x_l, wq_h, wq_l, bqkv, nullptr, qkv_h, qkv_l, E, E, E, E3, 1.f);

    flash_attn<<<dim3(SEQ / 128, BATCH * N_HEAD), 256, FLASH_SMEM>>>(
        qkv_h, qkv_l, at_h, at_l);

    gemm_bf16x3<true, true, false><<<dim3(E / BN, M / BM), 256, GEMM_SMEM>>>(
        at_h, at_l, wp_h, wp_l, bproj, out, nullptr, nullptr, E, E, E, E, 1.f);
}

// round 8
// speedup vs baseline: 5.6361x; 1.2989x over previous
#include <cuda_runtime.h>
#include <cuda_fp16.h>
#include <cstdint>

#define N_EMBD 2048
#define N_HEAD 16
#define HEAD_DIM 128
#define BATCH 2
#define SEQ 2048

#define BM 128
#define BN 128

// ---------------- scratch ----------------------------------------------------
__device__ __half g_x_h[(size_t)BATCH * SEQ * N_EMBD];
__device__ __half g_x_l[(size_t)BATCH * SEQ * N_EMBD];
__device__ __half g_wqkvT[(size_t)3 * N_EMBD * N_EMBD];
__device__ __half g_wprojT[(size_t)N_EMBD * N_EMBD];
__device__ __half g_qkv_h[(size_t)BATCH * SEQ * 3 * N_EMBD];
__device__ __half g_qkv_l[(size_t)BATCH * SEQ * 3 * N_EMBD];
__device__ __half g_attn_h[(size_t)BATCH * SEQ * N_EMBD];
__device__ __half g_attn_l[(size_t)BATCH * SEQ * N_EMBD];

// ---------------- PTX helpers -------------------------------------------------
__device__ __forceinline__ uint32_t smem_u32(const void* p) {
    return (uint32_t)__cvta_generic_to_shared(p);
}
__device__ __forceinline__ void ldsm_x4(uint32_t* r, uint32_t addr) {
    asm volatile("ldmatrix.sync.aligned.m8n8.x4.shared.b16 {%0,%1,%2,%3}, [%4];"
                 : "=r"(r[0]), "=r"(r[1]), "=r"(r[2]), "=r"(r[3]) : "r"(addr));
}
__device__ __forceinline__ void ldsm_x4_t(uint32_t* r, uint32_t addr) {
    asm volatile("ldmatrix.sync.aligned.m8n8.x4.trans.shared.b16 {%0,%1,%2,%3}, [%4];"
                 : "=r"(r[0]), "=r"(r[1]), "=r"(r[2]), "=r"(r[3]) : "r"(addr));
}
__device__ __forceinline__ void mma_f16(float* d, const uint32_t* a, const uint32_t* b) {
    asm volatile(
        "mma.sync.aligned.m16n8k16.row.col.f32.f16.f16.f32 "
        "{%0,%1,%2,%3},{%4,%5,%6,%7},{%8,%9},{%0,%1,%2,%3};"
        : "+f"(d[0]), "+f"(d[1]), "+f"(d[2]), "+f"(d[3])
        : "r"(a[0]), "r"(a[1]), "r"(a[2]), "r"(a[3]), "r"(b[0]), "r"(b[1]));
}
__device__ __forceinline__ void cp16(uint32_t dst, const void* src) {
    asm volatile("cp.async.cg.shared.global [%0], [%1], 16;" :: "r"(dst), "l"(src));
}
__device__ __forceinline__ void cp_commit() {
    asm volatile("cp.async.commit_group;" ::: "memory");
}
template <int W> __device__ __forceinline__ void cp_wait() {
    asm volatile("cp.async.wait_group %0;" :: "n"(W) : "memory");
}
__device__ __forceinline__ uint32_t packh(__half a, __half b) {
    __half2 t; t.x = a; t.y = b;
    uint32_t u; *(__half2*)&u = t; return u;
}

// ---------------- fp16 2-term GEMM: C = A@B^T (+bias) -------------------------
// A:[M][K] split hi/lo fp16; B:[N][K] plain fp16 K-contiguous.
// BK=64, 2-stage cp.async, 2 CTAs/SM. Terms: Ah*B + Al*B.
template <bool BIAS, bool WF32, bool WSPLIT>
__global__ __launch_bounds__(256, 2) void gemm_f16x2(
    const __half* __restrict__ Ah, const __half* __restrict__ Al,
    const __half* __restrict__ B,
    const float* __restrict__ bias,
    float* __restrict__ C, __half* __restrict__ Ch, __half* __restrict__ Cl,
    int K, int lda, int ldb, int ldc, int loLim)
{
    extern __shared__ char smem[];
    const int tid = threadIdx.x;
    const int m0 = blockIdx.y * BM, n0 = blockIdx.x * BN;
    const int nt = K >> 6;

    // stage: A_hi[0,16K) A_lo[16K,32K) B[32K,48K); stride 48KB
    const uint32_t S0 = smem_u32(smem);
    const int crow = tid >> 1;            // 0..127
    const int cc0  = (tid & 1) * 4;       // chunk 0 or 4

    auto copy_stage = [&](int kt) {
        const uint32_t base = S0 + (uint32_t)(kt & 1) * 49152;
        const int kel = (kt << 6) + cc0 * 8;
        const __half* ah = Ah + (size_t)(m0 + crow) * lda + kel;
        const __half* al = Al + (size_t)(m0 + crow) * lda + kel;
        const __half* bb = B  + (size_t)(n0 + crow) * ldb + kel;
#pragma unroll
        for (int j = 0; j < 4; ++j) {
            uint32_t sw = (((cc0 + j) ^ (crow & 7)) << 4) + crow * 128;
            cp16(base + sw,         ah + j * 8);
            cp16(base + 16384 + sw, al + j * 8);
            cp16(base + 32768 + sw, bb + j * 8);
        }
    };

    const int warp = tid >> 5, lane = tid & 31;
    const int wm = warp >> 1, wn = warp & 1;
    const int rselA = (lane & 7) + (((lane >> 3) & 1) << 3);
    const int chA   = (lane >> 4) & 1;
    const int rselB = (lane & 7) + (((lane >> 4) & 1) << 3);
    const int chB   = (lane >> 3) & 1;

    float acc[2][8][4];
#pragma unroll
    for (int a = 0; a < 2; ++a)
#pragma unroll
        for (int b = 0; b < 8; ++b)
#pragma unroll
            for (int c = 0; c < 4; ++c) acc[a][b][c] = 0.f;

    auto compute_tile = [&](int buf) {
        const uint32_t base = S0 + (uint32_t)buf * 49152;
#pragma unroll
        for (int ks = 0; ks < 4; ++ks) {
            uint32_t aH[2][4], aL[2][4];
            const int g = 2 * ks + chA;
#pragma unroll
            for (int mf = 0; mf < 2; ++mf) {
                int row = wm * 32 + mf * 16 + rselA;
                uint32_t off = row * 128 + ((g ^ (row & 7)) << 4);
                ldsm_x4(aH[mf], base + off);
                ldsm_x4(aL[mf], base + 16384 + off);
            }
            const int gb = 2 * ks + chB;
#pragma unroll
            for (int np = 0; np < 4; ++np) {
                uint32_t bh[4];
                int rowb = wn * 64 + np * 16 + rselB;
                ldsm_x4(bh, base + 32768 + rowb * 128 + ((gb ^ (rowb & 7)) << 4));
#pragma unroll
                for (int mf = 0; mf < 2; ++mf) {
                    mma_f16(acc[mf][2 * np],     aH[mf], bh);
                    mma_f16(acc[mf][2 * np + 1], aH[mf], bh + 2);
                    mma_f16(acc[mf][2 * np],     aL[mf], bh);
                    mma_f16(acc[mf][2 * np + 1], aL[mf], bh + 2);
                }
            }
        }
    };

    copy_stage(0); cp_commit();
    if (nt > 1) { copy_stage(1); cp_commit(); }
    for (int kt = 0; kt < nt; ++kt) {
        if (kt + 1 < nt) cp_wait<1>(); else cp_wait<0>();
        __syncthreads();
        compute_tile(kt & 1);
        __syncthreads();
        if (kt + 2 < nt) { copy_stage(kt + 2); cp_commit(); }
    }

#pragma unroll
    for (int mf = 0; mf < 2; ++mf) {
        int row = m0 + wm * 32 + mf * 16 + (lane >> 2);
#pragma unroll
        for (int nf = 0; nf < 8; ++nf) {
            int col = n0 + wn * 64 + nf * 8 + (lane & 3) * 2;
            float v0 = acc[mf][nf][0], v1 = acc[mf][nf][1];
            float v2 = acc[mf][nf][2], v3 = acc[mf][nf][3];
            if (BIAS) {
                float b0 = bias[col], b1 = bias[col + 1];
                v0 += b0; v1 += b1; v2 += b0; v3 += b1;
            }
            size_t o0 = (size_t)row * ldc + col;
            size_t o1 = (size_t)(row + 8) * ldc + col;
            if (WF32) {
                *(float2*)(C + o0) = make_float2(v0, v1);
                *(float2*)(C + o1) = make_float2(v2, v3);
            }
            if (WSPLIT) {
                __half h0 = __float2half_rn(v0), h1 = __float2half_rn(v1);
                __half h2 = __float2half_rn(v2), h3 = __float2half_rn(v3);
                *(uint32_t*)(Ch + o0) = packh(h0, h1);
                *(uint32_t*)(Ch + o1) = packh(h2, h3);
                if (col < loLim) {
                    *(uint32_t*)(Cl + o0) = packh(
                        __float2half_rn(v0 - __half2float(h0)),
                        __float2half_rn(v1 - __half2float(h1)));
                    *(uint32_t*)(Cl + o1) = packh(
                        __float2half_rn(v2 - __half2float(h2)),
                        __float2half_rn(v3 - __half2float(h3)));
                }
            }
        }
    }
}

// ---------------- fused flash attention (fp16, 2-term) ------------------------
// Q split hi/lo; K, V plain fp16 (hi tensor only).
__global__ __launch_bounds__(256) void flash_attn(
    const __half* __restrict__ qkvh, const __half* __restrict__ qkvl,
    __half* __restrict__ outh, __half* __restrict__ outl)
{
    const int qi = 15 - (int)blockIdx.x;
    const int bh = blockIdx.y;
    const int b = bh >> 4, h = bh & 15;
    const int q0 = qi * 128;
    const size_t base = (size_t)b * SEQ * 6144 + (size_t)h * 128;
    const __half* Qp[2] = {qkvh + base, qkvl + base};
    const __half* Kp = qkvh + base + 2048;
    const __half* Vp = qkvh + base + 4096;

    extern __shared__ char smem[];
    const uint32_t S0 = smem_u32(smem);
    const int tid = threadIdx.x, lane = tid & 31, warp = tid >> 5;

    // Q: 2 halves x (2 p-planes x 128 rows x 128B) = 64KB
#pragma unroll
    for (int half = 0; half < 2; ++half) {
        const __half* src = Qp[half];
        const uint32_t qb = S0 + half * 32768;
#pragma unroll
        for (int i = 0; i < 8; ++i) {
            int idx = tid + i * 256;
            int row = idx >> 4, c = idx & 15, p = c >> 3, c8 = c & 7;
            cp16(qb + p * 16384 + row * 128 + ((c8 ^ (row & 7)) << 4),
                 src + (size_t)(q0 + row) * 6144 + p * 64 + c8 * 8);
        }
    }

    // KV stage: K[0,16K) V[16K,32K); 2 stages at S0+64K
    auto copy_kv = [&](int t) {
        const uint32_t sb = S0 + 65536 + (uint32_t)(t & 1) * 32768;
        const int kv0 = t * 64;
#pragma unroll
        for (int q = 0; q < 2; ++q) {
            const __half* src = q ? Vp : Kp;
#pragma unroll
            for (int i = 0; i < 4; ++i) {
                int idx = tid + i * 256;
                int row = idx >> 4, c = idx & 15, p = c >> 3, c8 = c & 7;
                cp16(sb + q * 16384 + p * 8192 + row * 128 + ((c8 ^ (row & 7)) << 4),
                     src + (size_t)(kv0 + row) * 6144 + p * 64 + c8 * 8);
            }
        }
    };

    const int rselA = (lane & 7) + (((lane >> 3) & 1) << 3);
    const int chA   = (lane >> 4) & 1;
    const int rselB = (lane & 7) + (((lane >> 4) & 1) << 3);
    const int chB   = (lane >> 3) & 1;
    const int qr = warp * 16;

    float m0 = -1e30f, m1 = -1e30f, l0 = 0.f, l1 = 0.f;
    float accO[16][4];
#pragma unroll
    for (int j = 0; j < 16; ++j)
#pragma unroll
        for (int c = 0; c < 4; ++c) accO[j][c] = 0.f;

    const int nt = 2 * qi + 2;
    copy_kv(0); cp_commit();
    if (nt > 1) { copy_kv(1); cp_commit(); }

    for (int t = 0; t < nt; ++t) {
        if (t + 1 < nt) cp_wait<1>(); else cp_wait<0>();
        __syncthreads();

        const uint32_t sb = S0 + 65536 + (uint32_t)(t & 1) * 32768;
        const uint32_t sK = sb, sV = sb + 16384;

        float accS[8][4];
#pragma unroll
        for (int j = 0; j < 8; ++j)
#pragma unroll
            for (int c = 0; c < 4; ++c) accS[j][c] = 0.f;

#pragma unroll
        for (int ks = 0; ks < 8; ++ks) {
            uint32_t aH[4], aL[4];
            {
                int row = qr + rselA;
                int g = ks * 2 + chA, p = g >> 3, c8 = g & 7;
                uint32_t off = (uint32_t)p * 16384 + row * 128 + ((c8 ^ (row & 7)) << 4);
                ldsm_x4(aH, S0 + off);
                ldsm_x4(aL, S0 + 32768 + off);
            }
#pragma unroll
            for (int n2 = 0; n2 < 4; ++n2) {
                uint32_t bH[4];
                int row = n2 * 16 + rselB;
                int g = ks * 2 + chB, p = g >> 3, c8 = g & 7;
                ldsm_x4(bH, sK + (uint32_t)p * 8192 + row * 128 + ((c8 ^ (row & 7)) << 4));
                mma_f16(accS[2 * n2],     aH, bH);
                mma_f16(accS[2 * n2 + 1], aH, bH + 2);
                mma_f16(accS[2 * n2],     aL, bH);
                mma_f16(accS[2 * n2 + 1], aL, bH + 2);
            }
        }

        const float isd = 0.08838834764831845f;
        const int kv0 = t * 64;
        const int grow0 = q0 + qr + (lane >> 2);
        const int grow1 = grow0 + 8;
        const bool masked = (t >= 2 * qi);
#pragma unroll
        for (int nf = 0; nf < 8; ++nf) {
#pragma unroll
            for (int c = 0; c < 4; ++c) accS[nf][c] *= isd;
            if (masked) {
                int col = kv0 + nf * 8 + (lane & 3) * 2;
                if (col     > grow0) accS[nf][0] = -1e30f;
                if (col + 1 > grow0) accS[nf][1] = -1e30f;
                if (col     > grow1) accS[nf][2] = -1e30f;
                if (col + 1 > grow1) accS[nf][3] = -1e30f;
            }
        }
        float mx0 = -1e30f, mx1 = -1e30f;
#pragma unroll
        for (int nf = 0; nf < 8; ++nf) {
            mx0 = fmaxf(mx0, fmaxf(accS[nf][0], accS[nf][1]));
            mx1 = fmaxf(mx1, fmaxf(accS[nf][2], accS[nf][3]));
        }
        mx0 = fmaxf(mx0, __shfl_xor_sync(0xffffffffu, mx0, 1));
        mx0 = fmaxf(mx0, __shfl_xor_sync(0xffffffffu, mx0, 2));
        mx1 = fmaxf(mx1, __shfl_xor_sync(0xffffffffu, mx1, 1));
        mx1 = fmaxf(mx1, __shfl_xor_sync(0xffffffffu, mx1, 2));
        const float nm0 = fmaxf(m0, mx0), nm1 = fmaxf(m1, mx1);
        const float cr0 = __expf(m0 - nm0), cr1 = __expf(m1 - nm1);
        m0 = nm0; m1 = nm1;

        float rs0 = 0.f, rs1 = 0.f;
        uint32_t phr[8], phr8[8], plr[8], plr8[8];
#pragma unroll
        for (int nf = 0; nf < 8; ++nf) {
            float p0 = __expf(accS[nf][0] - nm0), p1 = __expf(accS[nf][1] - nm0);
            float p2 = __expf(accS[nf][2] - nm1), p3 = __expf(accS[nf][3] - nm1);
            rs0 += p0 + p1; rs1 += p2 + p3;
            __half h0 = __float2half_rn(p0), h1 = __float2half_rn(p1);
            __half h2 = __float2half_rn(p2), h3 = __float2half_rn(p3);
            phr[nf]  = packh(h0, h1);
            phr8[nf] = packh(h2, h3);
            plr[nf]  = packh(__float2half_rn(p0 - __half2float(h0)),
                             __float2half_rn(p1 - __half2float(h1)));
            plr8[nf] = packh(__float2half_rn(p2 - __half2float(h2)),
                             __float2half_rn(p3 - __half2float(h3)));
        }
        rs0 += __shfl_xor_sync(0xffffffffu, rs0, 1);
        rs0 += __shfl_xor_sync(0xffffffffu, rs0, 2);
        rs1 += __shfl_xor_sync(0xffffffffu, rs1, 1);
        rs1 += __shfl_xor_sync(0xffffffffu, rs1, 2);
        l0 = l0 * cr0 + rs0;
        l1 = l1 * cr1 + rs1;
#pragma unroll
        for (int j = 0; j < 16; ++j) {
            accO[j][0] *= cr0; accO[j][1] *= cr0;
            accO[j][2] *= cr1; accO[j][3] *= cr1;
        }

        // O += P V  (P split 2-term, V plain)
#pragma unroll
        for (int ks = 0; ks < 4; ++ks) {
            uint32_t Aph[4] = {phr[2 * ks], phr8[2 * ks], phr[2 * ks + 1], phr8[2 * ks + 1]};
            uint32_t Apl[4] = {plr[2 * ks], plr8[2 * ks], plr[2 * ks + 1], plr8[2 * ks + 1]};
            const int rowv = ks * 16 + (lane & 15);
#pragma unroll
            for (int jj = 0; jj < 4; ++jj) {
                uint32_t vh0[4], vh1[4];
                {
                    int cv = 4 * jj + (lane >> 4), p = cv >> 3, c8 = cv & 7;
                    ldsm_x4_t(vh0, sV + (uint32_t)p * 8192 + rowv * 128 + ((c8 ^ (rowv & 7)) << 4));
                }
                {
                    int cv = 4 * jj + 2 + (lane >> 4), p = cv >> 3, c8 = cv & 7;
                    ldsm_x4_t(vh1, sV + (uint32_t)p * 8192 + rowv * 128 + ((c8 ^ (rowv & 7)) << 4));
                }
                float* a0 = accO[4 * jj];
                float* a1 = accO[4 * jj + 1];
                float* a2 = accO[4 * jj + 2];
                float* a3 = accO[4 * jj + 3];
                mma_f16(a0, Aph, vh0); mma_f16(a1, Aph, vh0 + 2);
                mma_f16(a2, Aph, vh1); mma_f16(a3, Aph, vh1 + 2);
                mma_f16(a0, Apl, vh0); mma_f16(a1, Apl, vh0 + 2);
                mma_f16(a2, Apl, vh1); mma_f16(a3, Apl, vh1 + 2);
            }
        }

        __syncthreads();
        if (t + 2 < nt) { copy_kv(t + 2); cp_commit(); }
    }

    const float i0 = 1.f / l0, i1 = 1.f / l1;
    const size_t obase = (size_t)b * SEQ * N_EMBD + (size_t)h * 128;
    const int row0 = q0 + qr + (lane >> 2);
#pragma unroll
    for (int j = 0; j < 16; ++j) {
        int d = j * 8 + (lane & 3) * 2;
        size_t o0 = obase + (size_t)row0 * N_EMBD + d;
        size_t o1 = obase + (size_t)(row0 + 8) * N_EMBD + d;
        float v0 = accO[j][0] * i0, v1 = accO[j][1] * i0;
        float v2 = accO[j][2] * i1, v3 = accO[j][3] * i1;
        __half h0 = __float2half_rn(v0), h1 = __float2half_rn(v1);
        __half h2 = __float2half_rn(v2), h3 = __float2half_rn(v3);
        *(uint32_t*)(outh + o0) = packh(h0, h1);
        *(uint32_t*)(outh + o1) = packh(h2, h3);
        *(uint32_t*)(outl + o0) = packh(__float2half_rn(v0 - __half2float(h0)),
                                        __float2half_rn(v1 - __half2float(h1)));
        *(uint32_t*)(outl + o1) = packh(__float2half_rn(v2 - __half2float(h2)),
                                        __float2half_rn(v3 - __half2float(h3)));
    }
}

// ---------------- converts ----------------------------------------------------
__global__ __launch_bounds__(256) void convert_split(
    const float* __restrict__ in, __half* __restrict__ oh,
    __half* __restrict__ ol, int n)
{
    for (int i = blockIdx.x * 256 + threadIdx.x; i < n; i += gridDim.x * 256) {
        float v = in[i];
        __half h = __float2half_rn(v);
        oh[i] = h;
        ol[i] = __float2half_rn(v - __half2float(h));
    }
}
__global__ __launch_bounds__(256) void transpose_w(
    const float* __restrict__ in, __half* __restrict__ out, int ld_in, int ld_out)
{
    __shared__ float t[32][33];
    const int c0 = blockIdx.x * 32, r0 = blockIdx.y * 32;
    const int tx = threadIdx.x, ty = threadIdx.y;
#pragma unroll
    for (int j = 0; j < 32; j += 8)
        t[ty + j][tx] = in[(size_t)(r0 + ty + j) * ld_in + c0 + tx];
    __syncthreads();
#pragma unroll
    for (int j = 0; j < 32; j += 8)
        out[(size_t)(c0 + ty + j) * ld_out + r0 + tx] = __float2half_rn(t[tx][ty + j]);
}

// ---------------- launch ------------------------------------------------------
extern "C" void kernel_launch(void* const* d_in, const int* in_sizes, int n_in,
                              void* d_out, int out_size)
{
    const float* x     = (const float*)d_in[0];
    const float* Wqkv  = (const float*)d_in[1];
    const float* bqkv  = (const float*)d_in[2];
    const float* Wproj = (const float*)d_in[3];
    const float* bproj = (const float*)d_in[4];
    float* out = (float*)d_out;

    __half *x_h, *x_l, *wq, *wp, *qkv_h, *qkv_l, *at_h, *at_l;
    cudaGetSymbolAddress((void**)&x_h, g_x_h);
    cudaGetSymbolAddress((void**)&x_l, g_x_l);
    cudaGetSymbolAddress((void**)&wq, g_wqkvT);
    cudaGetSymbolAddress((void**)&wp, g_wprojT);
    cudaGetSymbolAddress((void**)&qkv_h, g_qkv_h);
    cudaGetSymbolAddress((void**)&qkv_l, g_qkv_l);
    cudaGetSymbolAddress((void**)&at_h, g_attn_h);
    cudaGetSymbolAddress((void**)&at_l, g_attn_l);

    const int GEMM_SMEM = 98304;     // 2 stages x 48KB; 2 CTAs/SM
    const int FLASH_SMEM = 131072;   // Q 64KB + 2 stages x 32KB
    cudaFuncSetAttribute(gemm_f16x2<true, false, true>,
                         cudaFuncAttributeMaxDynamicSharedMemorySize, GEMM_SMEM);
    cudaFuncSetAttribute(gemm_f16x2<true, true, false>,
                         cudaFuncAttributeMaxDynamicSharedMemorySize, GEMM_SMEM);
    cudaFuncSetAttribute(flash_attn,
                         cudaFuncAttributeMaxDynamicSharedMemorySize, FLASH_SMEM);

    const int M = BATCH * SEQ, E = N_EMBD, E3 = 3 * N_EMBD;

    convert_split<<<4096, 256>>>(x, x_h, x_l, M * E);
    transpose_w<<<dim3(E3 / 32, E / 32), dim3(32, 8)>>>(Wqkv, wq, E3, E);
    transpose_w<<<dim3(E / 32, E / 32), dim3(32, 8)>>>(Wproj, wp, E, E);

    // 1) qkv = x @ Wqkv + b  -> hi (all cols), lo (Q cols only)
    gemm_f16x2<true, false, true><<<dim3(E3 / BN, M / BM), 256, GEMM_SMEM>>>(
        x_h, x_l, wq, bqkv, nullptr, qkv_h, qkv_l, E, E, E, E3, 2048);

    // 2-4) fused flash attention -> attn hi/lo
    flash_attn<<<dim3(SEQ / 128, BATCH * N_HEAD), 256, FLASH_SMEM>>>(
        qkv_h, qkv_l, at_h, at_l);

    // 5) out = attn @ Wproj + b
    gemm_f16x2<true, true, false><<<dim3(E / BN, M / BM), 256, GEMM_SMEM>>>(
        at_h, at_l, wp, bproj, out, nullptr, nullptr, E, E, E, E, 0);
}

// round 9
// speedup vs baseline: 6.5023x; 1.1537x over previous
#include <cuda_runtime.h>
#include <cuda_fp16.h>
#include <cstdint>

#define N_EMBD 2048
#define N_HEAD 16
#define HEAD_DIM 128
#define BATCH 2
#define SEQ 2048

#define BM 128
#define BN 128

// ---------------- scratch ----------------------------------------------------
__device__ __half g_x_h[(size_t)BATCH * SEQ * N_EMBD];
__device__ __half g_x_l[(size_t)BATCH * SEQ * N_EMBD];
__device__ __half g_wqkvT[(size_t)3 * N_EMBD * N_EMBD];
__device__ __half g_wprojT[(size_t)N_EMBD * N_EMBD];
__device__ __half g_qkv_h[(size_t)BATCH * SEQ * 3 * N_EMBD];
__device__ __half g_qkv_l[(size_t)BATCH * SEQ * 3 * N_EMBD];
__device__ __half g_attn_h[(size_t)BATCH * SEQ * N_EMBD];
__device__ __half g_attn_l[(size_t)BATCH * SEQ * N_EMBD];

// ---------------- PTX helpers -------------------------------------------------
__device__ __forceinline__ uint32_t smem_u32(const void* p) {
    return (uint32_t)__cvta_generic_to_shared(p);
}
__device__ __forceinline__ void ldsm_x4(uint32_t* r, uint32_t addr) {
    asm volatile("ldmatrix.sync.aligned.m8n8.x4.shared.b16 {%0,%1,%2,%3}, [%4];"
                 : "=r"(r[0]), "=r"(r[1]), "=r"(r[2]), "=r"(r[3]) : "r"(addr));
}
__device__ __forceinline__ void ldsm_x4_t(uint32_t* r, uint32_t addr) {
    asm volatile("ldmatrix.sync.aligned.m8n8.x4.trans.shared.b16 {%0,%1,%2,%3}, [%4];"
                 : "=r"(r[0]), "=r"(r[1]), "=r"(r[2]), "=r"(r[3]) : "r"(addr));
}
__device__ __forceinline__ void mma_f16(float* d, const uint32_t* a, const uint32_t* b) {
    asm volatile(
        "mma.sync.aligned.m16n8k16.row.col.f32.f16.f16.f32 "
        "{%0,%1,%2,%3},{%4,%5,%6,%7},{%8,%9},{%0,%1,%2,%3};"
        : "+f"(d[0]), "+f"(d[1]), "+f"(d[2]), "+f"(d[3])
        : "r"(a[0]), "r"(a[1]), "r"(a[2]), "r"(a[3]), "r"(b[0]), "r"(b[1]));
}
__device__ __forceinline__ void cp16(uint32_t dst, const void* src) {
    asm volatile("cp.async.cg.shared.global [%0], [%1], 16;" :: "r"(dst), "l"(src));
}
__device__ __forceinline__ void cp_commit() {
    asm volatile("cp.async.commit_group;" ::: "memory");
}
template <int W> __device__ __forceinline__ void cp_wait() {
    asm volatile("cp.async.wait_group %0;" :: "n"(W) : "memory");
}
__device__ __forceinline__ uint32_t packh(__half a, __half b) {
    __half2 t; t.x = a; t.y = b;
    uint32_t u; *(__half2*)&u = t; return u;
}

// ---------------- fp16 GEMM, BK=32, 3-stage, 1 sync/tile, 2 CTAs/SM -----------
// A:[M][K] split hi/lo fp16 (packed hi|lo per 128B smem row);
// B:[N][K] plain fp16, 64B smem rows.
// Column blocks with n0 < loLim use 2 terms (Ah+Al); others 1 term (Ah only).
template <bool BIAS, bool WF32, bool WSPLIT>
__global__ __launch_bounds__(256, 2) void gemm_f16x2(
    const __half* __restrict__ Ah, const __half* __restrict__ Al,
    const __half* __restrict__ B,
    const float* __restrict__ bias,
    float* __restrict__ C, __half* __restrict__ Ch, __half* __restrict__ Cl,
    int K, int lda, int ldb, int ldc, int loLim)
{
    extern __shared__ char smem[];
    const int tid = threadIdx.x;
    const int m0 = blockIdx.y * BM, n0 = blockIdx.x * BN;
    const int nt = K >> 5;
    const bool two = (n0 < loLim);

    // stage: A 16KB (128 rows x 128B: chunks 0-3 hi, 4-7 lo) + B 8KB (128 x 64B)
    const uint32_t S0 = smem_u32(smem);

    // A copy: 8 threads/row, chunk cc (hi if cc<4 else lo)
    const int crow = tid >> 3;          // 0..31
    const int cc   = tid & 7;
    const __half* aptr = (cc < 4) ? Ah : Al;
    const int kchunk = (cc & 3) << 3;
    const bool doA = (cc < 4) || two;
    // B copy: 2 threads/row, 2 chunks each
    const int rb  = tid >> 1;           // 0..127
    const int cb0 = (tid & 1) * 2;

    auto copy_stage = [&](int kt) {
        const uint32_t base = S0 + (uint32_t)(kt % 3) * 24576;
        const int k0 = kt << 5;
        if (doA) {
#pragma unroll
            for (int i = 0; i < 4; ++i) {
                int row = crow + (i << 5);
                cp16(base + row * 128 + ((cc ^ (row & 7)) << 4),
                     aptr + (size_t)(m0 + row) * lda + k0 + kchunk);
            }
        }
#pragma unroll
        for (int j = 0; j < 2; ++j) {
            int c = cb0 + j;
            cp16(base + 16384 + rb * 64 + ((c ^ ((rb >> 1) & 3)) << 4),
                 B + (size_t)(n0 + rb) * ldb + k0 + c * 8);
        }
    };

    const int warp = tid >> 5, lane = tid & 31;
    const int wm = warp >> 1, wn = warp & 1;
    const int rselA = (lane & 7) + (((lane >> 3) & 1) << 3);
    const int chA   = (lane >> 4) & 1;
    const int rselB = (lane & 7) + (((lane >> 4) & 1) << 3);
    const int chB   = (lane >> 3) & 1;

    float acc[2][8][4];
#pragma unroll
    for (int a = 0; a < 2; ++a)
#pragma unroll
        for (int b = 0; b < 8; ++b)
#pragma unroll
            for (int c = 0; c < 4; ++c) acc[a][b][c] = 0.f;

    auto compute_tile = [&](int buf) {
        const uint32_t abase = S0 + (uint32_t)buf * 24576;
        const uint32_t bbase = abase + 16384;
#pragma unroll
        for (int ks = 0; ks < 2; ++ks) {
            uint32_t aH[2][4], aL[2][4];
            const int g = 2 * ks + chA;
#pragma unroll
            for (int mf = 0; mf < 2; ++mf) {
                int row = wm * 32 + mf * 16 + rselA;
                uint32_t off = abase + row * 128;
                ldsm_x4(aH[mf], off + ((g ^ (row & 7)) << 4));
                if (two) ldsm_x4(aL[mf], off + (((g + 4) ^ (row & 7)) << 4));
            }
            const int gb = 2 * ks + chB;
#pragma unroll
            for (int np = 0; np < 4; ++np) {
                uint32_t bh[4];
                int rowb = wn * 64 + np * 16 + rselB;
                ldsm_x4(bh, bbase + rowb * 64 + ((gb ^ ((rowb >> 1) & 3)) << 4));
#pragma unroll
                for (int mf = 0; mf < 2; ++mf) {
                    mma_f16(acc[mf][2 * np],     aH[mf], bh);
                    mma_f16(acc[mf][2 * np + 1], aH[mf], bh + 2);
                    if (two) {
                        mma_f16(acc[mf][2 * np],     aL[mf], bh);
                        mma_f16(acc[mf][2 * np + 1], aL[mf], bh + 2);
                    }
                }
            }
        }
    };

    // 3-stage ring, one barrier per k-tile
    copy_stage(0); cp_commit();
    if (nt > 1) { copy_stage(1); cp_commit(); }
    for (int kt = 0; kt < nt; ++kt) {
        if (kt + 1 < nt) cp_wait<1>(); else cp_wait<0>();
        __syncthreads();
        if (kt + 2 < nt) { copy_stage(kt + 2); cp_commit(); }
        compute_tile(kt % 3);
    }

#pragma unroll
    for (int mf = 0; mf < 2; ++mf) {
        int row = m0 + wm * 32 + mf * 16 + (lane >> 2);
#pragma unroll
        for (int nf = 0; nf < 8; ++nf) {
            int col = n0 + wn * 64 + nf * 8 + (lane & 3) * 2;
            float v0 = acc[mf][nf][0], v1 = acc[mf][nf][1];
            float v2 = acc[mf][nf][2], v3 = acc[mf][nf][3];
            if (BIAS) {
                float b0 = bias[col], b1 = bias[col + 1];
                v0 += b0; v1 += b1; v2 += b0; v3 += b1;
            }
            size_t o0 = (size_t)row * ldc + col;
            size_t o1 = (size_t)(row + 8) * ldc + col;
            if (WF32) {
                *(float2*)(C + o0) = make_float2(v0, v1);
                *(float2*)(C + o1) = make_float2(v2, v3);
            }
            if (WSPLIT) {
                __half h0 = __float2half_rn(v0), h1 = __float2half_rn(v1);
                __half h2 = __float2half_rn(v2), h3 = __float2half_rn(v3);
                *(uint32_t*)(Ch + o0) = packh(h0, h1);
                *(uint32_t*)(Ch + o1) = packh(h2, h3);
                if (col < loLim) {
                    *(uint32_t*)(Cl + o0) = packh(
                        __float2half_rn(v0 - __half2float(h0)),
                        __float2half_rn(v1 - __half2float(h1)));
                    *(uint32_t*)(Cl + o1) = packh(
                        __float2half_rn(v2 - __half2float(h2)),
                        __float2half_rn(v3 - __half2float(h3)));
                }
            }
        }
    }
}

// ---------------- fused flash attention (fp16, 2-term Q/P; K,V plain) ---------
__global__ __launch_bounds__(256) void flash_attn(
    const __half* __restrict__ qkvh, const __half* __restrict__ qkvl,
    __half* __restrict__ outh, __half* __restrict__ outl)
{
    const int qi = 15 - (int)blockIdx.x;
    const int bh = blockIdx.y;
    const int b = bh >> 4, h = bh & 15;
    const int q0 = qi * 128;
    const size_t base = (size_t)b * SEQ * 6144 + (size_t)h * 128;
    const __half* Qp[2] = {qkvh + base, qkvl + base};
    const __half* Kp = qkvh + base + 2048;
    const __half* Vp = qkvh + base + 4096;

    extern __shared__ char smem[];
    const uint32_t S0 = smem_u32(smem);
    const int tid = threadIdx.x, lane = tid & 31, warp = tid >> 5;

#pragma unroll
    for (int half = 0; half < 2; ++half) {
        const __half* src = Qp[half];
        const uint32_t qb = S0 + half * 32768;
#pragma unroll
        for (int i = 0; i < 8; ++i) {
            int idx = tid + i * 256;
            int row = idx >> 4, c = idx & 15, p = c >> 3, c8 = c & 7;
            cp16(qb + p * 16384 + row * 128 + ((c8 ^ (row & 7)) << 4),
                 src + (size_t)(q0 + row) * 6144 + p * 64 + c8 * 8);
        }
    }

    auto copy_kv = [&](int t) {
        const uint32_t sb = S0 + 65536 + (uint32_t)(t & 1) * 32768;
        const int kv0 = t * 64;
#pragma unroll
        for (int q = 0; q < 2; ++q) {
            const __half* src = q ? Vp : Kp;
#pragma unroll
            for (int i = 0; i < 4; ++i) {
                int idx = tid + i * 256;
                int row = idx >> 4, c = idx & 15, p = c >> 3, c8 = c & 7;
                cp16(sb + q * 16384 + p * 8192 + row * 128 + ((c8 ^ (row & 7)) << 4),
                     src + (size_t)(kv0 + row) * 6144 + p * 64 + c8 * 8);
            }
        }
    };

    const int rselA = (lane & 7) + (((lane >> 3) & 1) << 3);
    const int chA   = (lane >> 4) & 1;
    const int rselB = (lane & 7) + (((lane >> 4) & 1) << 3);
    const int chB   = (lane >> 3) & 1;
    const int qr = warp * 16;

    float m0 = -1e30f, m1 = -1e30f, l0 = 0.f, l1 = 0.f;
    float accO[16][4];
#pragma unroll
    for (int j = 0; j < 16; ++j)
#pragma unroll
        for (int c = 0; c < 4; ++c) accO[j][c] = 0.f;

    const int nt = 2 * qi + 2;
    copy_kv(0); cp_commit();
    if (nt > 1) { copy_kv(1); cp_commit(); }

    for (int t = 0; t < nt; ++t) {
        if (t + 1 < nt) cp_wait<1>(); else cp_wait<0>();
        __syncthreads();

        const uint32_t sb = S0 + 65536 + (uint32_t)(t & 1) * 32768;
        const uint32_t sK = sb, sV = sb + 16384;

        float accS[8][4];
#pragma unroll
        for (int j = 0; j < 8; ++j)
#pragma unroll
            for (int c = 0; c < 4; ++c) accS[j][c] = 0.f;

#pragma unroll
        for (int ks = 0; ks < 8; ++ks) {
            uint32_t aH[4], aL[4];
            {
                int row = qr + rselA;
                int g = ks * 2 + chA, p = g >> 3, c8 = g & 7;
                uint32_t off = (uint32_t)p * 16384 + row * 128 + ((c8 ^ (row & 7)) << 4);
                ldsm_x4(aH, S0 + off);
                ldsm_x4(aL, S0 + 32768 + off);
            }
#pragma unroll
            for (int n2 = 0; n2 < 4; ++n2) {
                uint32_t bH[4];
                int row = n2 * 16 + rselB;
                int g = ks * 2 + chB, p = g >> 3, c8 = g & 7;
                ldsm_x4(bH, sK + (uint32_t)p * 8192 + row * 128 + ((c8 ^ (row & 7)) << 4));
                mma_f16(accS[2 * n2],     aH, bH);
                mma_f16(accS[2 * n2 + 1], aH, bH + 2);
                mma_f16(accS[2 * n2],     aL, bH);
                mma_f16(accS[2 * n2 + 1], aL, bH + 2);
            }
        }

        const float isd = 0.08838834764831845f;
        const int kv0 = t * 64;
        const int grow0 = q0 + qr + (lane >> 2);
        const int grow1 = grow0 + 8;
        const bool masked = (t >= 2 * qi);
#pragma unroll
        for (int nf = 0; nf < 8; ++nf) {
#pragma unroll
            for (int c = 0; c < 4; ++c) accS[nf][c] *= isd;
            if (masked) {
                int col = kv0 + nf * 8 + (lane & 3) * 2;
                if (col     > grow0) accS[nf][0] = -1e30f;
                if (col + 1 > grow0) accS[nf][1] = -1e30f;
                if (col     > grow1) accS[nf][2] = -1e30f;
                if (col + 1 > grow1) accS[nf][3] = -1e30f;
            }
        }
        float mx0 = -1e30f, mx1 = -1e30f;
#pragma unroll
        for (int nf = 0; nf < 8; ++nf) {
            mx0 = fmaxf(mx0, fmaxf(accS[nf][0], accS[nf][1]));
            mx1 = fmaxf(mx1, fmaxf(accS[nf][2], accS[nf][3]));
        }
        mx0 = fmaxf(mx0, __shfl_xor_sync(0xffffffffu, mx0, 1));
        mx0 = fmaxf(mx0, __shfl_xor_sync(0xffffffffu, mx0, 2));
        mx1 = fmaxf(mx1, __shfl_xor_sync(0xffffffffu, mx1, 1));
        mx1 = fmaxf(mx1, __shfl_xor_sync(0xffffffffu, mx1, 2));
        const float nm0 = fmaxf(m0, mx0), nm1 = fmaxf(m1, mx1);
        const float cr0 = __expf(m0 - nm0), cr1 = __expf(m1 - nm1);
        m0 = nm0; m1 = nm1;

        float rs0 = 0.f, rs1 = 0.f;
        uint32_t phr[8], phr8[8], plr[8], plr8[8];
#pragma unroll
        for (int nf = 0; nf < 8; ++nf) {
            float p0 = __expf(accS[nf][0] - nm0), p1 = __expf(accS[nf][1] - nm0);
            float p2 = __expf(accS[nf][2] - nm1), p3 = __expf(accS[nf][3] - nm1);
            rs0 += p0 + p1; rs1 += p2 + p3;
            __half h0 = __float2half_rn(p0), h1 = __float2half_rn(p1);
            __half h2 = __float2half_rn(p2), h3 = __float2half_rn(p3);
            phr[nf]  = packh(h0, h1);
            phr8[nf] = packh(h2, h3);
            plr[nf]  = packh(__float2half_rn(p0 - __half2float(h0)),
                             __float2half_rn(p1 - __half2float(h1)));
            plr8[nf] = packh(__float2half_rn(p2 - __half2float(h2)),
                             __float2half_rn(p3 - __half2float(h3)));
        }
        rs0 += __shfl_xor_sync(0xffffffffu, rs0, 1);
        rs0 += __shfl_xor_sync(0xffffffffu, rs0, 2);
        rs1 += __shfl_xor_sync(0xffffffffu, rs1, 1);
        rs1 += __shfl_xor_sync(0xffffffffu, rs1, 2);
        l0 = l0 * cr0 + rs0;
        l1 = l1 * cr1 + rs1;
#pragma unroll
        for (int j = 0; j < 16; ++j) {
            accO[j][0] *= cr0; accO[j][1] *= cr0;
            accO[j][2] *= cr1; accO[j][3] *= cr1;
        }

#pragma unroll
        for (int ks = 0; ks < 4; ++ks) {
            uint32_t Aph[4] = {phr[2 * ks], phr8[2 * ks], phr[2 * ks + 1], phr8[2 * ks + 1]};
            uint32_t Apl[4] = {plr[2 * ks], plr8[2 * ks], plr[2 * ks + 1], plr8[2 * ks + 1]};
            const int rowv = ks * 16 + (lane & 15);
#pragma unroll
            for (int jj = 0; jj < 4; ++jj) {
                uint32_t vh0[4], vh1[4];
                {
                    int cv = 4 * jj + (lane >> 4), p = cv >> 3, c8 = cv & 7;
                    ldsm_x4_t(vh0, sV + (uint32_t)p * 8192 + rowv * 128 + ((c8 ^ (rowv & 7)) << 4));
                }
                {
                    int cv = 4 * jj + 2 + (lane >> 4), p = cv >> 3, c8 = cv & 7;
                    ldsm_x4_t(vh1, sV + (uint32_t)p * 8192 + rowv * 128 + ((c8 ^ (rowv & 7)) << 4));
                }
                float* a0 = accO[4 * jj];
                float* a1 = accO[4 * jj + 1];
                float* a2 = accO[4 * jj + 2];
                float* a3 = accO[4 * jj + 3];
                mma_f16(a0, Aph, vh0); mma_f16(a1, Aph, vh0 + 2);
                mma_f16(a2, Aph, vh1); mma_f16(a3, Aph, vh1 + 2);
                mma_f16(a0, Apl, vh0); mma_f16(a1, Apl, vh0 + 2);
                mma_f16(a2, Apl, vh1); mma_f16(a3, Apl, vh1 + 2);
            }
        }

        __syncthreads();
        if (t + 2 < nt) { copy_kv(t + 2); cp_commit(); }
    }

    const float i0 = 1.f / l0, i1 = 1.f / l1;
    const size_t obase = (size_t)b * SEQ * N_EMBD + (size_t)h * 128;
    const int row0 = q0 + qr + (lane >> 2);
#pragma unroll
    for (int j = 0; j < 16; ++j) {
        int d = j * 8 + (lane & 3) * 2;
        size_t o0 = obase + (size_t)row0 * N_EMBD + d;
        size_t o1 = obase + (size_t)(row0 + 8) * N_EMBD + d;
        float v0 = accO[j][0] * i0, v1 = accO[j][1] * i0;
        float v2 = accO[j][2] * i1, v3 = accO[j][3] * i1;
        __half h0 = __float2half_rn(v0), h1 = __float2half_rn(v1);
        __half h2 = __float2half_rn(v2), h3 = __float2half_rn(v3);
        *(uint32_t*)(outh + o0) = packh(h0, h1);
        *(uint32_t*)(outh + o1) = packh(h2, h3);
        *(uint32_t*)(outl + o0) = packh(__float2half_rn(v0 - __half2float(h0)),
                                        __float2half_rn(v1 - __half2float(h1)));
        *(uint32_t*)(outl + o1) = packh(__float2half_rn(v2 - __half2float(h2)),
                                        __float2half_rn(v3 - __half2float(h3)));
    }
}

// ---------------- converts ----------------------------------------------------
__global__ __launch_bounds__(256) void convert_split(
    const float* __restrict__ in, __half* __restrict__ oh,
    __half* __restrict__ ol, int n)
{
    for (int i = blockIdx.x * 256 + threadIdx.x; i < n; i += gridDim.x * 256) {
        float v = in[i];
        __half h = __float2half_rn(v);
        oh[i] = h;
        ol[i] = __float2half_rn(v - __half2float(h));
    }
}
__global__ __launch_bounds__(256) void transpose_w(
    const float* __restrict__ in, __half* __restrict__ out, int ld_in, int ld_out)
{
    __shared__ float t[32][33];
    const int c0 = blockIdx.x * 32, r0 = blockIdx.y * 32;
    const int tx = threadIdx.x, ty = threadIdx.y;
#pragma unroll
    for (int j = 0; j < 32; j += 8)
        t[ty + j][tx] = in[(size_t)(r0 + ty + j) * ld_in + c0 + tx];
    __syncthreads();
#pragma unroll
    for (int j = 0; j < 32; j += 8)
        out[(size_t)(c0 + ty + j) * ld_out + r0 + tx] = __float2half_rn(t[tx][ty + j]);
}

// ---------------- launch ------------------------------------------------------
extern "C" void kernel_launch(void* const* d_in, const int* in_sizes, int n_in,
                              void* d_out, int out_size)
{
    const float* x     = (const float*)d_in[0];
    const float* Wqkv  = (const float*)d_in[1];
    const float* bqkv  = (const float*)d_in[2];
    const float* Wproj = (const float*)d_in[3];
    const float* bproj = (const float*)d_in[4];
    float* out = (float*)d_out;

    __half *x_h, *x_l, *wq, *wp, *qkv_h, *qkv_l, *at_h, *at_l;
    cudaGetSymbolAddress((void**)&x_h, g_x_h);
    cudaGetSymbolAddress((void**)&x_l, g_x_l);
    cudaGetSymbolAddress((void**)&wq, g_wqkvT);
    cudaGetSymbolAddress((void**)&wp, g_wprojT);
    cudaGetSymbolAddress((void**)&qkv_h, g_qkv_h);
    cudaGetSymbolAddress((void**)&qkv_l, g_qkv_l);
    cudaGetSymbolAddress((void**)&at_h, g_attn_h);
    cudaGetSymbolAddress((void**)&at_l, g_attn_l);

    const int GEMM_SMEM = 73728;     // 3 stages x 24KB; 2 CTAs/SM
    const int FLASH_SMEM = 131072;   // Q 64KB + 2 stages x 32KB
    cudaFuncSetAttribute(gemm_f16x2<true, false, true>,
                         cudaFuncAttributeMaxDynamicSharedMemorySize, GEMM_SMEM);
    cudaFuncSetAttribute(gemm_f16x2<true, true, false>,
                         cudaFuncAttributeMaxDynamicSharedMemorySize, GEMM_SMEM);
    cudaFuncSetAttribute(flash_attn,
                         cudaFuncAttributeMaxDynamicSharedMemorySize, FLASH_SMEM);

    const int M = BATCH * SEQ, E = N_EMBD, E3 = 3 * N_EMBD;

    convert_split<<<4096, 256>>>(x, x_h, x_l, M * E);
    transpose_w<<<dim3(E3 / 32, E / 32), dim3(32, 8)>>>(Wqkv, wq, E3, E);
    transpose_w<<<dim3(E / 32, E / 32), dim3(32, 8)>>>(Wproj, wp, E, E);

    // 1) qkv = x @ Wqkv + b : Q cols 2-term + lo output; K/V cols 1-term, hi only
    gemm_f16x2<true, false, true><<<dim3(E3 / BN, M / BM), 256, GEMM_SMEM>>>(
        x_h, x_l, wq, bqkv, nullptr, qkv_h, qkv_l, E, E, E, E3, 2048);

    // 2-4) fused flash attention -> attn hi/lo
    flash_attn<<<dim3(SEQ / 128, BATCH * N_HEAD), 256, FLASH_SMEM>>>(
        qkv_h, qkv_l, at_h, at_l);

    // 5) out = attn @ Wproj + b  (2-term everywhere)
    gemm_f16x2<true, true, false><<<dim3(E / BN, M / BM), 256, GEMM_SMEM>>>(
        at_h, at_l, wp, bproj, out, nullptr, nullptr, E, E, E, E, 2048);
}

// round 10
// speedup vs baseline: 7.8614x; 1.2090x over previous
#include <cuda_runtime.h>
#include <cuda_fp16.h>
#include <cstdint>

#define N_EMBD 2048
#define N_HEAD 16
#define HEAD_DIM 128
#define BATCH 2
#define SEQ 2048

#define BM 128
#define BN 128

// ---------------- scratch ----------------------------------------------------
__device__ __half g_x_h[(size_t)BATCH * SEQ * N_EMBD];
__device__ __half g_wqkvT[(size_t)3 * N_EMBD * N_EMBD];
__device__ __half g_wprojT[(size_t)N_EMBD * N_EMBD];
__device__ __half g_qkv_h[(size_t)BATCH * SEQ * 3 * N_EMBD];
__device__ __half g_attn_h[(size_t)BATCH * SEQ * N_EMBD];
__device__ __half g_attn_l[(size_t)BATCH * SEQ * N_EMBD];

// ---------------- PTX helpers -------------------------------------------------
__device__ __forceinline__ uint32_t smem_u32(const void* p) {
    return (uint32_t)__cvta_generic_to_shared(p);
}
__device__ __forceinline__ void ldsm_x4(uint32_t* r, uint32_t addr) {
    asm volatile("ldmatrix.sync.aligned.m8n8.x4.shared.b16 {%0,%1,%2,%3}, [%4];"
                 : "=r"(r[0]), "=r"(r[1]), "=r"(r[2]), "=r"(r[3]) : "r"(addr));
}
__device__ __forceinline__ void ldsm_x4_t(uint32_t* r, uint32_t addr) {
    asm volatile("ldmatrix.sync.aligned.m8n8.x4.trans.shared.b16 {%0,%1,%2,%3}, [%4];"
                 : "=r"(r[0]), "=r"(r[1]), "=r"(r[2]), "=r"(r[3]) : "r"(addr));
}
__device__ __forceinline__ void mma_f16(float* d, const uint32_t* a, const uint32_t* b) {
    asm volatile(
        "mma.sync.aligned.m16n8k16.row.col.f32.f16.f16.f32 "
        "{%0,%1,%2,%3},{%4,%5,%6,%7},{%8,%9},{%0,%1,%2,%3};"
        : "+f"(d[0]), "+f"(d[1]), "+f"(d[2]), "+f"(d[3])
        : "r"(a[0]), "r"(a[1]), "r"(a[2]), "r"(a[3]), "r"(b[0]), "r"(b[1]));
}
__device__ __forceinline__ void cp16(uint32_t dst, const void* src) {
    asm volatile("cp.async.cg.shared.global [%0], [%1], 16;" :: "r"(dst), "l"(src));
}
__device__ __forceinline__ void cp_commit() {
    asm volatile("cp.async.commit_group;" ::: "memory");
}
template <int W> __device__ __forceinline__ void cp_wait() {
    asm volatile("cp.async.wait_group %0;" :: "n"(W) : "memory");
}
__device__ __forceinline__ uint32_t packh(__half a, __half b) {
    __half2 t; t.x = a; t.y = b;
    uint32_t u; *(__half2*)&u = t; return u;
}

// ---------------- fp16 GEMM, BK=32, 3-stage, 1 sync/tile, 2 CTAs/SM -----------
// TWO=false: A plain fp16 (64B smem rows), 1 term.
// TWO=true : A split hi/lo fp16 (128B smem rows: chunks 0-3 hi, 4-7 lo), 2 terms.
// B always plain fp16, 64B smem rows.
template <bool TWO, bool BIAS, bool WF32, bool WSPLIT>
__global__ __launch_bounds__(256, 2) void gemm_f16(
    const __half* __restrict__ Ah, const __half* __restrict__ Al,
    const __half* __restrict__ B,
    const float* __restrict__ bias,
    float* __restrict__ C, __half* __restrict__ Ch,
    int K, int lda, int ldb, int ldc)
{
    extern __shared__ char smem[];
    const int tid = threadIdx.x;
    const int m0 = blockIdx.y * BM, n0 = blockIdx.x * BN;
    const int nt = K >> 5;

    constexpr uint32_t STAGE = TWO ? 24576u : 16384u;
    constexpr uint32_t BOFF  = TWO ? 16384u : 8192u;
    const uint32_t S0 = smem_u32(smem);

    // ---- copy mappings ----
    // 2-term A: 8 threads/row (128B rows); plain A & B: 2 threads/row (64B rows)
    const int crow = tid >> 3;          // 0..31   (TWO A path)
    const int cc   = tid & 7;
    const __half* aptr2 = (cc < 4) ? Ah : Al;
    const int kchunk = (cc & 3) << 3;
    const int rb  = tid >> 1;           // 0..127  (64B-row path)
    const int cb0 = (tid & 1) * 2;

    auto copy_stage = [&](int kt) {
        const uint32_t base = S0 + (uint32_t)(kt % 3) * STAGE;
        const int k0 = kt << 5;
        if (TWO) {
#pragma unroll
            for (int i = 0; i < 4; ++i) {
                int row = crow + (i << 5);
                cp16(base + row * 128 + ((cc ^ (row & 7)) << 4),
                     aptr2 + (size_t)(m0 + row) * lda + k0 + kchunk);
            }
        } else {
#pragma unroll
            for (int j = 0; j < 2; ++j) {
                int c = cb0 + j;
                cp16(base + rb * 64 + ((c ^ ((rb >> 1) & 3)) << 4),
                     Ah + (size_t)(m0 + rb) * lda + k0 + c * 8);
            }
        }
#pragma unroll
        for (int j = 0; j < 2; ++j) {
            int c = cb0 + j;
            cp16(base + BOFF + rb * 64 + ((c ^ ((rb >> 1) & 3)) << 4),
                 B + (size_t)(n0 + rb) * ldb + k0 + c * 8);
        }
    };

    const int warp = tid >> 5, lane = tid & 31;
    const int wm = warp >> 1, wn = warp & 1;
    const int rselA = (lane & 7) + (((lane >> 3) & 1) << 3);
    const int chA   = (lane >> 4) & 1;
    const int rselB = (lane & 7) + (((lane >> 4) & 1) << 3);
    const int chB   = (lane >> 3) & 1;

    float acc[2][8][4];
#pragma unroll
    for (int a = 0; a < 2; ++a)
#pragma unroll
        for (int b = 0; b < 8; ++b)
#pragma unroll
            for (int c = 0; c < 4; ++c) acc[a][b][c] = 0.f;

    auto compute_tile = [&](int buf) {
        const uint32_t abase = S0 + (uint32_t)buf * STAGE;
        const uint32_t bbase = abase + BOFF;
#pragma unroll
        for (int ks = 0; ks < 2; ++ks) {
            uint32_t aH[2][4], aL[2][4];
            const int g = 2 * ks + chA;
#pragma unroll
            for (int mf = 0; mf < 2; ++mf) {
                int row = wm * 32 + mf * 16 + rselA;
                if (TWO) {
                    uint32_t off = abase + row * 128;
                    ldsm_x4(aH[mf], off + ((g ^ (row & 7)) << 4));
                    ldsm_x4(aL[mf], off + (((g + 4) ^ (row & 7)) << 4));
                } else {
                    ldsm_x4(aH[mf], abase + row * 64 + ((g ^ ((row >> 1) & 3)) << 4));
                }
            }
            const int gb = 2 * ks + chB;
#pragma unroll
            for (int np = 0; np < 4; ++np) {
                uint32_t bh[4];
                int rowb = wn * 64 + np * 16 + rselB;
                ldsm_x4(bh, bbase + rowb * 64 + ((gb ^ ((rowb >> 1) & 3)) << 4));
#pragma unroll
                for (int mf = 0; mf < 2; ++mf) {
                    mma_f16(acc[mf][2 * np],     aH[mf], bh);
                    mma_f16(acc[mf][2 * np + 1], aH[mf], bh + 2);
                    if (TWO) {
                        mma_f16(acc[mf][2 * np],     aL[mf], bh);
                        mma_f16(acc[mf][2 * np + 1], aL[mf], bh + 2);
                    }
                }
            }
        }
    };

    copy_stage(0); cp_commit();
    if (nt > 1) { copy_stage(1); cp_commit(); }
    for (int kt = 0; kt < nt; ++kt) {
        if (kt + 1 < nt) cp_wait<1>(); else cp_wait<0>();
        __syncthreads();
        if (kt + 2 < nt) { copy_stage(kt + 2); cp_commit(); }
        compute_tile(kt % 3);
    }

#pragma unroll
    for (int mf = 0; mf < 2; ++mf) {
        int row = m0 + wm * 32 + mf * 16 + (lane >> 2);
#pragma unroll
        for (int nf = 0; nf < 8; ++nf) {
            int col = n0 + wn * 64 + nf * 8 + (lane & 3) * 2;
            float v0 = acc[mf][nf][0], v1 = acc[mf][nf][1];
            float v2 = acc[mf][nf][2], v3 = acc[mf][nf][3];
            if (BIAS) {
                float b0 = bias[col], b1 = bias[col + 1];
                v0 += b0; v1 += b1; v2 += b0; v3 += b1;
            }
            size_t o0 = (size_t)row * ldc + col;
            size_t o1 = (size_t)(row + 8) * ldc + col;
            if (WF32) {
                *(float2*)(C + o0) = make_float2(v0, v1);
                *(float2*)(C + o1) = make_float2(v2, v3);
            }
            if (WSPLIT) {
                *(uint32_t*)(Ch + o0) = packh(__float2half_rn(v0), __float2half_rn(v1));
                *(uint32_t*)(Ch + o1) = packh(__float2half_rn(v2), __float2half_rn(v3));
            }
        }
    }
}

// ---------------- fused flash attention (Q,K,V plain fp16; P 2-term) ----------
__global__ __launch_bounds__(256) void flash_attn(
    const __half* __restrict__ qkvh,
    __half* __restrict__ outh, __half* __restrict__ outl)
{
    const int qi = 15 - (int)blockIdx.x;
    const int bh = blockIdx.y;
    const int b = bh >> 4, h = bh & 15;
    const int q0 = qi * 128;
    const size_t base = (size_t)b * SEQ * 6144 + (size_t)h * 128;
    const __half* Qp = qkvh + base;
    const __half* Kp = qkvh + base + 2048;
    const __half* Vp = qkvh + base + 4096;

    extern __shared__ char smem[];
    const uint32_t S0 = smem_u32(smem);
    const int tid = threadIdx.x, lane = tid & 31, warp = tid >> 5;

    // Q: 2 p-planes x 128 rows x 128B = 32KB at S0
#pragma unroll
    for (int i = 0; i < 8; ++i) {
        int idx = tid + i * 256;
        int row = idx >> 4, c = idx & 15, p = c >> 3, c8 = c & 7;
        cp16(S0 + p * 16384 + row * 128 + ((c8 ^ (row & 7)) << 4),
             Qp + (size_t)(q0 + row) * 6144 + p * 64 + c8 * 8);
    }

    // KV stages: K[0,16K) V[16K,32K); 2 stages at S0+32K
    auto copy_kv = [&](int t) {
        const uint32_t sb = S0 + 32768 + (uint32_t)(t & 1) * 32768;
        const int kv0 = t * 64;
#pragma unroll
        for (int q = 0; q < 2; ++q) {
            const __half* src = q ? Vp : Kp;
#pragma unroll
            for (int i = 0; i < 4; ++i) {
                int idx = tid + i * 256;
                int row = idx >> 4, c = idx & 15, p = c >> 3, c8 = c & 7;
                cp16(sb + q * 16384 + p * 8192 + row * 128 + ((c8 ^ (row & 7)) << 4),
                     src + (size_t)(kv0 + row) * 6144 + p * 64 + c8 * 8);
            }
        }
    };

    const int rselA = (lane & 7) + (((lane >> 3) & 1) << 3);
    const int chA   = (lane >> 4) & 1;
    const int rselB = (lane & 7) + (((lane >> 4) & 1) << 3);
    const int chB   = (lane >> 3) & 1;
    const int qr = warp * 16;

    float m0 = -1e30f, m1 = -1e30f, l0 = 0.f, l1 = 0.f;
    float accO[16][4];
#pragma unroll
    for (int j = 0; j < 16; ++j)
#pragma unroll
        for (int c = 0; c < 4; ++c) accO[j][c] = 0.f;

    const int nt = 2 * qi + 2;
    copy_kv(0); cp_commit();
    if (nt > 1) { copy_kv(1); cp_commit(); }

    for (int t = 0; t < nt; ++t) {
        if (t + 1 < nt) cp_wait<1>(); else cp_wait<0>();
        __syncthreads();

        const uint32_t sb = S0 + 32768 + (uint32_t)(t & 1) * 32768;
        const uint32_t sK = sb, sV = sb + 16384;

        float accS[8][4];
#pragma unroll
        for (int j = 0; j < 8; ++j)
#pragma unroll
            for (int c = 0; c < 4; ++c) accS[j][c] = 0.f;

#pragma unroll
        for (int ks = 0; ks < 8; ++ks) {
            uint32_t aH[4];
            {
                int row = qr + rselA;
                int g = ks * 2 + chA, p = g >> 3, c8 = g & 7;
                ldsm_x4(aH, S0 + (uint32_t)p * 16384 + row * 128 + ((c8 ^ (row & 7)) << 4));
            }
#pragma unroll
            for (int n2 = 0; n2 < 4; ++n2) {
                uint32_t bH[4];
                int row = n2 * 16 + rselB;
                int g = ks * 2 + chB, p = g >> 3, c8 = g & 7;
                ldsm_x4(bH, sK + (uint32_t)p * 8192 + row * 128 + ((c8 ^ (row & 7)) << 4));
                mma_f16(accS[2 * n2],     aH, bH);
                mma_f16(accS[2 * n2 + 1], aH, bH + 2);
            }
        }

        const float isd = 0.08838834764831845f;
        const int kv0 = t * 64;
        const int grow0 = q0 + qr + (lane >> 2);
        const int grow1 = grow0 + 8;
        const bool masked = (t >= 2 * qi);
#pragma unroll
        for (int nf = 0; nf < 8; ++nf) {
#pragma unroll
            for (int c = 0; c < 4; ++c) accS[nf][c] *= isd;
            if (masked) {
                int col = kv0 + nf * 8 + (lane & 3) * 2;
                if (col     > grow0) accS[nf][0] = -1e30f;
                if (col + 1 > grow0) accS[nf][1] = -1e30f;
                if (col     > grow1) accS[nf][2] = -1e30f;
                if (col + 1 > grow1) accS[nf][3] = -1e30f;
            }
        }
        float mx0 = -1e30f, mx1 = -1e30f;
#pragma unroll
        for (int nf = 0; nf < 8; ++nf) {
            mx0 = fmaxf(mx0, fmaxf(accS[nf][0], accS[nf][1]));
            mx1 = fmaxf(mx1, fmaxf(accS[nf][2], accS[nf][3]));
        }
        mx0 = fmaxf(mx0, __shfl_xor_sync(0xffffffffu, mx0, 1));
        mx0 = fmaxf(mx0, __shfl_xor_sync(0xffffffffu, mx0, 2));
        mx1 = fmaxf(mx1, __shfl_xor_sync(0xffffffffu, mx1, 1));
        mx1 = fmaxf(mx1, __shfl_xor_sync(0xffffffffu, mx1, 2));
        const float nm0 = fmaxf(m0, mx0), nm1 = fmaxf(m1, mx1);
        const float cr0 = __expf(m0 - nm0), cr1 = __expf(m1 - nm1);
        m0 = nm0; m1 = nm1;

        float rs0 = 0.f, rs1 = 0.f;
        uint32_t phr[8], phr8[8], plr[8], plr8[8];
#pragma unroll
        for (int nf = 0; nf < 8; ++nf) {
            float p0 = __expf(accS[nf][0] - nm0), p1 = __expf(accS[nf][1] - nm0);
            float p2 = __expf(accS[nf][2] - nm1), p3 = __expf(accS[nf][3] - nm1);
            rs0 += p0 + p1; rs1 += p2 + p3;
            __half h0 = __float2half_rn(p0), h1 = __float2half_rn(p1);
            __half h2 = __float2half_rn(p2), h3 = __float2half_rn(p3);
            phr[nf]  = packh(h0, h1);
            phr8[nf] = packh(h2, h3);
            plr[nf]  = packh(__float2half_rn(p0 - __half2float(h0)),
                             __float2half_rn(p1 - __half2float(h1)));
            plr8[nf] = packh(__float2half_rn(p2 - __half2float(h2)),
                             __float2half_rn(p3 - __half2float(h3)));
        }
        rs0 += __shfl_xor_sync(0xffffffffu, rs0, 1);
        rs0 += __shfl_xor_sync(0xffffffffu, rs0, 2);
        rs1 += __shfl_xor_sync(0xffffffffu, rs1, 1);
        rs1 += __shfl_xor_sync(0xffffffffu, rs1, 2);
        l0 = l0 * cr0 + rs0;
        l1 = l1 * cr1 + rs1;
#pragma unroll
        for (int j = 0; j < 16; ++j) {
            accO[j][0] *= cr0; accO[j][1] *= cr0;
            accO[j][2] *= cr1; accO[j][3] *= cr1;
        }

        // O += P V  (P 2-term, V plain)
#pragma unroll
        for (int ks = 0; ks < 4; ++ks) {
            uint32_t Aph[4] = {phr[2 * ks], phr8[2 * ks], phr[2 * ks + 1], phr8[2 * ks + 1]};
            uint32_t Apl[4] = {plr[2 * ks], plr8[2 * ks], plr[2 * ks + 1], plr8[2 * ks + 1]};
            const int rowv = ks * 16 + (lane & 15);
#pragma unroll
            for (int jj = 0; jj < 4; ++jj) {
                uint32_t vh0[4], vh1[4];
                {
                    int cv = 4 * jj + (lane >> 4), p = cv >> 3, c8 = cv & 7;
                    ldsm_x4_t(vh0, sV + (uint32_t)p * 8192 + rowv * 128 + ((c8 ^ (rowv & 7)) << 4));
                }
                {
                    int cv = 4 * jj + 2 + (lane >> 4), p = cv >> 3, c8 = cv & 7;
                    ldsm_x4_t(vh1, sV + (uint32_t)p * 8192 + rowv * 128 + ((c8 ^ (rowv & 7)) << 4));
                }
                float* a0 = accO[4 * jj];
                float* a1 = accO[4 * jj + 1];
                float* a2 = accO[4 * jj + 2];
                float* a3 = accO[4 * jj + 3];
                mma_f16(a0, Aph, vh0); mma_f16(a1, Aph, vh0 + 2);
                mma_f16(a2, Aph, vh1); mma_f16(a3, Aph, vh1 + 2);
                mma_f16(a0, Apl, vh0); mma_f16(a1, Apl, vh0 + 2);
                mma_f16(a2, Apl, vh1); mma_f16(a3, Apl, vh1 + 2);
            }
        }

        __syncthreads();
        if (t + 2 < nt) { copy_kv(t + 2); cp_commit(); }
    }

    const float i0 = 1.f / l0, i1 = 1.f / l1;
    const size_t obase = (size_t)b * SEQ * N_EMBD + (size_t)h * 128;
    const int row0 = q0 + qr + (lane >> 2);
#pragma unroll
    for (int j = 0; j < 16; ++j) {
        int d = j * 8 + (lane & 3) * 2;
        size_t o0 = obase + (size_t)row0 * N_EMBD + d;
        size_t o1 = obase + (size_t)(row0 + 8) * N_EMBD + d;
        float v0 = accO[j][0] * i0, v1 = accO[j][1] * i0;
        float v2 = accO[j][2] * i1, v3 = accO[j][3] * i1;
        __half h0 = __float2half_rn(v0), h1 = __float2half_rn(v1);
        __half h2 = __float2half_rn(v2), h3 = __float2half_rn(v3);
        *(uint32_t*)(outh + o0) = packh(h0, h1);
        *(uint32_t*)(outh + o1) = packh(h2, h3);
        *(uint32_t*)(outl + o0) = packh(__float2half_rn(v0 - __half2float(h0)),
                                        __float2half_rn(v1 - __half2float(h1)));
        *(uint32_t*)(outl + o1) = packh(__float2half_rn(v2 - __half2float(h2)),
                                        __float2half_rn(v3 - __half2float(h3)));
    }
}

// ---------------- converts ----------------------------------------------------
__global__ __launch_bounds__(256) void convert_plain(
    const float* __restrict__ in, __half* __restrict__ oh, int n)
{
    for (int i = blockIdx.x * 256 + threadIdx.x; i < n; i += gridDim.x * 256)
        oh[i] = __float2half_rn(in[i]);
}
__global__ __launch_bounds__(256) void transpose_w(
    const float* __restrict__ in, __half* __restrict__ out, int ld_in, int ld_out)
{
    __shared__ float t[32][33];
    const int c0 = blockIdx.x * 32, r0 = blockIdx.y * 32;
    const int tx = threadIdx.x, ty = threadIdx.y;
#pragma unroll
    for (int j = 0; j < 32; j += 8)
        t[ty + j][tx] = in[(size_t)(r0 + ty + j) * ld_in + c0 + tx];
    __syncthreads();
#pragma unroll
    for (int j = 0; j < 32; j += 8)
        out[(size_t)(c0 + ty + j) * ld_out + r0 + tx] = __float2half_rn(t[tx][ty + j]);
}

// ---------------- launch ------------------------------------------------------
extern "C" void kernel_launch(void* const* d_in, const int* in_sizes, int n_in,
                              void* d_out, int out_size)
{
    const float* x     = (const float*)d_in[0];
    const float* Wqkv  = (const float*)d_in[1];
    const float* bqkv  = (const float*)d_in[2];
    const float* Wproj = (const float*)d_in[3];
    const float* bproj = (const float*)d_in[4];
    float* out = (float*)d_out;

    __half *x_h, *wq, *wp, *qkv_h, *at_h, *at_l;
    cudaGetSymbolAddress((void**)&x_h, g_x_h);
    cudaGetSymbolAddress((void**)&wq, g_wqkvT);
    cudaGetSymbolAddress((void**)&wp, g_wprojT);
    cudaGetSymbolAddress((void**)&qkv_h, g_qkv_h);
    cudaGetSymbolAddress((void**)&at_h, g_attn_h);
    cudaGetSymbolAddress((void**)&at_l, g_attn_l);

    const int GEMM1_SMEM = 49152;    // 3 stages x 16KB (plain A)
    const int GEMM2_SMEM = 73728;    // 3 stages x 24KB (split A)
    const int FLASH_SMEM = 98304;    // Q 32KB + 2 stages x 32KB
    cudaFuncSetAttribute(gemm_f16<false, true, false, true>,
                         cudaFuncAttributeMaxDynamicSharedMemorySize, GEMM1_SMEM);
    cudaFuncSetAttribute(gemm_f16<true, true, true, false>,
                         cudaFuncAttributeMaxDynamicSharedMemorySize, GEMM2_SMEM);
    cudaFuncSetAttribute(flash_attn,
                         cudaFuncAttributeMaxDynamicSharedMemorySize, FLASH_SMEM);

    const int M = BATCH * SEQ, E = N_EMBD, E3 = 3 * N_EMBD;

    convert_plain<<<4096, 256>>>(x, x_h, M * E);
    transpose_w<<<dim3(E3 / 32, E / 32), dim3(32, 8)>>>(Wqkv, wq, E3, E);
    transpose_w<<<dim3(E / 32, E / 32), dim3(32, 8)>>>(Wproj, wp, E, E);

    // 1) qkv = x @ Wqkv + b  (plain fp16, 1-term, hi out)
    gemm_f16<false, true, false, true><<<dim3(E3 / BN, M / BM), 256, GEMM1_SMEM>>>(
        x_h, nullptr, wq, bqkv, nullptr, qkv_h, E, E, E, E3);

    // 2-4) fused flash attention -> attn hi/lo
    flash_attn<<<dim3(SEQ / 128, BATCH * N_HEAD), 256, FLASH_SMEM>>>(
        qkv_h, at_h, at_l);

    // 5) out = attn @ Wproj + b  (2-term, fp32 out)
    gemm_f16<true, true, true, false><<<dim3(E / BN, M / BM), 256, GEMM2_SMEM>>>(
        at_h, at_l, wp, bproj, out, nullptr, E, E, E, E);
}

// round 11
// speedup vs baseline: 8.1462x; 1.0362x over previous
#include <cuda_runtime.h>
#include <cuda_fp16.h>
#include <cstdint>

#define N_EMBD 2048
#define N_HEAD 16
#define HEAD_DIM 128
#define BATCH 2
#define SEQ 2048

#define BM 128
#define BN 128

// ---------------- scratch ----------------------------------------------------
__device__ __half g_x_h[(size_t)BATCH * SEQ * N_EMBD];
__device__ __half g_wqkvT[(size_t)3 * N_EMBD * N_EMBD];
__device__ __half g_wprojT[(size_t)N_EMBD * N_EMBD];
__device__ __half g_qkv_h[(size_t)BATCH * SEQ * 3 * N_EMBD];
__device__ __half g_attn_h[(size_t)BATCH * SEQ * N_EMBD];
__device__ __half g_attn_l[(size_t)BATCH * SEQ * N_EMBD];

// ---------------- PTX helpers -------------------------------------------------
__device__ __forceinline__ uint32_t smem_u32(const void* p) {
    return (uint32_t)__cvta_generic_to_shared(p);
}
__device__ __forceinline__ void ldsm_x4(uint32_t* r, uint32_t addr) {
    asm volatile("ldmatrix.sync.aligned.m8n8.x4.shared.b16 {%0,%1,%2,%3}, [%4];"
                 : "=r"(r[0]), "=r"(r[1]), "=r"(r[2]), "=r"(r[3]) : "r"(addr));
}
__device__ __forceinline__ void ldsm_x4_t(uint32_t* r, uint32_t addr) {
    asm volatile("ldmatrix.sync.aligned.m8n8.x4.trans.shared.b16 {%0,%1,%2,%3}, [%4];"
                 : "=r"(r[0]), "=r"(r[1]), "=r"(r[2]), "=r"(r[3]) : "r"(addr));
}
__device__ __forceinline__ void mma_f16(float* d, const uint32_t* a, const uint32_t* b) {
    asm volatile(
        "mma.sync.aligned.m16n8k16.row.col.f32.f16.f16.f32 "
        "{%0,%1,%2,%3},{%4,%5,%6,%7},{%8,%9},{%0,%1,%2,%3};"
        : "+f"(d[0]), "+f"(d[1]), "+f"(d[2]), "+f"(d[3])
        : "r"(a[0]), "r"(a[1]), "r"(a[2]), "r"(a[3]), "r"(b[0]), "r"(b[1]));
}
__device__ __forceinline__ void cp16(uint32_t dst, const void* src) {
    asm volatile("cp.async.cg.shared.global [%0], [%1], 16;" :: "r"(dst), "l"(src));
}
__device__ __forceinline__ void cp_commit() {
    asm volatile("cp.async.commit_group;" ::: "memory");
}
template <int W> __device__ __forceinline__ void cp_wait() {
    asm volatile("cp.async.wait_group %0;" :: "n"(W) : "memory");
}
__device__ __forceinline__ uint32_t packh(__half a, __half b) {
    __half2 t; t.x = a; t.y = b;
    uint32_t u; *(__half2*)&u = t; return u;
}

// ---------------- plain fp16 GEMM, BK=64, 3-stage, 1 sync/tile, 2 CTAs/SM -----
// A:[M][K] plain fp16; B:[N][K] plain fp16. Both 128B smem rows (8 chunks).
__global__ __launch_bounds__(256, 2) void gemm_plain(
    const __half* __restrict__ A, const __half* __restrict__ B,
    const float* __restrict__ bias,
    __half* __restrict__ Ch,
    int K, int lda, int ldb, int ldc)
{
    extern __shared__ char smem[];
    const int tid = threadIdx.x;
    const int m0 = blockIdx.y * BM, n0 = blockIdx.x * BN;
    const int nt = K >> 6;

    const uint32_t S0 = smem_u32(smem);
    const int crow = tid >> 1;           // 0..127
    const int cc0  = (tid & 1) * 4;      // chunks 0-3 or 4-7

    auto copy_stage = [&](int kt) {
        const uint32_t base = S0 + (uint32_t)(kt % 3) * 32768;
        const int k0 = kt << 6;
        const __half* ap = A + (size_t)(m0 + crow) * lda + k0;
        const __half* bp = B + (size_t)(n0 + crow) * ldb + k0;
#pragma unroll
        for (int j = 0; j < 4; ++j) {
            int c = cc0 + j;
            uint32_t sw = crow * 128 + ((c ^ (crow & 7)) << 4);
            cp16(base + sw,         ap + c * 8);
            cp16(base + 16384 + sw, bp + c * 8);
        }
    };

    const int warp = tid >> 5, lane = tid & 31;
    const int wm = warp >> 1, wn = warp & 1;
    const int rselA = (lane & 7) + (((lane >> 3) & 1) << 3);
    const int chA   = (lane >> 4) & 1;
    const int rselB = (lane & 7) + (((lane >> 4) & 1) << 3);
    const int chB   = (lane >> 3) & 1;

    float acc[2][8][4];
#pragma unroll
    for (int a = 0; a < 2; ++a)
#pragma unroll
        for (int b = 0; b < 8; ++b)
#pragma unroll
            for (int c = 0; c < 4; ++c) acc[a][b][c] = 0.f;

    auto compute_tile = [&](int buf) {
        const uint32_t abase = S0 + (uint32_t)buf * 32768;
        const uint32_t bbase = abase + 16384;
#pragma unroll
        for (int ks = 0; ks < 4; ++ks) {
            uint32_t aH[2][4];
            const int g = 2 * ks + chA;
#pragma unroll
            for (int mf = 0; mf < 2; ++mf) {
                int row = wm * 32 + mf * 16 + rselA;
                ldsm_x4(aH[mf], abase + row * 128 + ((g ^ (row & 7)) << 4));
            }
            const int gb = 2 * ks + chB;
#pragma unroll
            for (int np = 0; np < 4; ++np) {
                uint32_t bh[4];
                int rowb = wn * 64 + np * 16 + rselB;
                ldsm_x4(bh, bbase + rowb * 128 + ((gb ^ (rowb & 7)) << 4));
#pragma unroll
                for (int mf = 0; mf < 2; ++mf) {
                    mma_f16(acc[mf][2 * np],     aH[mf], bh);
                    mma_f16(acc[mf][2 * np + 1], aH[mf], bh + 2);
                }
            }
        }
    };

    copy_stage(0); cp_commit();
    if (nt > 1) { copy_stage(1); cp_commit(); }
    for (int kt = 0; kt < nt; ++kt) {
        if (kt + 1 < nt) cp_wait<1>(); else cp_wait<0>();
        __syncthreads();
        if (kt + 2 < nt) { copy_stage(kt + 2); cp_commit(); }
        compute_tile(kt % 3);
    }

#pragma unroll
    for (int mf = 0; mf < 2; ++mf) {
        int row = m0 + wm * 32 + mf * 16 + (lane >> 2);
#pragma unroll
        for (int nf = 0; nf < 8; ++nf) {
            int col = n0 + wn * 64 + nf * 8 + (lane & 3) * 2;
            float b0 = bias[col], b1 = bias[col + 1];
            size_t o0 = (size_t)row * ldc + col;
            size_t o1 = (size_t)(row + 8) * ldc + col;
            *(uint32_t*)(Ch + o0) = packh(__float2half_rn(acc[mf][nf][0] + b0),
                                          __float2half_rn(acc[mf][nf][1] + b1));
            *(uint32_t*)(Ch + o1) = packh(__float2half_rn(acc[mf][nf][2] + b0),
                                          __float2half_rn(acc[mf][nf][3] + b1));
        }
    }
}

// ---------------- split-A fp16 GEMM (2-term), BK=32, 3-stage ------------------
// A hi/lo packed in 128B rows (chunks 0-3 hi, 4-7 lo); B 64B rows. fp32 out.
__global__ __launch_bounds__(256, 2) void gemm_split(
    const __half* __restrict__ Ah, const __half* __restrict__ Al,
    const __half* __restrict__ B,
    const float* __restrict__ bias,
    float* __restrict__ C,
    int K, int lda, int ldb, int ldc)
{
    extern __shared__ char smem[];
    const int tid = threadIdx.x;
    const int m0 = blockIdx.y * BM, n0 = blockIdx.x * BN;
    const int nt = K >> 5;

    const uint32_t S0 = smem_u32(smem);
    const int crow = tid >> 3;          // 0..31
    const int cc   = tid & 7;
    const __half* aptr = (cc < 4) ? Ah : Al;
    const int kchunk = (cc & 3) << 3;
    const int rb  = tid >> 1;           // 0..127
    const int cb0 = (tid & 1) * 2;

    auto copy_stage = [&](int kt) {
        const uint32_t base = S0 + (uint32_t)(kt % 3) * 24576;
        const int k0 = kt << 5;
#pragma unroll
        for (int i = 0; i < 4; ++i) {
            int row = crow + (i << 5);
            cp16(base + row * 128 + ((cc ^ (row & 7)) << 4),
                 aptr + (size_t)(m0 + row) * lda + k0 + kchunk);
        }
#pragma unroll
        for (int j = 0; j < 2; ++j) {
            int c = cb0 + j;
            cp16(base + 16384 + rb * 64 + ((c ^ ((rb >> 1) & 3)) << 4),
                 B + (size_t)(n0 + rb) * ldb + k0 + c * 8);
        }
    };

    const int warp = tid >> 5, lane = tid & 31;
    const int wm = warp >> 1, wn = warp & 1;
    const int rselA = (lane & 7) + (((lane >> 3) & 1) << 3);
    const int chA   = (lane >> 4) & 1;
    const int rselB = (lane & 7) + (((lane >> 4) & 1) << 3);
    const int chB   = (lane >> 3) & 1;

    float acc[2][8][4];
#pragma unroll
    for (int a = 0; a < 2; ++a)
#pragma unroll
        for (int b = 0; b < 8; ++b)
#pragma unroll
            for (int c = 0; c < 4; ++c) acc[a][b][c] = 0.f;

    auto compute_tile = [&](int buf) {
        const uint32_t abase = S0 + (uint32_t)buf * 24576;
        const uint32_t bbase = abase + 16384;
#pragma unroll
        for (int ks = 0; ks < 2; ++ks) {
            uint32_t aH[2][4], aL[2][4];
            const int g = 2 * ks + chA;
#pragma unroll
            for (int mf = 0; mf < 2; ++mf) {
                int row = wm * 32 + mf * 16 + rselA;
                uint32_t off = abase + row * 128;
                ldsm_x4(aH[mf], off + ((g ^ (row & 7)) << 4));
                ldsm_x4(aL[mf], off + (((g + 4) ^ (row & 7)) << 4));
            }
            const int gb = 2 * ks + chB;
#pragma unroll
            for (int np = 0; np < 4; ++np) {
                uint32_t bh[4];
                int rowb = wn * 64 + np * 16 + rselB;
                ldsm_x4(bh, bbase + rowb * 64 + ((gb ^ ((rowb >> 1) & 3)) << 4));
#pragma unroll
                for (int mf = 0; mf < 2; ++mf) {
                    mma_f16(acc[mf][2 * np],     aH[mf], bh);
                    mma_f16(acc[mf][2 * np + 1], aH[mf], bh + 2);
                    mma_f16(acc[mf][2 * np],     aL[mf], bh);
                    mma_f16(acc[mf][2 * np + 1], aL[mf], bh + 2);
                }
            }
        }
    };

    copy_stage(0); cp_commit();
    if (nt > 1) { copy_stage(1); cp_commit(); }
    for (int kt = 0; kt < nt; ++kt) {
        if (kt + 1 < nt) cp_wait<1>(); else cp_wait<0>();
        __syncthreads();
        if (kt + 2 < nt) { copy_stage(kt + 2); cp_commit(); }
        compute_tile(kt % 3);
    }

#pragma unroll
    for (int mf = 0; mf < 2; ++mf) {
        int row = m0 + wm * 32 + mf * 16 + (lane >> 2);
#pragma unroll
        for (int nf = 0; nf < 8; ++nf) {
            int col = n0 + wn * 64 + nf * 8 + (lane & 3) * 2;
            float b0 = bias[col], b1 = bias[col + 1];
            size_t o0 = (size_t)row * ldc + col;
            size_t o1 = (size_t)(row + 8) * ldc + col;
            *(float2*)(C + o0) = make_float2(acc[mf][nf][0] + b0, acc[mf][nf][1] + b1);
            *(float2*)(C + o1) = make_float2(acc[mf][nf][2] + b0, acc[mf][nf][3] + b1);
        }
    }
}

// ---------------- fused flash attention (all plain fp16 MMA inputs) -----------
__global__ __launch_bounds__(256) void flash_attn(
    const __half* __restrict__ qkvh,
    __half* __restrict__ outh, __half* __restrict__ outl)
{
    const int qi = 15 - (int)blockIdx.x;
    const int bh = blockIdx.y;
    const int b = bh >> 4, h = bh & 15;
    const int q0 = qi * 128;
    const size_t base = (size_t)b * SEQ * 6144 + (size_t)h * 128;
    const __half* Qp = qkvh + base;
    const __half* Kp = qkvh + base + 2048;
    const __half* Vp = qkvh + base + 4096;

    extern __shared__ char smem[];
    const uint32_t S0 = smem_u32(smem);
    const int tid = threadIdx.x, lane = tid & 31, warp = tid >> 5;

    // Q: 2 p-planes x 128 rows x 128B = 32KB at S0
#pragma unroll
    for (int i = 0; i < 8; ++i) {
        int idx = tid + i * 256;
        int row = idx >> 4, c = idx & 15, p = c >> 3, c8 = c & 7;
        cp16(S0 + p * 16384 + row * 128 + ((c8 ^ (row & 7)) << 4),
             Qp + (size_t)(q0 + row) * 6144 + p * 64 + c8 * 8);
    }

    auto copy_kv = [&](int t) {
        const uint32_t sb = S0 + 32768 + (uint32_t)(t & 1) * 32768;
        const int kv0 = t * 64;
#pragma unroll
        for (int q = 0; q < 2; ++q) {
            const __half* src = q ? Vp : Kp;
#pragma unroll
            for (int i = 0; i < 4; ++i) {
                int idx = tid + i * 256;
                int row = idx >> 4, c = idx & 15, p = c >> 3, c8 = c & 7;
                cp16(sb + q * 16384 + p * 8192 + row * 128 + ((c8 ^ (row & 7)) << 4),
                     src + (size_t)(kv0 + row) * 6144 + p * 64 + c8 * 8);
            }
        }
    };

    const int rselA = (lane & 7) + (((lane >> 3) & 1) << 3);
    const int chA   = (lane >> 4) & 1;
    const int rselB = (lane & 7) + (((lane >> 4) & 1) << 3);
    const int chB   = (lane >> 3) & 1;
    const int qr = warp * 16;

    float m0 = -1e30f, m1 = -1e30f, l0 = 0.f, l1 = 0.f;
    float accO[16][4];
#pragma unroll
    for (int j = 0; j < 16; ++j)
#pragma unroll
        for (int c = 0; c < 4; ++c) accO[j][c] = 0.f;

    const int nt = 2 * qi + 2;
    copy_kv(0); cp_commit();
    if (nt > 1) { copy_kv(1); cp_commit(); }

    for (int t = 0; t < nt; ++t) {
        if (t + 1 < nt) cp_wait<1>(); else cp_wait<0>();
        __syncthreads();

        const uint32_t sb = S0 + 32768 + (uint32_t)(t & 1) * 32768;
        const uint32_t sK = sb, sV = sb + 16384;

        float accS[8][4];
#pragma unroll
        for (int j = 0; j < 8; ++j)
#pragma unroll
            for (int c = 0; c < 4; ++c) accS[j][c] = 0.f;

#pragma unroll
        for (int ks = 0; ks < 8; ++ks) {
            uint32_t aH[4];
            {
                int row = qr + rselA;
                int g = ks * 2 + chA, p = g >> 3, c8 = g & 7;
                ldsm_x4(aH, S0 + (uint32_t)p * 16384 + row * 128 + ((c8 ^ (row & 7)) << 4));
            }
#pragma unroll
            for (int n2 = 0; n2 < 4; ++n2) {
                uint32_t bH[4];
                int row = n2 * 16 + rselB;
                int g = ks * 2 + chB, p = g >> 3, c8 = g & 7;
                ldsm_x4(bH, sK + (uint32_t)p * 8192 + row * 128 + ((c8 ^ (row & 7)) << 4));
                mma_f16(accS[2 * n2],     aH, bH);
                mma_f16(accS[2 * n2 + 1], aH, bH + 2);
            }
        }

        const float isd = 0.08838834764831845f;
        const int kv0 = t * 64;
        const int grow0 = q0 + qr + (lane >> 2);
        const int grow1 = grow0 + 8;
        const bool masked = (t >= 2 * qi);
#pragma unroll
        for (int nf = 0; nf < 8; ++nf) {
#pragma unroll
            for (int c = 0; c < 4; ++c) accS[nf][c] *= isd;
            if (masked) {
                int col = kv0 + nf * 8 + (lane & 3) * 2;
                if (col     > grow0) accS[nf][0] = -1e30f;
                if (col + 1 > grow0) accS[nf][1] = -1e30f;
                if (col     > grow1) accS[nf][2] = -1e30f;
                if (col + 1 > grow1) accS[nf][3] = -1e30f;
            }
        }
        float mx0 = -1e30f, mx1 = -1e30f;
#pragma unroll
        for (int nf = 0; nf < 8; ++nf) {
            mx0 = fmaxf(mx0, fmaxf(accS[nf][0], accS[nf][1]));
            mx1 = fmaxf(mx1, fmaxf(accS[nf][2], accS[nf][3]));
        }
        mx0 = fmaxf(mx0, __shfl_xor_sync(0xffffffffu, mx0, 1));
        mx0 = fmaxf(mx0, __shfl_xor_sync(0xffffffffu, mx0, 2));
        mx1 = fmaxf(mx1, __shfl_xor_sync(0xffffffffu, mx1, 1));
        mx1 = fmaxf(mx1, __shfl_xor_sync(0xffffffffu, mx1, 2));
        const float nm0 = fmaxf(m0, mx0), nm1 = fmaxf(m1, mx1);
        const float cr0 = __expf(m0 - nm0), cr1 = __expf(m1 - nm1);
        m0 = nm0; m1 = nm1;

        float rs0 = 0.f, rs1 = 0.f;
        uint32_t phr[8], phr8[8];
#pragma unroll
        for (int nf = 0; nf < 8; ++nf) {
            float p0 = __expf(accS[nf][0] - nm0), p1 = __expf(accS[nf][1] - nm0);
            float p2 = __expf(accS[nf][2] - nm1), p3 = __expf(accS[nf][3] - nm1);
            rs0 += p0 + p1; rs1 += p2 + p3;
            phr[nf]  = packh(__float2half_rn(p0), __float2half_rn(p1));
            phr8[nf] = packh(__float2half_rn(p2), __float2half_rn(p3));
        }
        rs0 += __shfl_xor_sync(0xffffffffu, rs0, 1);
        rs0 += __shfl_xor_sync(0xffffffffu, rs0, 2);
        rs1 += __shfl_xor_sync(0xffffffffu, rs1, 1);
        rs1 += __shfl_xor_sync(0xffffffffu, rs1, 2);
        l0 = l0 * cr0 + rs0;
        l1 = l1 * cr1 + rs1;
#pragma unroll
        for (int j = 0; j < 16; ++j) {
            accO[j][0] *= cr0; accO[j][1] *= cr0;
            accO[j][2] *= cr1; accO[j][3] *= cr1;
        }

        // O += P V  (P plain, V plain)
#pragma unroll
        for (int ks = 0; ks < 4; ++ks) {
            uint32_t Aph[4] = {phr[2 * ks], phr8[2 * ks], phr[2 * ks + 1], phr8[2 * ks + 1]};
            const int rowv = ks * 16 + (lane & 15);
#pragma unroll
            for (int jj = 0; jj < 4; ++jj) {
                uint32_t vh0[4], vh1[4];
                {
                    int cv = 4 * jj + (lane >> 4), p = cv >> 3, c8 = cv & 7;
                    ldsm_x4_t(vh0, sV + (uint32_t)p * 8192 + rowv * 128 + ((c8 ^ (rowv & 7)) << 4));
                }
                {
                    int cv = 4 * jj + 2 + (lane >> 4), p = cv >> 3, c8 = cv & 7;
                    ldsm_x4_t(vh1, sV + (uint32_t)p * 8192 + rowv * 128 + ((c8 ^ (rowv & 7)) << 4));
                }
                mma_f16(accO[4 * jj],     Aph, vh0);
                mma_f16(accO[4 * jj + 1], Aph, vh0 + 2);
                mma_f16(accO[4 * jj + 2], Aph, vh1);
                mma_f16(accO[4 * jj + 3], Aph, vh1 + 2);
            }
        }

        __syncthreads();
        if (t + 2 < nt) { copy_kv(t + 2); cp_commit(); }
    }

    const float i0 = 1.f / l0, i1 = 1.f / l1;
    const size_t obase = (size_t)b * SEQ * N_EMBD + (size_t)h * 128;
    const int row0 = q0 + qr + (lane >> 2);
#pragma unroll
    for (int j = 0; j < 16; ++j) {
        int d = j * 8 + (lane & 3) * 2;
        size_t o0 = obase + (size_t)row0 * N_EMBD + d;
        size_t o1 = obase + (size_t)(row0 + 8) * N_EMBD + d;
        float v0 = accO[j][0] * i0, v1 = accO[j][1] * i0;
        float v2 = accO[j][2] * i1, v3 = accO[j][3] * i1;
        __half h0 = __float2half_rn(v0), h1 = __float2half_rn(v1);
        __half h2 = __float2half_rn(v2), h3 = __float2half_rn(v3);
        *(uint32_t*)(outh + o0) = packh(h0, h1);
        *(uint32_t*)(outh + o1) = packh(h2, h3);
        *(uint32_t*)(outl + o0) = packh(__float2half_rn(v0 - __half2float(h0)),
                                        __float2half_rn(v1 - __half2float(h1)));
        *(uint32_t*)(outl + o1) = packh(__float2half_rn(v2 - __half2float(h2)),
                                        __float2half_rn(v3 - __half2float(h3)));
    }
}

// ---------------- converts ----------------------------------------------------
__global__ __launch_bounds__(256) void convert_plain(
    const float* __restrict__ in, __half* __restrict__ oh, int n)
{
    for (int i = blockIdx.x * 256 + threadIdx.x; i < n; i += gridDim.x * 256)
        oh[i] = __float2half_rn(in[i]);
}
__global__ __launch_bounds__(256) void transpose_w(
    const float* __restrict__ in, __half* __restrict__ out, int ld_in, int ld_out)
{
    __shared__ float t[32][33];
    const int c0 = blockIdx.x * 32, r0 = blockIdx.y * 32;
    const int tx = threadIdx.x, ty = threadIdx.y;
#pragma unroll
    for (int j = 0; j < 32; j += 8)
        t[ty + j][tx] = in[(size_t)(r0 + ty + j) * ld_in + c0 + tx];
    __syncthreads();
#pragma unroll
    for (int j = 0; j < 32; j += 8)
        out[(size_t)(c0 + ty + j) * ld_out + r0 + tx] = __float2half_rn(t[tx][ty + j]);
}

// ---------------- launch ------------------------------------------------------
extern "C" void kernel_launch(void* const* d_in, const int* in_sizes, int n_in,
                              void* d_out, int out_size)
{
    const float* x     = (const float*)d_in[0];
    const float* Wqkv  = (const float*)d_in[1];
    const float* bqkv  = (const float*)d_in[2];
    const float* Wproj = (const float*)d_in[3];
    const float* bproj = (const float*)d_in[4];
    float* out = (float*)d_out;

    __half *x_h, *wq, *wp, *qkv_h, *at_h, *at_l;
    cudaGetSymbolAddress((void**)&x_h, g_x_h);
    cudaGetSymbolAddress((void**)&wq, g_wqkvT);
    cudaGetSymbolAddress((void**)&wp, g_wprojT);
    cudaGetSymbolAddress((void**)&qkv_h, g_qkv_h);
    cudaGetSymbolAddress((void**)&at_h, g_attn_h);
    cudaGetSymbolAddress((void**)&at_l, g_attn_l);

    const int GEMM1_SMEM = 98304;    // 3 stages x 32KB (BK=64 plain)
    const int GEMM2_SMEM = 73728;    // 3 stages x 24KB (BK=32 split)
    const int FLASH_SMEM = 98304;    // Q 32KB + 2 stages x 32KB
    cudaFuncSetAttribute(gemm_plain,
                         cudaFuncAttributeMaxDynamicSharedMemorySize, GEMM1_SMEM);
    cudaFuncSetAttribute(gemm_split,
                         cudaFuncAttributeMaxDynamicSharedMemorySize, GEMM2_SMEM);
    cudaFuncSetAttribute(flash_attn,
                         cudaFuncAttributeMaxDynamicSharedMemorySize, FLASH_SMEM);

    const int M = BATCH * SEQ, E = N_EMBD, E3 = 3 * N_EMBD;

    convert_plain<<<4096, 256>>>(x, x_h, M * E);
    transpose_w<<<dim3(E3 / 32, E / 32), dim3(32, 8)>>>(Wqkv, wq, E3, E);
    transpose_w<<<dim3(E / 32, E / 32), dim3(32, 8)>>>(Wproj, wp, E, E);

    // 1) qkv = x @ Wqkv + b  (plain fp16, BK=64)
    gemm_plain<<<dim3(E3 / BN, M / BM), 256, GEMM1_SMEM>>>(
        x_h, wq, bqkv, qkv_h, E, E, E, E3);

    // 2-4) fused flash attention -> attn hi/lo
    flash_attn<<<dim3(SEQ / 128, BATCH * N_HEAD), 256, FLASH_SMEM>>>(
        qkv_h, at_h, at_l);

    // 5) out = attn @ Wproj + b  (2-term split A, fp32 out)
    gemm_split<<<dim3(E / BN, M / BM), 256, GEMM2_SMEM>>>(
        at_h, at_l, wp, bproj, out, E, E, E, E);
}

// round 12
// speedup vs baseline: 9.2447x; 1.1349x over previous
#include <cuda_runtime.h>
#include <cuda_fp16.h>
#include <cstdint>

#define N_EMBD 2048
#define N_HEAD 16
#define HEAD_DIM 128
#define BATCH 2
#define SEQ 2048

#define BM 128
#define BN 128

// ---------------- scratch ----------------------------------------------------
__device__ __half g_x_h[(size_t)BATCH * SEQ * N_EMBD];
__device__ __half g_wqkvT[(size_t)3 * N_EMBD * N_EMBD];
__device__ __half g_wprojT[(size_t)N_EMBD * N_EMBD];
__device__ __half g_qkv_h[(size_t)BATCH * SEQ * 3 * N_EMBD];
__device__ __half g_attn_h[(size_t)BATCH * SEQ * N_EMBD];

// ---------------- PTX helpers -------------------------------------------------
__device__ __forceinline__ uint32_t smem_u32(const void* p) {
    return (uint32_t)__cvta_generic_to_shared(p);
}
__device__ __forceinline__ void ldsm_x4(uint32_t* r, uint32_t addr) {
    asm volatile("ldmatrix.sync.aligned.m8n8.x4.shared.b16 {%0,%1,%2,%3}, [%4];"
                 : "=r"(r[0]), "=r"(r[1]), "=r"(r[2]), "=r"(r[3]) : "r"(addr));
}
__device__ __forceinline__ void ldsm_x4_t(uint32_t* r, uint32_t addr) {
    asm volatile("ldmatrix.sync.aligned.m8n8.x4.trans.shared.b16 {%0,%1,%2,%3}, [%4];"
                 : "=r"(r[0]), "=r"(r[1]), "=r"(r[2]), "=r"(r[3]) : "r"(addr));
}
__device__ __forceinline__ void mma_f16(float* d, const uint32_t* a, const uint32_t* b) {
    asm volatile(
        "mma.sync.aligned.m16n8k16.row.col.f32.f16.f16.f32 "
        "{%0,%1,%2,%3},{%4,%5,%6,%7},{%8,%9},{%0,%1,%2,%3};"
        : "+f"(d[0]), "+f"(d[1]), "+f"(d[2]), "+f"(d[3])
        : "r"(a[0]), "r"(a[1]), "r"(a[2]), "r"(a[3]), "r"(b[0]), "r"(b[1]));
}
__device__ __forceinline__ void cp16(uint32_t dst, const void* src) {
    asm volatile("cp.async.cg.shared.global [%0], [%1], 16;" :: "r"(dst), "l"(src));
}
__device__ __forceinline__ void cp_commit() {
    asm volatile("cp.async.commit_group;" ::: "memory");
}
template <int W> __device__ __forceinline__ void cp_wait() {
    asm volatile("cp.async.wait_group %0;" :: "n"(W) : "memory");
}
__device__ __forceinline__ uint32_t packh(__half a, __half b) {
    __half2 t; t.x = a; t.y = b;
    uint32_t u; *(__half2*)&u = t; return u;
}

// ---------------- plain fp16 GEMM, BK=32, 3-stage, 1 sync/tile, 2 CTAs/SM -----
// A:[M][K], B:[N][K] both plain fp16, 64B smem rows.
// WF32: fp32 output; else fp16 output. Bias always added.
template <bool WF32>
__global__ __launch_bounds__(256, 2) void gemm_plain32(
    const __half* __restrict__ A, const __half* __restrict__ B,
    const float* __restrict__ bias,
    float* __restrict__ C, __half* __restrict__ Ch,
    int K, int lda, int ldb, int ldc)
{
    extern __shared__ char smem[];
    const int tid = threadIdx.x;
    const int m0 = blockIdx.y * BM, n0 = blockIdx.x * BN;
    const int nt = K >> 5;

    const uint32_t S0 = smem_u32(smem);
    const int rb  = tid >> 1;           // 0..127
    const int cb0 = (tid & 1) * 2;      // chunks 0-1 or 2-3

    auto copy_stage = [&](int kt) {
        const uint32_t base = S0 + (uint32_t)(kt % 3) * 16384;
        const int k0 = kt << 5;
#pragma unroll
        for (int j = 0; j < 2; ++j) {
            int c = cb0 + j;
            uint32_t sw = rb * 64 + ((c ^ ((rb >> 1) & 3)) << 4);
            cp16(base + sw,        A + (size_t)(m0 + rb) * lda + k0 + c * 8);
            cp16(base + 8192 + sw, B + (size_t)(n0 + rb) * ldb + k0 + c * 8);
        }
    };

    const int warp = tid >> 5, lane = tid & 31;
    const int wm = warp >> 1, wn = warp & 1;
    const int rselA = (lane & 7) + (((lane >> 3) & 1) << 3);
    const int chA   = (lane >> 4) & 1;
    const int rselB = (lane & 7) + (((lane >> 4) & 1) << 3);
    const int chB   = (lane >> 3) & 1;

    float acc[2][8][4];
#pragma unroll
    for (int a = 0; a < 2; ++a)
#pragma unroll
        for (int b = 0; b < 8; ++b)
#pragma unroll
            for (int c = 0; c < 4; ++c) acc[a][b][c] = 0.f;

    auto compute_tile = [&](int buf) {
        const uint32_t abase = S0 + (uint32_t)buf * 16384;
        const uint32_t bbase = abase + 8192;
#pragma unroll
        for (int ks = 0; ks < 2; ++ks) {
            uint32_t aH[2][4];
            const int g = 2 * ks + chA;
#pragma unroll
            for (int mf = 0; mf < 2; ++mf) {
                int row = wm * 32 + mf * 16 + rselA;
                ldsm_x4(aH[mf], abase + row * 64 + ((g ^ ((row >> 1) & 3)) << 4));
            }
            const int gb = 2 * ks + chB;
#pragma unroll
            for (int np = 0; np < 4; ++np) {
                uint32_t bh[4];
                int rowb = wn * 64 + np * 16 + rselB;
                ldsm_x4(bh, bbase + rowb * 64 + ((gb ^ ((rowb >> 1) & 3)) << 4));
#pragma unroll
                for (int mf = 0; mf < 2; ++mf) {
                    mma_f16(acc[mf][2 * np],     aH[mf], bh);
                    mma_f16(acc[mf][2 * np + 1], aH[mf], bh + 2);
                }
            }
        }
    };

    copy_stage(0); cp_commit();
    if (nt > 1) { copy_stage(1); cp_commit(); }
    for (int kt = 0; kt < nt; ++kt) {
        if (kt + 1 < nt) cp_wait<1>(); else cp_wait<0>();
        __syncthreads();
        if (kt + 2 < nt) { copy_stage(kt + 2); cp_commit(); }
        compute_tile(kt % 3);
    }

#pragma unroll
    for (int mf = 0; mf < 2; ++mf) {
        int row = m0 + wm * 32 + mf * 16 + (lane >> 2);
#pragma unroll
        for (int nf = 0; nf < 8; ++nf) {
            int col = n0 + wn * 64 + nf * 8 + (lane & 3) * 2;
            float b0 = bias[col], b1 = bias[col + 1];
            float v0 = acc[mf][nf][0] + b0, v1 = acc[mf][nf][1] + b1;
            float v2 = acc[mf][nf][2] + b0, v3 = acc[mf][nf][3] + b1;
            size_t o0 = (size_t)row * ldc + col;
            size_t o1 = (size_t)(row + 8) * ldc + col;
            if (WF32) {
                *(float2*)(C + o0) = make_float2(v0, v1);
                *(float2*)(C + o1) = make_float2(v2, v3);
            } else {
                *(uint32_t*)(Ch + o0) = packh(__float2half_rn(v0), __float2half_rn(v1));
                *(uint32_t*)(Ch + o1) = packh(__float2half_rn(v2), __float2half_rn(v3));
            }
        }
    }
}

// ---------------- fused flash attention (all plain fp16) ----------------------
__global__ __launch_bounds__(256) void flash_attn(
    const __half* __restrict__ qkvh, __half* __restrict__ outh)
{
    const int qi = 15 - (int)blockIdx.x;
    const int bh = blockIdx.y;
    const int b = bh >> 4, h = bh & 15;
    const int q0 = qi * 128;
    const size_t base = (size_t)b * SEQ * 6144 + (size_t)h * 128;
    const __half* Qp = qkvh + base;
    const __half* Kp = qkvh + base + 2048;
    const __half* Vp = qkvh + base + 4096;

    extern __shared__ char smem[];
    const uint32_t S0 = smem_u32(smem);
    const int tid = threadIdx.x, lane = tid & 31, warp = tid >> 5;

    // Q: 2 p-planes x 128 rows x 128B = 32KB at S0
#pragma unroll
    for (int i = 0; i < 8; ++i) {
        int idx = tid + i * 256;
        int row = idx >> 4, c = idx & 15, p = c >> 3, c8 = c & 7;
        cp16(S0 + p * 16384 + row * 128 + ((c8 ^ (row & 7)) << 4),
             Qp + (size_t)(q0 + row) * 6144 + p * 64 + c8 * 8);
    }

    auto copy_kv = [&](int t) {
        const uint32_t sb = S0 + 32768 + (uint32_t)(t & 1) * 32768;
        const int kv0 = t * 64;
#pragma unroll
        for (int q = 0; q < 2; ++q) {
            const __half* src = q ? Vp : Kp;
#pragma unroll
            for (int i = 0; i < 4; ++i) {
                int idx = tid + i * 256;
                int row = idx >> 4, c = idx & 15, p = c >> 3, c8 = c & 7;
                cp16(sb + q * 16384 + p * 8192 + row * 128 + ((c8 ^ (row & 7)) << 4),
                     src + (size_t)(kv0 + row) * 6144 + p * 64 + c8 * 8);
            }
        }
    };

    const int rselA = (lane & 7) + (((lane >> 3) & 1) << 3);
    const int chA   = (lane >> 4) & 1;
    const int rselB = (lane & 7) + (((lane >> 4) & 1) << 3);
    const int chB   = (lane >> 3) & 1;
    const int qr = warp * 16;

    float m0 = -1e30f, m1 = -1e30f, l0 = 0.f, l1 = 0.f;
    float accO[16][4];
#pragma unroll
    for (int j = 0; j < 16; ++j)
#pragma unroll
        for (int c = 0; c < 4; ++c) accO[j][c] = 0.f;

    const int nt = 2 * qi + 2;
    copy_kv(0); cp_commit();
    if (nt > 1) { copy_kv(1); cp_commit(); }

    for (int t = 0; t < nt; ++t) {
        if (t + 1 < nt) cp_wait<1>(); else cp_wait<0>();
        __syncthreads();

        const uint32_t sb = S0 + 32768 + (uint32_t)(t & 1) * 32768;
        const uint32_t sK = sb, sV = sb + 16384;

        float accS[8][4];
#pragma unroll
        for (int j = 0; j < 8; ++j)
#pragma unroll
            for (int c = 0; c < 4; ++c) accS[j][c] = 0.f;

#pragma unroll
        for (int ks = 0; ks < 8; ++ks) {
            uint32_t aH[4];
            {
                int row = qr + rselA;
                int g = ks * 2 + chA, p = g >> 3, c8 = g & 7;
                ldsm_x4(aH, S0 + (uint32_t)p * 16384 + row * 128 + ((c8 ^ (row & 7)) << 4));
            }
#pragma unroll
            for (int n2 = 0; n2 < 4; ++n2) {
                uint32_t bH[4];
                int row = n2 * 16 + rselB;
                int g = ks * 2 + chB, p = g >> 3, c8 = g & 7;
                ldsm_x4(bH, sK + (uint32_t)p * 8192 + row * 128 + ((c8 ^ (row & 7)) << 4));
                mma_f16(accS[2 * n2],     aH, bH);
                mma_f16(accS[2 * n2 + 1], aH, bH + 2);
            }
        }

        const float isd = 0.08838834764831845f;
        const int kv0 = t * 64;
        const int grow0 = q0 + qr + (lane >> 2);
        const int grow1 = grow0 + 8;
        const bool masked = (t >= 2 * qi);
#pragma unroll
        for (int nf = 0; nf < 8; ++nf) {
#pragma unroll
            for (int c = 0; c < 4; ++c) accS[nf][c] *= isd;
            if (masked) {
                int col = kv0 + nf * 8 + (lane & 3) * 2;
                if (col     > grow0) accS[nf][0] = -1e30f;
                if (col + 1 > grow0) accS[nf][1] = -1e30f;
                if (col     > grow1) accS[nf][2] = -1e30f;
                if (col + 1 > grow1) accS[nf][3] = -1e30f;
            }
        }
        float mx0 = -1e30f, mx1 = -1e30f;
#pragma unroll
        for (int nf = 0; nf < 8; ++nf) {
            mx0 = fmaxf(mx0, fmaxf(accS[nf][0], accS[nf][1]));
            mx1 = fmaxf(mx1, fmaxf(accS[nf][2], accS[nf][3]));
        }
        mx0 = fmaxf(mx0, __shfl_xor_sync(0xffffffffu, mx0, 1));
        mx0 = fmaxf(mx0, __shfl_xor_sync(0xffffffffu, mx0, 2));
        mx1 = fmaxf(mx1, __shfl_xor_sync(0xffffffffu, mx1, 1));
        mx1 = fmaxf(mx1, __shfl_xor_sync(0xffffffffu, mx1, 2));
        const float nm0 = fmaxf(m0, mx0), nm1 = fmaxf(m1, mx1);
        const float cr0 = __expf(m0 - nm0), cr1 = __expf(m1 - nm1);
        m0 = nm0; m1 = nm1;

        float rs0 = 0.f, rs1 = 0.f;
        uint32_t phr[8], phr8[8];
#pragma unroll
        for (int nf = 0; nf < 8; ++nf) {
            float p0 = __expf(accS[nf][0] - nm0), p1 = __expf(accS[nf][1] - nm0);
            float p2 = __expf(accS[nf][2] - nm1), p3 = __expf(accS[nf][3] - nm1);
            rs0 += p0 + p1; rs1 += p2 + p3;
            phr[nf]  = packh(__float2half_rn(p0), __float2half_rn(p1));
            phr8[nf] = packh(__float2half_rn(p2), __float2half_rn(p3));
        }
        rs0 += __shfl_xor_sync(0xffffffffu, rs0, 1);
        rs0 += __shfl_xor_sync(0xffffffffu, rs0, 2);
        rs1 += __shfl_xor_sync(0xffffffffu, rs1, 1);
        rs1 += __shfl_xor_sync(0xffffffffu, rs1, 2);
        l0 = l0 * cr0 + rs0;
        l1 = l1 * cr1 + rs1;
#pragma unroll
        for (int j = 0; j < 16; ++j) {
            accO[j][0] *= cr0; accO[j][1] *= cr0;
            accO[j][2] *= cr1; accO[j][3] *= cr1;
        }

        // O += P V
#pragma unroll
        for (int ks = 0; ks < 4; ++ks) {
            uint32_t Aph[4] = {phr[2 * ks], phr8[2 * ks], phr[2 * ks + 1], phr8[2 * ks + 1]};
            const int rowv = ks * 16 + (lane & 15);
#pragma unroll
            for (int jj = 0; jj < 4; ++jj) {
                uint32_t vh0[4], vh1[4];
                {
                    int cv = 4 * jj + (lane >> 4), p = cv >> 3, c8 = cv & 7;
                    ldsm_x4_t(vh0, sV + (uint32_t)p * 8192 + rowv * 128 + ((c8 ^ (rowv & 7)) << 4));
                }
                {
                    int cv = 4 * jj + 2 + (lane >> 4), p = cv >> 3, c8 = cv & 7;
                    ldsm_x4_t(vh1, sV + (uint32_t)p * 8192 + rowv * 128 + ((c8 ^ (rowv & 7)) << 4));
                }
                mma_f16(accO[4 * jj],     Aph, vh0);
                mma_f16(accO[4 * jj + 1], Aph, vh0 + 2);
                mma_f16(accO[4 * jj + 2], Aph, vh1);
                mma_f16(accO[4 * jj + 3], Aph, vh1 + 2);
            }
        }

        __syncthreads();
        if (t + 2 < nt) { copy_kv(t + 2); cp_commit(); }
    }

    const float i0 = 1.f / l0, i1 = 1.f / l1;
    const size_t obase = (size_t)b * SEQ * N_EMBD + (size_t)h * 128;
    const int row0 = q0 + qr + (lane >> 2);
#pragma unroll
    for (int j = 0; j < 16; ++j) {
        int d = j * 8 + (lane & 3) * 2;
        size_t o0 = obase + (size_t)row0 * N_EMBD + d;
        size_t o1 = obase + (size_t)(row0 + 8) * N_EMBD + d;
        *(uint32_t*)(outh + o0) = packh(__float2half_rn(accO[j][0] * i0),
                                        __float2half_rn(accO[j][1] * i0));
        *(uint32_t*)(outh + o1) = packh(__float2half_rn(accO[j][2] * i1),
                                        __float2half_rn(accO[j][3] * i1));
    }
}

// ---------------- converts ----------------------------------------------------
__global__ __launch_bounds__(256) void convert_plain(
    const float* __restrict__ in, __half* __restrict__ oh, int n)
{
    for (int i = blockIdx.x * 256 + threadIdx.x; i < n; i += gridDim.x * 256)
        oh[i] = __float2half_rn(in[i]);
}
__global__ __launch_bounds__(256) void transpose_w(
    const float* __restrict__ in, __half* __restrict__ out, int ld_in, int ld_out)
{
    __shared__ float t[32][33];
    const int c0 = blockIdx.x * 32, r0 = blockIdx.y * 32;
    const int tx = threadIdx.x, ty = threadIdx.y;
#pragma unroll
    for (int j = 0; j < 32; j += 8)
        t[ty + j][tx] = in[(size_t)(r0 + ty + j) * ld_in + c0 + tx];
    __syncthreads();
#pragma unroll
    for (int j = 0; j < 32; j += 8)
        out[(size_t)(c0 + ty + j) * ld_out + r0 + tx] = __float2half_rn(t[tx][ty + j]);
}

// ---------------- launch ------------------------------------------------------
extern "C" void kernel_launch(void* const* d_in, const int* in_sizes, int n_in,
                              void* d_out, int out_size)
{
    const float* x     = (const float*)d_in[0];
    const float* Wqkv  = (const float*)d_in[1];
    const float* bqkv  = (const float*)d_in[2];
    const float* Wproj = (const float*)d_in[3];
    const float* bproj = (const float*)d_in[4];
    float* out = (float*)d_out;

    __half *x_h, *wq, *wp, *qkv_h, *at_h;
    cudaGetSymbolAddress((void**)&x_h, g_x_h);
    cudaGetSymbolAddress((void**)&wq, g_wqkvT);
    cudaGetSymbolAddress((void**)&wp, g_wprojT);
    cudaGetSymbolAddress((void**)&qkv_h, g_qkv_h);
    cudaGetSymbolAddress((void**)&at_h, g_attn_h);

    const int GEMM_SMEM  = 49152;    // 3 stages x 16KB
    const int FLASH_SMEM = 98304;    // Q 32KB + 2 stages x 32KB
    cudaFuncSetAttribute(gemm_plain32<false>,
                         cudaFuncAttributeMaxDynamicSharedMemorySize, GEMM_SMEM);
    cudaFuncSetAttribute(gemm_plain32<true>,
                         cudaFuncAttributeMaxDynamicSharedMemorySize, GEMM_SMEM);
    cudaFuncSetAttribute(flash_attn,
                         cudaFuncAttributeMaxDynamicSharedMemorySize, FLASH_SMEM);

    const int M = BATCH * SEQ, E = N_EMBD, E3 = 3 * N_EMBD;

    convert_plain<<<4096, 256>>>(x, x_h, M * E);
    transpose_w<<<dim3(E3 / 32, E / 32), dim3(32, 8)>>>(Wqkv, wq, E3, E);
    transpose_w<<<dim3(E / 32, E / 32), dim3(32, 8)>>>(Wproj, wp, E, E);

    // 1) qkv = x @ Wqkv + b  (plain fp16, BK=32 — proven round-10 config)
    gemm_plain32<false><<<dim3(E3 / BN, M / BM), 256, GEMM_SMEM>>>(
        x_h, wq, bqkv, nullptr, qkv_h, E, E, E, E3);

    // 2-4) fused flash attention -> attn (plain fp16)
    flash_attn<<<dim3(SEQ / 128, BATCH * N_HEAD), 256, FLASH_SMEM>>>(qkv_h, at_h);

    // 5) out = attn @ Wproj + b  (plain fp16, fp32 out)
    gemm_plain32<true><<<dim3(E / BN, M / BM), 256, GEMM_SMEM>>>(
        at_h, wp, bproj, out, nullptr, E, E, E, E);
}